// round 7
// baseline (speedup 1.0000x reference)
#include <cuda_runtime.h>
#include <cuda_bf16.h>

#define SEQ 2048
#define DM 2048
#define NH 32
#define HD 64

// Scratch (static device allocations are allowed; cudaMalloc is not)
__device__ float g_Q[SEQ * DM];
__device__ float g_K[SEQ * DM];
__device__ float g_V[SEQ * DM];
__device__ float g_att[SEQ * DM];
__device__ float g_cos[SEQ * 32];
__device__ float g_sin[SEQ * 32];

// Preprocessed (roped, hi/lo-split, bf16x2-packed) operands for attention.
// K/Q: [h][l][word j] packs dims (2j,2j+1) of the rotated vector.
// V:   [h][kp][dim d] packs (V[2kp][d], V[2kp+1][d]).
__device__ unsigned g_QHp[NH * SEQ * 32];
__device__ unsigned g_QLp[NH * SEQ * 32];
__device__ unsigned g_KHp[NH * SEQ * 32];
__device__ unsigned g_KLp[NH * SEQ * 32];
__device__ unsigned g_VHp[NH * (SEQ / 2) * 64];
__device__ unsigned g_VLp[NH * (SEQ / 2) * 64];

// ---------------------------------------------------------------------------
// helpers
// ---------------------------------------------------------------------------
__device__ __forceinline__ unsigned f2tf32(float f) {
    unsigned r;
    asm("cvt.rna.tf32.f32 %0, %1;" : "=r"(r) : "f"(f));
    return r;
}

__device__ __forceinline__ void mma_tf32(float* c, const unsigned* a, const unsigned* b) {
    asm volatile(
        "mma.sync.aligned.m16n8k8.row.col.f32.tf32.tf32.f32 "
        "{%0,%1,%2,%3}, {%4,%5,%6,%7}, {%8,%9}, {%0,%1,%2,%3};"
        : "+f"(c[0]), "+f"(c[1]), "+f"(c[2]), "+f"(c[3])
        : "r"(a[0]), "r"(a[1]), "r"(a[2]), "r"(a[3]), "r"(b[0]), "r"(b[1]));
}

__device__ __forceinline__ void mma_bf16(float* c, const unsigned* a, const unsigned* b) {
    asm volatile(
        "mma.sync.aligned.m16n8k16.row.col.f32.bf16.bf16.f32 "
        "{%0,%1,%2,%3}, {%4,%5,%6,%7}, {%8,%9}, {%0,%1,%2,%3};"
        : "+f"(c[0]), "+f"(c[1]), "+f"(c[2]), "+f"(c[3])
        : "r"(a[0]), "r"(a[1]), "r"(a[2]), "r"(a[3]), "r"(b[0]), "r"(b[1]));
}

__device__ __forceinline__ unsigned pack_bf(float e0, float e1) {
    unsigned r;
    asm("cvt.rn.bf16x2.f32 %0, %1, %2;" : "=r"(r) : "f"(e1), "f"(e0));
    return r;
}

__device__ __forceinline__ float bf_hi(float x) {
    return __bfloat162float(__float2bfloat16(x));
}

__device__ __forceinline__ void cp16(void* sptr, const void* gptr) {
    unsigned sa = (unsigned)__cvta_generic_to_shared(sptr);
    asm volatile("cp.async.cg.shared.global [%0], [%1], 16;" :: "r"(sa), "l"(gptr)
                 : "memory");
}
__device__ __forceinline__ void cp_commit() {
    asm volatile("cp.async.commit_group;" ::: "memory");
}
template <int N>
__device__ __forceinline__ void cp_wait() {
    asm volatile("cp.async.wait_group %0;" :: "n"(N) : "memory");
}

// FMA-pipe exp2 (no MUFU)
__device__ __forceinline__ float exp2p(float y) {
    y = fmaxf(y, -126.0f);
    float z = y + 12582912.0f;
    int i = __float_as_int(z) - 0x4B400000;
    float f = y - (z - 12582912.0f);
    float p = 1.3534384e-3f;
    p = fmaf(p, f, 9.6181291e-3f);
    p = fmaf(p, f, 5.5504109e-2f);
    p = fmaf(p, f, 2.4022650e-1f);
    p = fmaf(p, f, 6.9314718e-1f);
    p = fmaf(p, f, 1.0f);
    return __int_as_float(__float_as_int(p) + (i << 23));
}

#define LOG2E 1.4426950408889634f

// ---------------------------------------------------------------------------
// RoPE cos/sin table
// ---------------------------------------------------------------------------
__global__ void rope_table_kernel() {
    int idx = blockIdx.x * blockDim.x + threadIdx.x;
    if (idx >= SEQ * 32) return;
    int l = idx >> 5;
    int j = idx & 31;
    float invf = powf(10000.0f, -(float)j * (1.0f / 32.0f));
    float fr = (float)l * invf;
    g_cos[idx] = cosf(fr);
    g_sin[idx] = sinf(fr);
}

// ---------------------------------------------------------------------------
// Preprocess: rope+split Q,K (blockIdx.y 0/1), split-pair V (blockIdx.y 2)
// into the attention tile layouts.
// ---------------------------------------------------------------------------
__global__ void __launch_bounds__(256) preprocess_kernel() {
    int t = blockIdx.x * blockDim.x + threadIdx.x;
    int which = blockIdx.y;
    if (which < 2) {
        if (t >= SEQ * NH) return;
        int l = t >> 5, h = t & 31;
        const float* src = (which == 0 ? g_Q : g_K) + (size_t)l * DM + h * HD;
        unsigned* dh = (which == 0 ? g_QHp : g_KHp) + ((size_t)h * SEQ + l) * 32;
        unsigned* dl = (which == 0 ? g_QLp : g_KLp) + ((size_t)h * SEQ + l) * 32;
        float v[64];
#pragma unroll
        for (int i = 0; i < 16; i++)
            *(float4*)(v + 4 * i) = *(const float4*)(src + 4 * i);
        float r[64];
#pragma unroll
        for (int p = 0; p < 32; p++) {
            float c = g_cos[l * 32 + p];
            float s = g_sin[l * 32 + p];
            r[p]      = v[2 * p] * c - v[2 * p + 1] * s;
            r[32 + p] = v[2 * p] * s + v[2 * p + 1] * c;
        }
#pragma unroll
        for (int j = 0; j < 32; j++) {
            float h0 = bf_hi(r[2 * j]), h1 = bf_hi(r[2 * j + 1]);
            dh[j] = pack_bf(h0, h1);
            dl[j] = pack_bf(r[2 * j] - h0, r[2 * j + 1] - h1);
        }
    } else {
        if (t >= (SEQ / 2) * NH) return;
        int kp = t >> 5, h = t & 31;
        const float* a = g_V + (size_t)(2 * kp) * DM + h * HD;
        const float* b = a + DM;
        unsigned* dh = g_VHp + ((size_t)h * (SEQ / 2) + kp) * 64;
        unsigned* dl = g_VLp + ((size_t)h * (SEQ / 2) + kp) * 64;
#pragma unroll 8
        for (int d = 0; d < 64; d++) {
            float va = a[d], vb = b[d];
            float hA = bf_hi(va), hB = bf_hi(vb);
            dh[d] = pack_bf(hA, hB);
            dl[d] = pack_bf(va - hA, vb - hB);
        }
    }
}

// ---------------------------------------------------------------------------
// TF32 tensor-core GEMM, double-buffered smem + register prefetch, 2 CTAs/SM.
// C[M,N] = A[M,K] * B[N,K]^T, M=N=K=2048. 128x128x32 tile, 8 warps 4x2.
// Dynamic smem: 2 buffers x (As 4608 + Bs 4608) words = 73728 B.
// ---------------------------------------------------------------------------
#define SST 36
#define GBUF 9216

__device__ __forceinline__ void gemm_store_tile(unsigned* As, unsigned* Bs,
                                                const float4* av, const float4* bv,
                                                int lrow, int lcol) {
#pragma unroll
    for (int p = 0; p < 4; p++) {
        int row = lrow + p * 32;
        unsigned* as = &As[row * SST + lcol];
        as[0] = f2tf32(av[p].x); as[1] = f2tf32(av[p].y);
        as[2] = f2tf32(av[p].z); as[3] = f2tf32(av[p].w);
        unsigned* bs = &Bs[row * SST + lcol];
        bs[0] = f2tf32(bv[p].x); bs[1] = f2tf32(bv[p].y);
        bs[2] = f2tf32(bv[p].z); bs[3] = f2tf32(bv[p].w);
    }
}

__device__ __forceinline__ void gemm_compute_k8(const unsigned* As, const unsigned* Bs,
                                                float acc[2][8][4], int k8,
                                                int wm, int wn, int g, int tg) {
    int c = k8 * 8 + tg;
    unsigned afr[2][4], bfr[8][2];
#pragma unroll
    for (int mi = 0; mi < 2; mi++) {
        int r = wm * 32 + mi * 16 + g;
        afr[mi][0] = As[r * SST + c];
        afr[mi][1] = As[(r + 8) * SST + c];
        afr[mi][2] = As[r * SST + c + 4];
        afr[mi][3] = As[(r + 8) * SST + c + 4];
    }
#pragma unroll
    for (int ni = 0; ni < 8; ni++) {
        int n = wn * 64 + ni * 8 + g;
        bfr[ni][0] = Bs[n * SST + c];
        bfr[ni][1] = Bs[n * SST + c + 4];
    }
#pragma unroll
    for (int mi = 0; mi < 2; mi++)
#pragma unroll
        for (int ni = 0; ni < 8; ni++)
            mma_tf32(acc[mi][ni], afr[mi], bfr[ni]);
}

__device__ __forceinline__ void gemm_body(float* __restrict__ C,
                                          const float* __restrict__ A,
                                          const float* __restrict__ B) {
    extern __shared__ unsigned gsm[];

    int tid = threadIdx.x;
    int lane = tid & 31, warp = tid >> 5;
    int wm = warp >> 1, wn = warp & 1;
    int g = lane >> 2, tg = lane & 3;
    int bm = blockIdx.y * 128, bn = blockIdx.x * 128;

    int lrow = tid >> 3;
    int lcol = (tid & 7) * 4;

    float acc[2][8][4];
#pragma unroll
    for (int mi = 0; mi < 2; mi++)
#pragma unroll
        for (int ni = 0; ni < 8; ni++)
#pragma unroll
            for (int j = 0; j < 4; j++) acc[mi][ni][j] = 0.0f;

    const float* Ap = A + (size_t)(bm + lrow) * DM + lcol;
    const float* Bp = B + (size_t)(bn + lrow) * DM + lcol;

    float4 av[4], bv[4];
#pragma unroll
    for (int p = 0; p < 4; p++) {
        av[p] = *(const float4*)(Ap + (size_t)p * 32 * DM);
        bv[p] = *(const float4*)(Bp + (size_t)p * 32 * DM);
    }
    gemm_store_tile(gsm, gsm + 4608, av, bv, lrow, lcol);

    int cur = 0;
    for (int k0 = 0; k0 < DM; k0 += 32) {
        __syncthreads();
        bool more = (k0 + 32 < DM);
        if (more) {
#pragma unroll
            for (int p = 0; p < 4; p++) {
                av[p] = *(const float4*)(Ap + (size_t)p * 32 * DM + k0 + 32);
                bv[p] = *(const float4*)(Bp + (size_t)p * 32 * DM + k0 + 32);
            }
        }
        unsigned* As = gsm + cur * GBUF;
        unsigned* Bs = As + 4608;
        gemm_compute_k8(As, Bs, acc, 0, wm, wn, g, tg);
        gemm_compute_k8(As, Bs, acc, 1, wm, wn, g, tg);
        if (more) {
            unsigned* An = gsm + (cur ^ 1) * GBUF;
            gemm_store_tile(An, An + 4608, av, bv, lrow, lcol);
        }
        gemm_compute_k8(As, Bs, acc, 2, wm, wn, g, tg);
        gemm_compute_k8(As, Bs, acc, 3, wm, wn, g, tg);
        cur ^= 1;
    }

#pragma unroll
    for (int mi = 0; mi < 2; mi++)
#pragma unroll
        for (int ni = 0; ni < 8; ni++) {
            int r0 = bm + wm * 32 + mi * 16 + g;
            int cc = bn + wn * 64 + ni * 8 + 2 * tg;
            *(float2*)&C[(size_t)r0 * DM + cc] =
                make_float2(acc[mi][ni][0], acc[mi][ni][1]);
            *(float2*)&C[(size_t)(r0 + 8) * DM + cc] =
                make_float2(acc[mi][ni][2], acc[mi][ni][3]);
        }
}

__global__ void __launch_bounds__(256, 2) gemm_qkv_kernel(const float* __restrict__ x,
                                                          const float* __restrict__ Wq,
                                                          const float* __restrict__ Wk,
                                                          const float* __restrict__ Wv) {
    const float* B;
    float* C;
    if (blockIdx.z == 0)      { B = Wq; C = g_Q; }
    else if (blockIdx.z == 1) { B = Wk; C = g_K; }
    else                      { B = Wv; C = g_V; }
    gemm_body(C, x, B);
}

__global__ void __launch_bounds__(256, 2) gemm_out_kernel(float* __restrict__ C,
                                                          const float* __restrict__ Wo) {
    gemm_body(C, g_att, Wo);
}

// ---------------------------------------------------------------------------
// Split-BF16 flash attention, cp.async double-buffered tiles.
// Operands come preprocessed from g_{Q,K}{H,L}p / g_V{H,L}p; inner loop is
// pure cp.async + mma + softmax. Smem per buffer: KH/KL 64x36, VH/VL 32x72
// (= 9216 words); x2 buffers + 2048-word mask = 20480 words = 81920 B.
// ---------------------------------------------------------------------------
#define BQ 128
#define BK 64
#define KWST 36
#define VWST 72
#define ABUF 9216
#define AOFF_KH 0
#define AOFF_KL 2304
#define AOFF_VH 4608
#define AOFF_VL 6912
#define AOFF_MS 18432
#define ASMEM_BYTES ((AOFF_MS + SEQ) * 4)   // 81920

__device__ __forceinline__ void attn_issue_tile(unsigned* buf, int h, int k0) {
    int t = threadIdx.x;
    const unsigned* KHs = g_KHp + ((size_t)h * SEQ + k0) * 32;
    const unsigned* KLs = g_KLp + ((size_t)h * SEQ + k0) * 32;
    const unsigned* VHs = g_VHp + ((size_t)h * (SEQ / 2) + (k0 >> 1)) * 64;
    const unsigned* VLs = g_VLp + ((size_t)h * (SEQ / 2) + (k0 >> 1)) * 64;
#pragma unroll
    for (int i = 0; i < 2; i++) {
        int s = t + i * 256;             // 0..511
        int row = s >> 3, c = (s & 7) * 4;
        cp16(&buf[AOFF_KH + row * KWST + c], KHs + row * 32 + c);
        cp16(&buf[AOFF_KL + row * KWST + c], KLs + row * 32 + c);
    }
#pragma unroll
    for (int i = 0; i < 2; i++) {
        int s = t + i * 256;
        int kp = s >> 4, c = (s & 15) * 4;
        cp16(&buf[AOFF_VH + kp * VWST + c], VHs + kp * 64 + c);
        cp16(&buf[AOFF_VL + kp * VWST + c], VLs + kp * 64 + c);
    }
    cp_commit();
}

__global__ void __launch_bounds__(256, 2) attn_bf16_kernel(const int* __restrict__ mask) {
    extern __shared__ unsigned smu[];
    int* MS = (int*)(smu + AOFF_MS);

    int tid = threadIdx.x;
    int lane = tid & 31, w = tid >> 5;
    int g = lane >> 2, tg = lane & 3;
    int h = blockIdx.y;
    int q0 = blockIdx.x * BQ;

    // mask -> smem (whole sequence, once)
    for (int i = tid; i < SEQ; i += 256) MS[i] = mask[i];

    // start streaming tile 0
    attn_issue_tile(smu, h, 0);

    // Q fragments straight from preprocessed global
    unsigned qh[4][4], ql[4][4];
    {
        int rA = q0 + w * 16 + g, rB = rA + 8;
        const unsigned* QH = g_QHp + (size_t)h * SEQ * 32;
        const unsigned* QL = g_QLp + (size_t)h * SEQ * 32;
#pragma unroll
        for (int ks = 0; ks < 4; ks++) {
            int c = ks * 8 + tg;
            qh[ks][0] = QH[rA * 32 + c];
            qh[ks][1] = QH[rB * 32 + c];
            qh[ks][2] = QH[rA * 32 + c + 4];
            qh[ks][3] = QH[rB * 32 + c + 4];
            ql[ks][0] = QL[rA * 32 + c];
            ql[ks][1] = QL[rB * 32 + c];
            ql[ks][2] = QL[rA * 32 + c + 4];
            ql[ks][3] = QL[rB * 32 + c + 4];
        }
    }

    float o[8][4];
#pragma unroll
    for (int ni = 0; ni < 8; ni++)
#pragma unroll
        for (int j = 0; j < 4; j++) o[ni][j] = 0.0f;
    float mA = -3.0e38f, mB = -3.0e38f, lA = 0.0f, lB = 0.0f;

    for (int kt = 0; kt < SEQ / BK; kt++) {
        int k0 = kt * BK;
        if (kt + 1 < SEQ / BK) {
            attn_issue_tile(smu + ((kt + 1) & 1) * ABUF, h, k0 + BK);
            cp_wait<1>();
        } else {
            cp_wait<0>();
        }
        __syncthreads();   // tile kt visible to all; MS ready on iter 0

        const unsigned* KH = smu + (kt & 1) * ABUF + AOFF_KH;
        const unsigned* KL = smu + (kt & 1) * ABUF + AOFF_KL;
        const unsigned* VH = smu + (kt & 1) * ABUF + AOFF_VH;
        const unsigned* VL = smu + (kt & 1) * ABUF + AOFF_VL;

        // --- S = Q . K^T ---
        float sacc[8][4];
#pragma unroll
        for (int ni = 0; ni < 8; ni++)
#pragma unroll
            for (int j = 0; j < 4; j++) sacc[ni][j] = 0.0f;

#pragma unroll
        for (int ks = 0; ks < 4; ks++) {
#pragma unroll
            for (int ni = 0; ni < 8; ni++) {
                int kr = ni * 8 + g;
                unsigned bh[2], bl[2];
                bh[0] = KH[kr * KWST + ks * 8 + tg];
                bh[1] = KH[kr * KWST + ks * 8 + tg + 4];
                bl[0] = KL[kr * KWST + ks * 8 + tg];
                bl[1] = KL[kr * KWST + ks * 8 + tg + 4];
                mma_bf16(sacc[ni], qh[ks], bh);
                mma_bf16(sacc[ni], ql[ks], bh);
                mma_bf16(sacc[ni], qh[ks], bl);
            }
        }

        // --- scale + mask ---
#pragma unroll
        for (int ni = 0; ni < 8; ni++) {
            int m0 = MS[k0 + ni * 8 + 2 * tg];
            int m1 = MS[k0 + ni * 8 + 2 * tg + 1];
            sacc[ni][0] = m0 ? sacc[ni][0] * 0.125f : -1.0e9f;
            sacc[ni][1] = m1 ? sacc[ni][1] * 0.125f : -1.0e9f;
            sacc[ni][2] = m0 ? sacc[ni][2] * 0.125f : -1.0e9f;
            sacc[ni][3] = m1 ? sacc[ni][3] * 0.125f : -1.0e9f;
        }

        // --- online softmax (rows g, g+8) ---
        float mxA = -3.0e38f, mxB = -3.0e38f;
#pragma unroll
        for (int ni = 0; ni < 8; ni++) {
            mxA = fmaxf(mxA, fmaxf(sacc[ni][0], sacc[ni][1]));
            mxB = fmaxf(mxB, fmaxf(sacc[ni][2], sacc[ni][3]));
        }
        mxA = fmaxf(mxA, __shfl_xor_sync(0xffffffffu, mxA, 1));
        mxA = fmaxf(mxA, __shfl_xor_sync(0xffffffffu, mxA, 2));
        mxB = fmaxf(mxB, __shfl_xor_sync(0xffffffffu, mxB, 1));
        mxB = fmaxf(mxB, __shfl_xor_sync(0xffffffffu, mxB, 2));

        float mnA = fmaxf(mA, mxA), mnB = fmaxf(mB, mxB);
        float corrA = exp2p((mA - mnA) * LOG2E);
        float corrB = exp2p((mB - mnB) * LOG2E);

        float sumA = 0.0f, sumB = 0.0f;
#pragma unroll
        for (int ni = 0; ni < 8; ni++) {
            sacc[ni][0] = exp2p((sacc[ni][0] - mnA) * LOG2E);
            sacc[ni][1] = exp2p((sacc[ni][1] - mnA) * LOG2E);
            sacc[ni][2] = exp2p((sacc[ni][2] - mnB) * LOG2E);
            sacc[ni][3] = exp2p((sacc[ni][3] - mnB) * LOG2E);
            sumA += sacc[ni][0] + sacc[ni][1];
            sumB += sacc[ni][2] + sacc[ni][3];
        }
        sumA += __shfl_xor_sync(0xffffffffu, sumA, 1);
        sumA += __shfl_xor_sync(0xffffffffu, sumA, 2);
        sumB += __shfl_xor_sync(0xffffffffu, sumB, 1);
        sumB += __shfl_xor_sync(0xffffffffu, sumB, 2);

        lA = lA * corrA + sumA;
        lB = lB * corrB + sumB;
        mA = mnA;
        mB = mnB;
#pragma unroll
        for (int ni = 0; ni < 8; ni++) {
            o[ni][0] *= corrA; o[ni][1] *= corrA;
            o[ni][2] *= corrB; o[ni][3] *= corrB;
        }

        // --- O += P . V (S C-frag == PV A-frag) ---
#pragma unroll
        for (int ks = 0; ks < 4; ks++) {
            unsigned ah[4], al[4];
#pragma unroll
            for (int half = 0; half < 2; half++) {
                const float* s2 = sacc[2 * ks + half];
                float h0 = bf_hi(s2[0]), h1 = bf_hi(s2[1]);
                float h2 = bf_hi(s2[2]), h3 = bf_hi(s2[3]);
                ah[2 * half]     = pack_bf(h0, h1);
                ah[2 * half + 1] = pack_bf(h2, h3);
                al[2 * half]     = pack_bf(s2[0] - h0, s2[1] - h1);
                al[2 * half + 1] = pack_bf(s2[2] - h2, s2[3] - h3);
            }
#pragma unroll
            for (int ni = 0; ni < 8; ni++) {
                int vr = ks * 8 + tg;
                unsigned bh[2], bl[2];
                bh[0] = VH[vr * VWST + ni * 8 + g];
                bh[1] = VH[(vr + 4) * VWST + ni * 8 + g];
                bl[0] = VL[vr * VWST + ni * 8 + g];
                bl[1] = VL[(vr + 4) * VWST + ni * 8 + g];
                mma_bf16(o[ni], ah, bh);
                mma_bf16(o[ni], al, bh);
                mma_bf16(o[ni], ah, bl);
            }
        }
        __syncthreads();   // readers done -> next issue may overwrite other buffer
    }

    // --- normalize + store ---
    float invA = 1.0f / lA, invB = 1.0f / lB;
    float* Og = g_att + (size_t)(q0 + w * 16) * DM + h * HD;
#pragma unroll
    for (int ni = 0; ni < 8; ni++) {
        *(float2*)&Og[(size_t)g * DM + ni * 8 + 2 * tg] =
            make_float2(o[ni][0] * invA, o[ni][1] * invA);
        *(float2*)&Og[(size_t)(g + 8) * DM + ni * 8 + 2 * tg] =
            make_float2(o[ni][2] * invB, o[ni][3] * invB);
    }
}

// ---------------------------------------------------------------------------
// launch
// ---------------------------------------------------------------------------
extern "C" void kernel_launch(void* const* d_in, const int* in_sizes, int n_in,
                              void* d_out, int out_size) {
    const float* x    = (const float*)d_in[0];
    const int*   mask = (const int*)d_in[1];
    const float* Wq   = (const float*)d_in[2];
    const float* Wk   = (const float*)d_in[3];
    const float* Wv   = (const float*)d_in[4];
    const float* Wo   = (const float*)d_in[5];
    float* out = (float*)d_out;

    const int gemm_smem = 2 * GBUF * (int)sizeof(unsigned);   // 73728
    cudaFuncSetAttribute(gemm_qkv_kernel, cudaFuncAttributeMaxDynamicSharedMemorySize,
                         gemm_smem);
    cudaFuncSetAttribute(gemm_out_kernel, cudaFuncAttributeMaxDynamicSharedMemorySize,
                         gemm_smem);
    cudaFuncSetAttribute(attn_bf16_kernel, cudaFuncAttributeMaxDynamicSharedMemorySize,
                         ASMEM_BYTES);

    rope_table_kernel<<<(SEQ * 32 + 255) / 256, 256>>>();
    gemm_qkv_kernel<<<dim3(16, 16, 3), 256, gemm_smem>>>(x, Wq, Wk, Wv);
    preprocess_kernel<<<dim3((SEQ * NH + 255) / 256, 3), 256>>>();
    attn_bf16_kernel<<<dim3(SEQ / BQ, NH), 256, ASMEM_BYTES>>>(mask);
    gemm_out_kernel<<<dim3(16, 16), 256, gemm_smem>>>(out, Wo);
}

// round 9
// speedup vs baseline: 1.0121x; 1.0121x over previous
#include <cuda_runtime.h>
#include <cuda_bf16.h>

#define SEQ 2048
#define DM 2048
#define NH 32
#define HD 64

// Scratch (static device allocations are allowed; cudaMalloc is not)
__device__ float g_Q[SEQ * DM];
__device__ float g_K[SEQ * DM];
__device__ float g_V[SEQ * DM];
__device__ float g_att[SEQ * DM];
__device__ float g_cos[SEQ * 32];
__device__ float g_sin[SEQ * 32];

// tf32-rounded copies of the GEMM inputs (so mma's internal truncation is a
// no-op and cp.async can feed smem directly -> numerics identical to cvt.rna).
__device__ float g_xr[SEQ * DM];
__device__ float g_Wqr[DM * DM];
__device__ float g_Wkr[DM * DM];
__device__ float g_Wvr[DM * DM];
__device__ float g_Wor[DM * DM];

// Preprocessed (roped, hi/lo-split, bf16x2-packed) operands for attention.
__device__ unsigned g_QHp[NH * SEQ * 32];
__device__ unsigned g_QLp[NH * SEQ * 32];
__device__ unsigned g_KHp[NH * SEQ * 32];
__device__ unsigned g_KLp[NH * SEQ * 32];
__device__ unsigned g_VHp[NH * (SEQ / 2) * 64];
__device__ unsigned g_VLp[NH * (SEQ / 2) * 64];

// ---------------------------------------------------------------------------
// helpers
// ---------------------------------------------------------------------------
__device__ __forceinline__ unsigned f2tf32(float f) {
    unsigned r;
    asm("cvt.rna.tf32.f32 %0, %1;" : "=r"(r) : "f"(f));
    return r;
}

__device__ __forceinline__ float tf32r(float f) {
    return __uint_as_float(f2tf32(f));
}

// operands are fp32 bit patterns already rounded to tf32
__device__ __forceinline__ void mma_tf32(float* c, const unsigned* a, const unsigned* b) {
    asm volatile(
        "mma.sync.aligned.m16n8k8.row.col.f32.tf32.tf32.f32 "
        "{%0,%1,%2,%3}, {%4,%5,%6,%7}, {%8,%9}, {%0,%1,%2,%3};"
        : "+f"(c[0]), "+f"(c[1]), "+f"(c[2]), "+f"(c[3])
        : "r"(a[0]), "r"(a[1]), "r"(a[2]), "r"(a[3]), "r"(b[0]), "r"(b[1]));
}

__device__ __forceinline__ void mma_bf16(float* c, const unsigned* a, const unsigned* b) {
    asm volatile(
        "mma.sync.aligned.m16n8k16.row.col.f32.bf16.bf16.f32 "
        "{%0,%1,%2,%3}, {%4,%5,%6,%7}, {%8,%9}, {%0,%1,%2,%3};"
        : "+f"(c[0]), "+f"(c[1]), "+f"(c[2]), "+f"(c[3])
        : "r"(a[0]), "r"(a[1]), "r"(a[2]), "r"(a[3]), "r"(b[0]), "r"(b[1]));
}

__device__ __forceinline__ unsigned pack_bf(float e0, float e1) {
    unsigned r;
    asm("cvt.rn.bf16x2.f32 %0, %1, %2;" : "=r"(r) : "f"(e1), "f"(e0));
    return r;
}

__device__ __forceinline__ float bf_hi(float x) {
    return __bfloat162float(__float2bfloat16(x));
}

__device__ __forceinline__ void cp16(void* sptr, const void* gptr) {
    unsigned sa = (unsigned)__cvta_generic_to_shared(sptr);
    asm volatile("cp.async.cg.shared.global [%0], [%1], 16;" :: "r"(sa), "l"(gptr)
                 : "memory");
}
__device__ __forceinline__ void cp_commit() {
    asm volatile("cp.async.commit_group;" ::: "memory");
}
template <int N>
__device__ __forceinline__ void cp_wait() {
    asm volatile("cp.async.wait_group %0;" :: "n"(N) : "memory");
}

// FMA-pipe exp2 (no MUFU)
__device__ __forceinline__ float exp2p(float y) {
    y = fmaxf(y, -126.0f);
    float z = y + 12582912.0f;
    int i = __float_as_int(z) - 0x4B400000;
    float f = y - (z - 12582912.0f);
    float p = 1.3534384e-3f;
    p = fmaf(p, f, 9.6181291e-3f);
    p = fmaf(p, f, 5.5504109e-2f);
    p = fmaf(p, f, 2.4022650e-1f);
    p = fmaf(p, f, 6.9314718e-1f);
    p = fmaf(p, f, 1.0f);
    return __int_as_float(__float_as_int(p) + (i << 23));
}

#define LOG2E 1.4426950408889634f

// ---------------------------------------------------------------------------
// RoPE cos/sin table
// ---------------------------------------------------------------------------
__global__ void rope_table_kernel() {
    int idx = blockIdx.x * blockDim.x + threadIdx.x;
    if (idx >= SEQ * 32) return;
    int l = idx >> 5;
    int j = idx & 31;
    float invf = powf(10000.0f, -(float)j * (1.0f / 32.0f));
    float fr = (float)l * invf;
    g_cos[idx] = cosf(fr);
    g_sin[idx] = sinf(fr);
}

// ---------------------------------------------------------------------------
// RNA-round the five GEMM input matrices to tf32 (blockIdx.y selects array)
// ---------------------------------------------------------------------------
__global__ void __launch_bounds__(256) round_tf32_kernel(
    const float* __restrict__ x,  const float* __restrict__ Wq,
    const float* __restrict__ Wk, const float* __restrict__ Wv,
    const float* __restrict__ Wo) {
    int idx = blockIdx.x * blockDim.x + threadIdx.x;   // float4 index, 1M per array
    if (idx >= (SEQ * DM) / 4) return;
    const float* src;
    float* dst;
    switch (blockIdx.y) {
        case 0:  src = x;  dst = g_xr;  break;
        case 1:  src = Wq; dst = g_Wqr; break;
        case 2:  src = Wk; dst = g_Wkr; break;
        case 3:  src = Wv; dst = g_Wvr; break;
        default: src = Wo; dst = g_Wor; break;
    }
    float4 v = ((const float4*)src)[idx];
    v.x = tf32r(v.x); v.y = tf32r(v.y); v.z = tf32r(v.z); v.w = tf32r(v.w);
    ((float4*)dst)[idx] = v;
}

// ---------------------------------------------------------------------------
// Preprocess: rope+split Q,K (blockIdx.y 0/1), split-pair V (blockIdx.y 2)
// ---------------------------------------------------------------------------
__global__ void __launch_bounds__(256) preprocess_kernel() {
    int t = blockIdx.x * blockDim.x + threadIdx.x;
    int which = blockIdx.y;
    if (which < 2) {
        if (t >= SEQ * NH) return;
        int l = t >> 5, h = t & 31;
        const float* src = (which == 0 ? g_Q : g_K) + (size_t)l * DM + h * HD;
        unsigned* dh = (which == 0 ? g_QHp : g_KHp) + ((size_t)h * SEQ + l) * 32;
        unsigned* dl = (which == 0 ? g_QLp : g_KLp) + ((size_t)h * SEQ + l) * 32;
        float v[64];
#pragma unroll
        for (int i = 0; i < 16; i++)
            *(float4*)(v + 4 * i) = *(const float4*)(src + 4 * i);
        float r[64];
#pragma unroll
        for (int p = 0; p < 32; p++) {
            float c = g_cos[l * 32 + p];
            float s = g_sin[l * 32 + p];
            r[p]      = v[2 * p] * c - v[2 * p + 1] * s;
            r[32 + p] = v[2 * p] * s + v[2 * p + 1] * c;
        }
#pragma unroll
        for (int j = 0; j < 32; j++) {
            float h0 = bf_hi(r[2 * j]), h1 = bf_hi(r[2 * j + 1]);
            dh[j] = pack_bf(h0, h1);
            dl[j] = pack_bf(r[2 * j] - h0, r[2 * j + 1] - h1);
        }
    } else {
        if (t >= (SEQ / 2) * NH) return;
        int kp = t >> 5, h = t & 31;
        const float* a = g_V + (size_t)(2 * kp) * DM + h * HD;
        const float* b = a + DM;
        unsigned* dh = g_VHp + ((size_t)h * (SEQ / 2) + kp) * 64;
        unsigned* dl = g_VLp + ((size_t)h * (SEQ / 2) + kp) * 64;
#pragma unroll 8
        for (int d = 0; d < 64; d++) {
            float va = a[d], vb = b[d];
            float hA = bf_hi(va), hB = bf_hi(vb);
            dh[d] = pack_bf(hA, hB);
            dl[d] = pack_bf(va - hA, vb - hB);
        }
    }
}

// ---------------------------------------------------------------------------
// TF32 GEMM, cp.async double-buffered, operands pre-rounded to tf32.
// C[M,N] = A[M,K] * B[N,K]^T, M=N=K=2048. 128x128x32 tile, 8 warps 4x2,
// 2 CTAs/SM. No LDG/CVT/STS in the loop: pure cp.async + LDS + HMMA.
// ---------------------------------------------------------------------------
#define SST 36
#define GTW (128 * SST)        // words per matrix tile: 4608
#define GBUFW (2 * GTW)        // A+B per buffer: 9216
#define GSMEM_BYTES (2 * GBUFW * 4)   // 73728

__device__ __forceinline__ void g_issue(unsigned* buf, const float* A, const float* B,
                                        int bm, int bn, int k0) {
    int t = threadIdx.x;
#pragma unroll
    for (int i = 0; i < 4; i++) {
        int s = t + i * 256;            // 0..1023
        int row = s >> 3, c4 = (s & 7) * 4;
        cp16(&buf[row * SST + c4], A + (size_t)(bm + row) * DM + k0 + c4);
        cp16(&buf[GTW + row * SST + c4], B + (size_t)(bn + row) * DM + k0 + c4);
    }
    cp_commit();
}

__device__ __forceinline__ void gemm_compute_k8(const unsigned* As, const unsigned* Bs,
                                                float acc[2][8][4], int k8,
                                                int wm, int wn, int g, int tg) {
    int c = k8 * 8 + tg;
    unsigned afr[2][4], bfr[8][2];
#pragma unroll
    for (int mi = 0; mi < 2; mi++) {
        int r = wm * 32 + mi * 16 + g;
        afr[mi][0] = As[r * SST + c];
        afr[mi][1] = As[(r + 8) * SST + c];
        afr[mi][2] = As[r * SST + c + 4];
        afr[mi][3] = As[(r + 8) * SST + c + 4];
    }
#pragma unroll
    for (int ni = 0; ni < 8; ni++) {
        int n = wn * 64 + ni * 8 + g;
        bfr[ni][0] = Bs[n * SST + c];
        bfr[ni][1] = Bs[n * SST + c + 4];
    }
#pragma unroll
    for (int mi = 0; mi < 2; mi++)
#pragma unroll
        for (int ni = 0; ni < 8; ni++)
            mma_tf32(acc[mi][ni], afr[mi], bfr[ni]);
}

__device__ __forceinline__ void gemm_body(float* __restrict__ C,
                                          const float* __restrict__ A,
                                          const float* __restrict__ B) {
    extern __shared__ unsigned gsm[];

    int tid = threadIdx.x;
    int lane = tid & 31, warp = tid >> 5;
    int wm = warp >> 1, wn = warp & 1;
    int g = lane >> 2, tg = lane & 3;
    int bm = blockIdx.y * 128, bn = blockIdx.x * 128;

    float acc[2][8][4];
#pragma unroll
    for (int mi = 0; mi < 2; mi++)
#pragma unroll
        for (int ni = 0; ni < 8; ni++)
#pragma unroll
            for (int j = 0; j < 4; j++) acc[mi][ni][j] = 0.0f;

    g_issue(gsm, A, B, bm, bn, 0);

    for (int kt = 0; kt < DM / 32; kt++) {
        if (kt + 1 < DM / 32) {
            g_issue(gsm + ((kt + 1) & 1) * GBUFW, A, B, bm, bn, (kt + 1) * 32);
            cp_wait<1>();
        } else {
            cp_wait<0>();
        }
        __syncthreads();
        const unsigned* As = gsm + (kt & 1) * GBUFW;
        const unsigned* Bs = As + GTW;
        gemm_compute_k8(As, Bs, acc, 0, wm, wn, g, tg);
        gemm_compute_k8(As, Bs, acc, 1, wm, wn, g, tg);
        gemm_compute_k8(As, Bs, acc, 2, wm, wn, g, tg);
        gemm_compute_k8(As, Bs, acc, 3, wm, wn, g, tg);
        __syncthreads();
    }

#pragma unroll
    for (int mi = 0; mi < 2; mi++)
#pragma unroll
        for (int ni = 0; ni < 8; ni++) {
            int r0 = bm + wm * 32 + mi * 16 + g;
            int cc = bn + wn * 64 + ni * 8 + 2 * tg;
            *(float2*)&C[(size_t)r0 * DM + cc] =
                make_float2(acc[mi][ni][0], acc[mi][ni][1]);
            *(float2*)&C[(size_t)(r0 + 8) * DM + cc] =
                make_float2(acc[mi][ni][2], acc[mi][ni][3]);
        }
}

__global__ void __launch_bounds__(256, 2) gemm_qkv_kernel() {
    const float* B;
    float* C;
    if (blockIdx.z == 0)      { B = g_Wqr; C = g_Q; }
    else if (blockIdx.z == 1) { B = g_Wkr; C = g_K; }
    else                      { B = g_Wvr; C = g_V; }
    gemm_body(C, g_xr, B);
}

__global__ void __launch_bounds__(256, 2) gemm_out_kernel(float* __restrict__ C) {
    gemm_body(C, g_att, g_Wor);
}

// ---------------------------------------------------------------------------
// Split-BF16 flash attention, cp.async double-buffered (round-7 version).
// Epilogue writes g_att pre-rounded to tf32 for the out-GEMM.
// ---------------------------------------------------------------------------
#define BQ 128
#define BK 64
#define KWST 36
#define VWST 72
#define ABUF 9216
#define AOFF_KH 0
#define AOFF_KL 2304
#define AOFF_VH 4608
#define AOFF_VL 6912
#define AOFF_MS 18432
#define ASMEM_BYTES ((AOFF_MS + SEQ) * 4)   // 81920

__device__ __forceinline__ void attn_issue_tile(unsigned* buf, int h, int k0) {
    int t = threadIdx.x;
    const unsigned* KHs = g_KHp + ((size_t)h * SEQ + k0) * 32;
    const unsigned* KLs = g_KLp + ((size_t)h * SEQ + k0) * 32;
    const unsigned* VHs = g_VHp + ((size_t)h * (SEQ / 2) + (k0 >> 1)) * 64;
    const unsigned* VLs = g_VLp + ((size_t)h * (SEQ / 2) + (k0 >> 1)) * 64;
#pragma unroll
    for (int i = 0; i < 2; i++) {
        int s = t + i * 256;
        int row = s >> 3, c = (s & 7) * 4;
        cp16(&buf[AOFF_KH + row * KWST + c], KHs + row * 32 + c);
        cp16(&buf[AOFF_KL + row * KWST + c], KLs + row * 32 + c);
    }
#pragma unroll
    for (int i = 0; i < 2; i++) {
        int s = t + i * 256;
        int kp = s >> 4, c = (s & 15) * 4;
        cp16(&buf[AOFF_VH + kp * VWST + c], VHs + kp * 64 + c);
        cp16(&buf[AOFF_VL + kp * VWST + c], VLs + kp * 64 + c);
    }
    cp_commit();
}

__global__ void __launch_bounds__(256, 2) attn_bf16_kernel(const int* __restrict__ mask) {
    extern __shared__ unsigned smu[];
    int* MS = (int*)(smu + AOFF_MS);

    int tid = threadIdx.x;
    int lane = tid & 31, w = tid >> 5;
    int g = lane >> 2, tg = lane & 3;
    int h = blockIdx.y;
    int q0 = blockIdx.x * BQ;

    for (int i = tid; i < SEQ; i += 256) MS[i] = mask[i];

    attn_issue_tile(smu, h, 0);

    unsigned qh[4][4], ql[4][4];
    {
        int rA = q0 + w * 16 + g, rB = rA + 8;
        const unsigned* QH = g_QHp + (size_t)h * SEQ * 32;
        const unsigned* QL = g_QLp + (size_t)h * SEQ * 32;
#pragma unroll
        for (int ks = 0; ks < 4; ks++) {
            int c = ks * 8 + tg;
            qh[ks][0] = QH[rA * 32 + c];
            qh[ks][1] = QH[rB * 32 + c];
            qh[ks][2] = QH[rA * 32 + c + 4];
            qh[ks][3] = QH[rB * 32 + c + 4];
            ql[ks][0] = QL[rA * 32 + c];
            ql[ks][1] = QL[rB * 32 + c];
            ql[ks][2] = QL[rA * 32 + c + 4];
            ql[ks][3] = QL[rB * 32 + c + 4];
        }
    }

    float o[8][4];
#pragma unroll
    for (int ni = 0; ni < 8; ni++)
#pragma unroll
        for (int j = 0; j < 4; j++) o[ni][j] = 0.0f;
    float mA = -3.0e38f, mB = -3.0e38f, lA = 0.0f, lB = 0.0f;

    for (int kt = 0; kt < SEQ / BK; kt++) {
        int k0 = kt * BK;
        if (kt + 1 < SEQ / BK) {
            attn_issue_tile(smu + ((kt + 1) & 1) * ABUF, h, k0 + BK);
            cp_wait<1>();
        } else {
            cp_wait<0>();
        }
        __syncthreads();

        const unsigned* KH = smu + (kt & 1) * ABUF + AOFF_KH;
        const unsigned* KL = smu + (kt & 1) * ABUF + AOFF_KL;
        const unsigned* VH = smu + (kt & 1) * ABUF + AOFF_VH;
        const unsigned* VL = smu + (kt & 1) * ABUF + AOFF_VL;

        float sacc[8][4];
#pragma unroll
        for (int ni = 0; ni < 8; ni++)
#pragma unroll
            for (int j = 0; j < 4; j++) sacc[ni][j] = 0.0f;

#pragma unroll
        for (int ks = 0; ks < 4; ks++) {
#pragma unroll
            for (int ni = 0; ni < 8; ni++) {
                int kr = ni * 8 + g;
                unsigned bh[2], bl[2];
                bh[0] = KH[kr * KWST + ks * 8 + tg];
                bh[1] = KH[kr * KWST + ks * 8 + tg + 4];
                bl[0] = KL[kr * KWST + ks * 8 + tg];
                bl[1] = KL[kr * KWST + ks * 8 + tg + 4];
                mma_bf16(sacc[ni], qh[ks], bh);
                mma_bf16(sacc[ni], ql[ks], bh);
                mma_bf16(sacc[ni], qh[ks], bl);
            }
        }

#pragma unroll
        for (int ni = 0; ni < 8; ni++) {
            int m0 = MS[k0 + ni * 8 + 2 * tg];
            int m1 = MS[k0 + ni * 8 + 2 * tg + 1];
            sacc[ni][0] = m0 ? sacc[ni][0] * 0.125f : -1.0e9f;
            sacc[ni][1] = m1 ? sacc[ni][1] * 0.125f : -1.0e9f;
            sacc[ni][2] = m0 ? sacc[ni][2] * 0.125f : -1.0e9f;
            sacc[ni][3] = m1 ? sacc[ni][3] * 0.125f : -1.0e9f;
        }

        float mxA = -3.0e38f, mxB = -3.0e38f;
#pragma unroll
        for (int ni = 0; ni < 8; ni++) {
            mxA = fmaxf(mxA, fmaxf(sacc[ni][0], sacc[ni][1]));
            mxB = fmaxf(mxB, fmaxf(sacc[ni][2], sacc[ni][3]));
        }
        mxA = fmaxf(mxA, __shfl_xor_sync(0xffffffffu, mxA, 1));
        mxA = fmaxf(mxA, __shfl_xor_sync(0xffffffffu, mxA, 2));
        mxB = fmaxf(mxB, __shfl_xor_sync(0xffffffffu, mxB, 1));
        mxB = fmaxf(mxB, __shfl_xor_sync(0xffffffffu, mxB, 2));

        float mnA = fmaxf(mA, mxA), mnB = fmaxf(mB, mxB);
        float corrA = exp2p((mA - mnA) * LOG2E);
        float corrB = exp2p((mB - mnB) * LOG2E);

        float sumA = 0.0f, sumB = 0.0f;
#pragma unroll
        for (int ni = 0; ni < 8; ni++) {
            sacc[ni][0] = exp2p((sacc[ni][0] - mnA) * LOG2E);
            sacc[ni][1] = exp2p((sacc[ni][1] - mnA) * LOG2E);
            sacc[ni][2] = exp2p((sacc[ni][2] - mnB) * LOG2E);
            sacc[ni][3] = exp2p((sacc[ni][3] - mnB) * LOG2E);
            sumA += sacc[ni][0] + sacc[ni][1];
            sumB += sacc[ni][2] + sacc[ni][3];
        }
        sumA += __shfl_xor_sync(0xffffffffu, sumA, 1);
        sumA += __shfl_xor_sync(0xffffffffu, sumA, 2);
        sumB += __shfl_xor_sync(0xffffffffu, sumB, 1);
        sumB += __shfl_xor_sync(0xffffffffu, sumB, 2);

        lA = lA * corrA + sumA;
        lB = lB * corrB + sumB;
        mA = mnA;
        mB = mnB;
#pragma unroll
        for (int ni = 0; ni < 8; ni++) {
            o[ni][0] *= corrA; o[ni][1] *= corrA;
            o[ni][2] *= corrB; o[ni][3] *= corrB;
        }

#pragma unroll
        for (int ks = 0; ks < 4; ks++) {
            unsigned ah[4], al[4];
#pragma unroll
            for (int half = 0; half < 2; half++) {
                const float* s2 = sacc[2 * ks + half];
                float h0 = bf_hi(s2[0]), h1 = bf_hi(s2[1]);
                float h2 = bf_hi(s2[2]), h3 = bf_hi(s2[3]);
                ah[2 * half]     = pack_bf(h0, h1);
                ah[2 * half + 1] = pack_bf(h2, h3);
                al[2 * half]     = pack_bf(s2[0] - h0, s2[1] - h1);
                al[2 * half + 1] = pack_bf(s2[2] - h2, s2[3] - h3);
            }
#pragma unroll
            for (int ni = 0; ni < 8; ni++) {
                int vr = ks * 8 + tg;
                unsigned bh[2], bl[2];
                bh[0] = VH[vr * VWST + ni * 8 + g];
                bh[1] = VH[(vr + 4) * VWST + ni * 8 + g];
                bl[0] = VL[vr * VWST + ni * 8 + g];
                bl[1] = VL[(vr + 4) * VWST + ni * 8 + g];
                mma_bf16(o[ni], ah, bh);
                mma_bf16(o[ni], al, bh);
                mma_bf16(o[ni], ah, bl);
            }
        }
        __syncthreads();
    }

    // normalize + store, pre-rounded to tf32 for the out-GEMM
    float invA = 1.0f / lA, invB = 1.0f / lB;
    float* Og = g_att + (size_t)(q0 + w * 16) * DM + h * HD;
#pragma unroll
    for (int ni = 0; ni < 8; ni++) {
        *(float2*)&Og[(size_t)g * DM + ni * 8 + 2 * tg] =
            make_float2(tf32r(o[ni][0] * invA), tf32r(o[ni][1] * invA));
        *(float2*)&Og[(size_t)(g + 8) * DM + ni * 8 + 2 * tg] =
            make_float2(tf32r(o[ni][2] * invB), tf32r(o[ni][3] * invB));
    }
}

// ---------------------------------------------------------------------------
// launch
// ---------------------------------------------------------------------------
extern "C" void kernel_launch(void* const* d_in, const int* in_sizes, int n_in,
                              void* d_out, int out_size) {
    const float* x    = (const float*)d_in[0];
    const int*   mask = (const int*)d_in[1];
    const float* Wq   = (const float*)d_in[2];
    const float* Wk   = (const float*)d_in[3];
    const float* Wv   = (const float*)d_in[4];
    const float* Wo   = (const float*)d_in[5];
    float* out = (float*)d_out;

    cudaFuncSetAttribute(gemm_qkv_kernel, cudaFuncAttributeMaxDynamicSharedMemorySize,
                         GSMEM_BYTES);
    cudaFuncSetAttribute(gemm_out_kernel, cudaFuncAttributeMaxDynamicSharedMemorySize,
                         GSMEM_BYTES);
    cudaFuncSetAttribute(attn_bf16_kernel, cudaFuncAttributeMaxDynamicSharedMemorySize,
                         ASMEM_BYTES);

    rope_table_kernel<<<(SEQ * 32 + 255) / 256, 256>>>();
    round_tf32_kernel<<<dim3((SEQ * DM / 4 + 255) / 256, 5), 256>>>(x, Wq, Wk, Wv, Wo);
    gemm_qkv_kernel<<<dim3(16, 16, 3), 256, GSMEM_BYTES>>>();
    preprocess_kernel<<<dim3((SEQ * NH + 255) / 256, 3), 256>>>();
    attn_bf16_kernel<<<dim3(SEQ / BQ, NH), 256, ASMEM_BYTES>>>(mask);
    gemm_out_kernel<<<dim3(16, 16), 256, GSMEM_BYTES>>>(out);
}

// round 10
// speedup vs baseline: 1.1394x; 1.1258x over previous
#include <cuda_runtime.h>
#include <cuda_bf16.h>

#define SEQ 2048
#define DM 2048
#define NH 32
#define HD 64

// Scratch (static device allocations are allowed; cudaMalloc is not)
__device__ float g_Q[SEQ * DM];
__device__ float g_K[SEQ * DM];
__device__ float g_V[SEQ * DM];
__device__ float g_att[SEQ * DM];
__device__ float g_cos[SEQ * 32];
__device__ float g_sin[SEQ * 32];

// tf32-rounded copies of the GEMM inputs (so mma's internal truncation is a
// no-op and cp.async can feed smem directly -> numerics identical to cvt.rna).
__device__ float g_xr[SEQ * DM];
__device__ float g_Wqr[DM * DM];
__device__ float g_Wkr[DM * DM];
__device__ float g_Wvr[DM * DM];
__device__ float g_Wor[DM * DM];

// Preprocessed (roped, hi/lo-split, bf16x2-packed) operands for attention.
__device__ unsigned g_QHp[NH * SEQ * 32];
__device__ unsigned g_QLp[NH * SEQ * 32];
__device__ unsigned g_KHp[NH * SEQ * 32];
__device__ unsigned g_KLp[NH * SEQ * 32];
__device__ unsigned g_VHp[NH * (SEQ / 2) * 64];
__device__ unsigned g_VLp[NH * (SEQ / 2) * 64];

// ---------------------------------------------------------------------------
// helpers
// ---------------------------------------------------------------------------
__device__ __forceinline__ unsigned f2tf32(float f) {
    unsigned r;
    asm("cvt.rna.tf32.f32 %0, %1;" : "=r"(r) : "f"(f));
    return r;
}

__device__ __forceinline__ float tf32r(float f) {
    return __uint_as_float(f2tf32(f));
}

// operands are fp32 bit patterns already rounded to tf32
__device__ __forceinline__ void mma_tf32(float* c, const unsigned* a, const unsigned* b) {
    asm volatile(
        "mma.sync.aligned.m16n8k8.row.col.f32.tf32.tf32.f32 "
        "{%0,%1,%2,%3}, {%4,%5,%6,%7}, {%8,%9}, {%0,%1,%2,%3};"
        : "+f"(c[0]), "+f"(c[1]), "+f"(c[2]), "+f"(c[3])
        : "r"(a[0]), "r"(a[1]), "r"(a[2]), "r"(a[3]), "r"(b[0]), "r"(b[1]));
}

__device__ __forceinline__ void mma_bf16(float* c, const unsigned* a, const unsigned* b) {
    asm volatile(
        "mma.sync.aligned.m16n8k16.row.col.f32.bf16.bf16.f32 "
        "{%0,%1,%2,%3}, {%4,%5,%6,%7}, {%8,%9}, {%0,%1,%2,%3};"
        : "+f"(c[0]), "+f"(c[1]), "+f"(c[2]), "+f"(c[3])
        : "r"(a[0]), "r"(a[1]), "r"(a[2]), "r"(a[3]), "r"(b[0]), "r"(b[1]));
}

__device__ __forceinline__ unsigned pack_bf(float e0, float e1) {
    unsigned r;
    asm("cvt.rn.bf16x2.f32 %0, %1, %2;" : "=r"(r) : "f"(e1), "f"(e0));
    return r;
}

__device__ __forceinline__ float bf_hi(float x) {
    return __bfloat162float(__float2bfloat16(x));
}

__device__ __forceinline__ void cp16(void* sptr, const void* gptr) {
    unsigned sa = (unsigned)__cvta_generic_to_shared(sptr);
    asm volatile("cp.async.cg.shared.global [%0], [%1], 16;" :: "r"(sa), "l"(gptr)
                 : "memory");
}
__device__ __forceinline__ void cp_commit() {
    asm volatile("cp.async.commit_group;" ::: "memory");
}
template <int N>
__device__ __forceinline__ void cp_wait() {
    asm volatile("cp.async.wait_group %0;" :: "n"(N) : "memory");
}

// FMA-pipe exp2 (no MUFU)
__device__ __forceinline__ float exp2p(float y) {
    y = fmaxf(y, -126.0f);
    float z = y + 12582912.0f;
    int i = __float_as_int(z) - 0x4B400000;
    float f = y - (z - 12582912.0f);
    float p = 1.3534384e-3f;
    p = fmaf(p, f, 9.6181291e-3f);
    p = fmaf(p, f, 5.5504109e-2f);
    p = fmaf(p, f, 2.4022650e-1f);
    p = fmaf(p, f, 6.9314718e-1f);
    p = fmaf(p, f, 1.0f);
    return __int_as_float(__float_as_int(p) + (i << 23));
}

#define LOG2E 1.4426950408889634f

// ---------------------------------------------------------------------------
// RoPE cos/sin table
// ---------------------------------------------------------------------------
__global__ void rope_table_kernel() {
    int idx = blockIdx.x * blockDim.x + threadIdx.x;
    if (idx >= SEQ * 32) return;
    int l = idx >> 5;
    int j = idx & 31;
    float invf = powf(10000.0f, -(float)j * (1.0f / 32.0f));
    float fr = (float)l * invf;
    g_cos[idx] = cosf(fr);
    g_sin[idx] = sinf(fr);
}

// ---------------------------------------------------------------------------
// RNA-round the five GEMM input matrices to tf32 (blockIdx.y selects array)
// ---------------------------------------------------------------------------
__global__ void __launch_bounds__(256) round_tf32_kernel(
    const float* __restrict__ x,  const float* __restrict__ Wq,
    const float* __restrict__ Wk, const float* __restrict__ Wv,
    const float* __restrict__ Wo) {
    int idx = blockIdx.x * blockDim.x + threadIdx.x;   // float4 index, 1M per array
    if (idx >= (SEQ * DM) / 4) return;
    const float* src;
    float* dst;
    switch (blockIdx.y) {
        case 0:  src = x;  dst = g_xr;  break;
        case 1:  src = Wq; dst = g_Wqr; break;
        case 2:  src = Wk; dst = g_Wkr; break;
        case 3:  src = Wv; dst = g_Wvr; break;
        default: src = Wo; dst = g_Wor; break;
    }
    float4 v = ((const float4*)src)[idx];
    v.x = tf32r(v.x); v.y = tf32r(v.y); v.z = tf32r(v.z); v.w = tf32r(v.w);
    ((float4*)dst)[idx] = v;
}

// ---------------------------------------------------------------------------
// Preprocess v2 — fine-grained, one thread per float4.
// y=0/1: rope+split Q/K. thread=(h,l,j4): 1 coalesced float4 read, writes
// words j4 and 16+j4 of hi/lo arrays (consecutive across adjacent threads).
// y=2: V pair-pack. thread=(h,kp,d4): 2 float4 reads, 2 uint4 writes.
// ---------------------------------------------------------------------------
__global__ void __launch_bounds__(256) preprocess_kernel() {
    int t = blockIdx.x * blockDim.x + threadIdx.x;
    int which = blockIdx.y;
    if (which < 2) {
        if (t >= NH * SEQ * 16) return;
        int j4 = t & 15;
        int l = (t >> 4) & (SEQ - 1);
        int h = t >> 15;
        const float* src = (which == 0 ? g_Q : g_K) + (size_t)l * DM + h * HD + 4 * j4;
        float4 q4 = *(const float4*)src;
        float2 cs = *(const float2*)&g_cos[l * 32 + 2 * j4];
        float2 sn = *(const float2*)&g_sin[l * 32 + 2 * j4];
        float oa0 = q4.x * cs.x - q4.y * sn.x;   // out dim 2*j4
        float oa1 = q4.z * cs.y - q4.w * sn.y;   // out dim 2*j4+1
        float ob0 = q4.x * sn.x + q4.y * cs.x;   // out dim 32+2*j4
        float ob1 = q4.z * sn.y + q4.w * cs.y;   // out dim 32+2*j4+1
        float ha0 = bf_hi(oa0), ha1 = bf_hi(oa1);
        float hb0 = bf_hi(ob0), hb1 = bf_hi(ob1);
        unsigned* dh = (which == 0 ? g_QHp : g_KHp) + ((size_t)h * SEQ + l) * 32;
        unsigned* dl = (which == 0 ? g_QLp : g_KLp) + ((size_t)h * SEQ + l) * 32;
        dh[j4]      = pack_bf(ha0, ha1);
        dl[j4]      = pack_bf(oa0 - ha0, oa1 - ha1);
        dh[16 + j4] = pack_bf(hb0, hb1);
        dl[16 + j4] = pack_bf(ob0 - hb0, ob1 - hb1);
    } else {
        if (t >= NH * (SEQ / 2) * 16) return;
        int d4 = t & 15;
        int kp = (t >> 4) & (SEQ / 2 - 1);
        int h = t >> 14;
        const float* a = g_V + (size_t)(2 * kp) * DM + h * HD + 4 * d4;
        const float* b = a + DM;
        float4 va = *(const float4*)a;
        float4 vb = *(const float4*)b;
        float af[4] = {va.x, va.y, va.z, va.w};
        float bf[4] = {vb.x, vb.y, vb.z, vb.w};
        unsigned wh[4], wl[4];
#pragma unroll
        for (int jj = 0; jj < 4; jj++) {
            float hA = bf_hi(af[jj]), hB = bf_hi(bf[jj]);
            wh[jj] = pack_bf(hA, hB);
            wl[jj] = pack_bf(af[jj] - hA, bf[jj] - hB);
        }
        size_t base = ((size_t)h * (SEQ / 2) + kp) * 64 + 4 * d4;
        *(uint4*)(g_VHp + base) = make_uint4(wh[0], wh[1], wh[2], wh[3]);
        *(uint4*)(g_VLp + base) = make_uint4(wl[0], wl[1], wl[2], wl[3]);
    }
}

// ---------------------------------------------------------------------------
// TF32 GEMM, 3-stage cp.async pipeline, ONE sync per k-tile, operands
// pre-rounded to tf32. C[M,N] = A[M,K] * B[N,K]^T. 128x128x32 tile,
// 8 warps 4x2, 2 CTAs/SM (3 x 36 KB smem = 108 KB).
// ---------------------------------------------------------------------------
#define SST 36
#define GTW (128 * SST)        // words per matrix tile: 4608
#define GBUFW (2 * GTW)        // A+B per buffer: 9216
#define GSTAGES 3
#define GSMEM_BYTES (GSTAGES * GBUFW * 4)   // 110592

__device__ __forceinline__ void g_issue(unsigned* buf, const float* A, const float* B,
                                        int bm, int bn, int k0) {
    int t = threadIdx.x;
#pragma unroll
    for (int i = 0; i < 4; i++) {
        int s = t + i * 256;            // 0..1023
        int row = s >> 3, c4 = (s & 7) * 4;
        cp16(&buf[row * SST + c4], A + (size_t)(bm + row) * DM + k0 + c4);
        cp16(&buf[GTW + row * SST + c4], B + (size_t)(bn + row) * DM + k0 + c4);
    }
    cp_commit();
}

__device__ __forceinline__ void gemm_compute_k8(const unsigned* As, const unsigned* Bs,
                                                float acc[2][8][4], int k8,
                                                int wm, int wn, int g, int tg) {
    int c = k8 * 8 + tg;
    unsigned afr[2][4], bfr[8][2];
#pragma unroll
    for (int mi = 0; mi < 2; mi++) {
        int r = wm * 32 + mi * 16 + g;
        afr[mi][0] = As[r * SST + c];
        afr[mi][1] = As[(r + 8) * SST + c];
        afr[mi][2] = As[r * SST + c + 4];
        afr[mi][3] = As[(r + 8) * SST + c + 4];
    }
#pragma unroll
    for (int ni = 0; ni < 8; ni++) {
        int n = wn * 64 + ni * 8 + g;
        bfr[ni][0] = Bs[n * SST + c];
        bfr[ni][1] = Bs[n * SST + c + 4];
    }
#pragma unroll
    for (int mi = 0; mi < 2; mi++)
#pragma unroll
        for (int ni = 0; ni < 8; ni++)
            mma_tf32(acc[mi][ni], afr[mi], bfr[ni]);
}

__device__ __forceinline__ void gemm_body(float* __restrict__ C,
                                          const float* __restrict__ A,
                                          const float* __restrict__ B) {
    extern __shared__ unsigned gsm[];

    int tid = threadIdx.x;
    int lane = tid & 31, warp = tid >> 5;
    int wm = warp >> 1, wn = warp & 1;
    int g = lane >> 2, tg = lane & 3;
    int bm = blockIdx.y * 128, bn = blockIdx.x * 128;

    float acc[2][8][4];
#pragma unroll
    for (int mi = 0; mi < 2; mi++)
#pragma unroll
        for (int ni = 0; ni < 8; ni++)
#pragma unroll
            for (int j = 0; j < 4; j++) acc[mi][ni][j] = 0.0f;

    const int NKT = DM / 32;   // 64
    g_issue(gsm, A, B, bm, bn, 0);
    g_issue(gsm + GBUFW, A, B, bm, bn, 32);

    for (int kt = 0; kt < NKT; kt++) {
        // in-flight before wait: {kt, kt+1} -> wait<1> completes kt
        if (kt + 1 < NKT) cp_wait<1>(); else cp_wait<0>();
        __syncthreads();   // tile kt visible to all; reads of tile kt-1 done
        if (kt + 2 < NKT)
            g_issue(gsm + ((kt + 2) % GSTAGES) * GBUFW, A, B, bm, bn, (kt + 2) * 32);
        const unsigned* As = gsm + (kt % GSTAGES) * GBUFW;
        const unsigned* Bs = As + GTW;
        gemm_compute_k8(As, Bs, acc, 0, wm, wn, g, tg);
        gemm_compute_k8(As, Bs, acc, 1, wm, wn, g, tg);
        gemm_compute_k8(As, Bs, acc, 2, wm, wn, g, tg);
        gemm_compute_k8(As, Bs, acc, 3, wm, wn, g, tg);
    }

#pragma unroll
    for (int mi = 0; mi < 2; mi++)
#pragma unroll
        for (int ni = 0; ni < 8; ni++) {
            int r0 = bm + wm * 32 + mi * 16 + g;
            int cc = bn + wn * 64 + ni * 8 + 2 * tg;
            *(float2*)&C[(size_t)r0 * DM + cc] =
                make_float2(acc[mi][ni][0], acc[mi][ni][1]);
            *(float2*)&C[(size_t)(r0 + 8) * DM + cc] =
                make_float2(acc[mi][ni][2], acc[mi][ni][3]);
        }
}

__global__ void __launch_bounds__(256, 2) gemm_qkv_kernel() {
    const float* B;
    float* C;
    if (blockIdx.z == 0)      { B = g_Wqr; C = g_Q; }
    else if (blockIdx.z == 1) { B = g_Wkr; C = g_K; }
    else                      { B = g_Wvr; C = g_V; }
    gemm_body(C, g_xr, B);
}

__global__ void __launch_bounds__(256, 2) gemm_out_kernel(float* __restrict__ C) {
    gemm_body(C, g_att, g_Wor);
}

// ---------------------------------------------------------------------------
// Split-BF16 flash attention, cp.async double-buffered (round-9 version).
// Epilogue writes g_att pre-rounded to tf32 for the out-GEMM.
// ---------------------------------------------------------------------------
#define BQ 128
#define BK 64
#define KWST 36
#define VWST 72
#define ABUF 9216
#define AOFF_KH 0
#define AOFF_KL 2304
#define AOFF_VH 4608
#define AOFF_VL 6912
#define AOFF_MS 18432
#define ASMEM_BYTES ((AOFF_MS + SEQ) * 4)   // 81920

__device__ __forceinline__ void attn_issue_tile(unsigned* buf, int h, int k0) {
    int t = threadIdx.x;
    const unsigned* KHs = g_KHp + ((size_t)h * SEQ + k0) * 32;
    const unsigned* KLs = g_KLp + ((size_t)h * SEQ + k0) * 32;
    const unsigned* VHs = g_VHp + ((size_t)h * (SEQ / 2) + (k0 >> 1)) * 64;
    const unsigned* VLs = g_VLp + ((size_t)h * (SEQ / 2) + (k0 >> 1)) * 64;
#pragma unroll
    for (int i = 0; i < 2; i++) {
        int s = t + i * 256;
        int row = s >> 3, c = (s & 7) * 4;
        cp16(&buf[AOFF_KH + row * KWST + c], KHs + row * 32 + c);
        cp16(&buf[AOFF_KL + row * KWST + c], KLs + row * 32 + c);
    }
#pragma unroll
    for (int i = 0; i < 2; i++) {
        int s = t + i * 256;
        int kp = s >> 4, c = (s & 15) * 4;
        cp16(&buf[AOFF_VH + kp * VWST + c], VHs + kp * 64 + c);
        cp16(&buf[AOFF_VL + kp * VWST + c], VLs + kp * 64 + c);
    }
    cp_commit();
}

__global__ void __launch_bounds__(256, 2) attn_bf16_kernel(const int* __restrict__ mask) {
    extern __shared__ unsigned smu[];
    int* MS = (int*)(smu + AOFF_MS);

    int tid = threadIdx.x;
    int lane = tid & 31, w = tid >> 5;
    int g = lane >> 2, tg = lane & 3;
    int h = blockIdx.y;
    int q0 = blockIdx.x * BQ;

    for (int i = tid; i < SEQ; i += 256) MS[i] = mask[i];

    attn_issue_tile(smu, h, 0);

    unsigned qh[4][4], ql[4][4];
    {
        int rA = q0 + w * 16 + g, rB = rA + 8;
        const unsigned* QH = g_QHp + (size_t)h * SEQ * 32;
        const unsigned* QL = g_QLp + (size_t)h * SEQ * 32;
#pragma unroll
        for (int ks = 0; ks < 4; ks++) {
            int c = ks * 8 + tg;
            qh[ks][0] = QH[rA * 32 + c];
            qh[ks][1] = QH[rB * 32 + c];
            qh[ks][2] = QH[rA * 32 + c + 4];
            qh[ks][3] = QH[rB * 32 + c + 4];
            ql[ks][0] = QL[rA * 32 + c];
            ql[ks][1] = QL[rB * 32 + c];
            ql[ks][2] = QL[rA * 32 + c + 4];
            ql[ks][3] = QL[rB * 32 + c + 4];
        }
    }

    float o[8][4];
#pragma unroll
    for (int ni = 0; ni < 8; ni++)
#pragma unroll
        for (int j = 0; j < 4; j++) o[ni][j] = 0.0f;
    float mA = -3.0e38f, mB = -3.0e38f, lA = 0.0f, lB = 0.0f;

    for (int kt = 0; kt < SEQ / BK; kt++) {
        int k0 = kt * BK;
        if (kt + 1 < SEQ / BK) {
            attn_issue_tile(smu + ((kt + 1) & 1) * ABUF, h, k0 + BK);
            cp_wait<1>();
        } else {
            cp_wait<0>();
        }
        __syncthreads();

        const unsigned* KH = smu + (kt & 1) * ABUF + AOFF_KH;
        const unsigned* KL = smu + (kt & 1) * ABUF + AOFF_KL;
        const unsigned* VH = smu + (kt & 1) * ABUF + AOFF_VH;
        const unsigned* VL = smu + (kt & 1) * ABUF + AOFF_VL;

        float sacc[8][4];
#pragma unroll
        for (int ni = 0; ni < 8; ni++)
#pragma unroll
            for (int j = 0; j < 4; j++) sacc[ni][j] = 0.0f;

#pragma unroll
        for (int ks = 0; ks < 4; ks++) {
#pragma unroll
            for (int ni = 0; ni < 8; ni++) {
                int kr = ni * 8 + g;
                unsigned bh[2], bl[2];
                bh[0] = KH[kr * KWST + ks * 8 + tg];
                bh[1] = KH[kr * KWST + ks * 8 + tg + 4];
                bl[0] = KL[kr * KWST + ks * 8 + tg];
                bl[1] = KL[kr * KWST + ks * 8 + tg + 4];
                mma_bf16(sacc[ni], qh[ks], bh);
                mma_bf16(sacc[ni], ql[ks], bh);
                mma_bf16(sacc[ni], qh[ks], bl);
            }
        }

#pragma unroll
        for (int ni = 0; ni < 8; ni++) {
            int m0 = MS[k0 + ni * 8 + 2 * tg];
            int m1 = MS[k0 + ni * 8 + 2 * tg + 1];
            sacc[ni][0] = m0 ? sacc[ni][0] * 0.125f : -1.0e9f;
            sacc[ni][1] = m1 ? sacc[ni][1] * 0.125f : -1.0e9f;
            sacc[ni][2] = m0 ? sacc[ni][2] * 0.125f : -1.0e9f;
            sacc[ni][3] = m1 ? sacc[ni][3] * 0.125f : -1.0e9f;
        }

        float mxA = -3.0e38f, mxB = -3.0e38f;
#pragma unroll
        for (int ni = 0; ni < 8; ni++) {
            mxA = fmaxf(mxA, fmaxf(sacc[ni][0], sacc[ni][1]));
            mxB = fmaxf(mxB, fmaxf(sacc[ni][2], sacc[ni][3]));
        }
        mxA = fmaxf(mxA, __shfl_xor_sync(0xffffffffu, mxA, 1));
        mxA = fmaxf(mxA, __shfl_xor_sync(0xffffffffu, mxA, 2));
        mxB = fmaxf(mxB, __shfl_xor_sync(0xffffffffu, mxB, 1));
        mxB = fmaxf(mxB, __shfl_xor_sync(0xffffffffu, mxB, 2));

        float mnA = fmaxf(mA, mxA), mnB = fmaxf(mB, mxB);
        float corrA = exp2p((mA - mnA) * LOG2E);
        float corrB = exp2p((mB - mnB) * LOG2E);

        float sumA = 0.0f, sumB = 0.0f;
#pragma unroll
        for (int ni = 0; ni < 8; ni++) {
            sacc[ni][0] = exp2p((sacc[ni][0] - mnA) * LOG2E);
            sacc[ni][1] = exp2p((sacc[ni][1] - mnA) * LOG2E);
            sacc[ni][2] = exp2p((sacc[ni][2] - mnB) * LOG2E);
            sacc[ni][3] = exp2p((sacc[ni][3] - mnB) * LOG2E);
            sumA += sacc[ni][0] + sacc[ni][1];
            sumB += sacc[ni][2] + sacc[ni][3];
        }
        sumA += __shfl_xor_sync(0xffffffffu, sumA, 1);
        sumA += __shfl_xor_sync(0xffffffffu, sumA, 2);
        sumB += __shfl_xor_sync(0xffffffffu, sumB, 1);
        sumB += __shfl_xor_sync(0xffffffffu, sumB, 2);

        lA = lA * corrA + sumA;
        lB = lB * corrB + sumB;
        mA = mnA;
        mB = mnB;
#pragma unroll
        for (int ni = 0; ni < 8; ni++) {
            o[ni][0] *= corrA; o[ni][1] *= corrA;
            o[ni][2] *= corrB; o[ni][3] *= corrB;
        }

#pragma unroll
        for (int ks = 0; ks < 4; ks++) {
            unsigned ah[4], al[4];
#pragma unroll
            for (int half = 0; half < 2; half++) {
                const float* s2 = sacc[2 * ks + half];
                float h0 = bf_hi(s2[0]), h1 = bf_hi(s2[1]);
                float h2 = bf_hi(s2[2]), h3 = bf_hi(s2[3]);
                ah[2 * half]     = pack_bf(h0, h1);
                ah[2 * half + 1] = pack_bf(h2, h3);
                al[2 * half]     = pack_bf(s2[0] - h0, s2[1] - h1);
                al[2 * half + 1] = pack_bf(s2[2] - h2, s2[3] - h3);
            }
#pragma unroll
            for (int ni = 0; ni < 8; ni++) {
                int vr = ks * 8 + tg;
                unsigned bh[2], bl[2];
                bh[0] = VH[vr * VWST + ni * 8 + g];
                bh[1] = VH[(vr + 4) * VWST + ni * 8 + g];
                bl[0] = VL[vr * VWST + ni * 8 + g];
                bl[1] = VL[(vr + 4) * VWST + ni * 8 + g];
                mma_bf16(o[ni], ah, bh);
                mma_bf16(o[ni], al, bh);
                mma_bf16(o[ni], ah, bl);
            }
        }
        __syncthreads();
    }

    // normalize + store, pre-rounded to tf32 for the out-GEMM
    float invA = 1.0f / lA, invB = 1.0f / lB;
    float* Og = g_att + (size_t)(q0 + w * 16) * DM + h * HD;
#pragma unroll
    for (int ni = 0; ni < 8; ni++) {
        *(float2*)&Og[(size_t)g * DM + ni * 8 + 2 * tg] =
            make_float2(tf32r(o[ni][0] * invA), tf32r(o[ni][1] * invA));
        *(float2*)&Og[(size_t)(g + 8) * DM + ni * 8 + 2 * tg] =
            make_float2(tf32r(o[ni][2] * invB), tf32r(o[ni][3] * invB));
    }
}

// ---------------------------------------------------------------------------
// launch
// ---------------------------------------------------------------------------
extern "C" void kernel_launch(void* const* d_in, const int* in_sizes, int n_in,
                              void* d_out, int out_size) {
    const float* x    = (const float*)d_in[0];
    const int*   mask = (const int*)d_in[1];
    const float* Wq   = (const float*)d_in[2];
    const float* Wk   = (const float*)d_in[3];
    const float* Wv   = (const float*)d_in[4];
    const float* Wo   = (const float*)d_in[5];
    float* out = (float*)d_out;

    cudaFuncSetAttribute(gemm_qkv_kernel, cudaFuncAttributeMaxDynamicSharedMemorySize,
                         GSMEM_BYTES);
    cudaFuncSetAttribute(gemm_out_kernel, cudaFuncAttributeMaxDynamicSharedMemorySize,
                         GSMEM_BYTES);
    cudaFuncSetAttribute(attn_bf16_kernel, cudaFuncAttributeMaxDynamicSharedMemorySize,
                         ASMEM_BYTES);

    rope_table_kernel<<<(SEQ * 32 + 255) / 256, 256>>>();
    round_tf32_kernel<<<dim3((SEQ * DM / 4 + 255) / 256, 5), 256>>>(x, Wq, Wk, Wv, Wo);
    gemm_qkv_kernel<<<dim3(16, 16, 3), 256, GSMEM_BYTES>>>();
    preprocess_kernel<<<dim3((NH * SEQ * 16 + 255) / 256, 3), 256>>>();
    attn_bf16_kernel<<<dim3(SEQ / BQ, NH), 256, ASMEM_BYTES>>>(mask);
    gemm_out_kernel<<<dim3(16, 16), 256, GSMEM_BYTES>>>(out);
}

// round 11
// speedup vs baseline: 1.1416x; 1.0019x over previous
#include <cuda_runtime.h>
#include <cuda_bf16.h>

#define SEQ 2048
#define DM 2048
#define NH 32
#define HD 64

// Scratch (static device allocations are allowed; cudaMalloc is not)
__device__ float g_Q[SEQ * DM];
__device__ float g_K[SEQ * DM];
__device__ float g_V[SEQ * DM];
__device__ float g_att[SEQ * DM];
__device__ float g_cos[SEQ * 32];
__device__ float g_sin[SEQ * 32];

// tf32-rounded copies of the GEMM inputs (so mma's internal truncation is a
// no-op and cp.async can feed smem directly -> numerics identical to cvt.rna).
__device__ float g_xr[SEQ * DM];
__device__ float g_Wqr[DM * DM];
__device__ float g_Wkr[DM * DM];
__device__ float g_Wvr[DM * DM];
__device__ float g_Wor[DM * DM];

// Preprocessed (roped, hi/lo-split, bf16x2-packed) operands for attention.
__device__ unsigned g_QHp[NH * SEQ * 32];
__device__ unsigned g_QLp[NH * SEQ * 32];
__device__ unsigned g_KHp[NH * SEQ * 32];
__device__ unsigned g_KLp[NH * SEQ * 32];
__device__ unsigned g_VHp[NH * (SEQ / 2) * 64];
__device__ unsigned g_VLp[NH * (SEQ / 2) * 64];

// ---------------------------------------------------------------------------
// helpers
// ---------------------------------------------------------------------------
__device__ __forceinline__ unsigned f2tf32(float f) {
    unsigned r;
    asm("cvt.rna.tf32.f32 %0, %1;" : "=r"(r) : "f"(f));
    return r;
}

__device__ __forceinline__ float tf32r(float f) {
    return __uint_as_float(f2tf32(f));
}

// operands are fp32 bit patterns already rounded to tf32
__device__ __forceinline__ void mma_tf32(float* c, const unsigned* a, const unsigned* b) {
    asm volatile(
        "mma.sync.aligned.m16n8k8.row.col.f32.tf32.tf32.f32 "
        "{%0,%1,%2,%3}, {%4,%5,%6,%7}, {%8,%9}, {%0,%1,%2,%3};"
        : "+f"(c[0]), "+f"(c[1]), "+f"(c[2]), "+f"(c[3])
        : "r"(a[0]), "r"(a[1]), "r"(a[2]), "r"(a[3]), "r"(b[0]), "r"(b[1]));
}

__device__ __forceinline__ void mma_bf16(float* c, const unsigned* a, const unsigned* b) {
    asm volatile(
        "mma.sync.aligned.m16n8k16.row.col.f32.bf16.bf16.f32 "
        "{%0,%1,%2,%3}, {%4,%5,%6,%7}, {%8,%9}, {%0,%1,%2,%3};"
        : "+f"(c[0]), "+f"(c[1]), "+f"(c[2]), "+f"(c[3])
        : "r"(a[0]), "r"(a[1]), "r"(a[2]), "r"(a[3]), "r"(b[0]), "r"(b[1]));
}

__device__ __forceinline__ unsigned pack_bf(float e0, float e1) {
    unsigned r;
    asm("cvt.rn.bf16x2.f32 %0, %1, %2;" : "=r"(r) : "f"(e1), "f"(e0));
    return r;
}

__device__ __forceinline__ float bf_hi(float x) {
    return __bfloat162float(__float2bfloat16(x));
}

__device__ __forceinline__ void cp16(void* sptr, const void* gptr) {
    unsigned sa = (unsigned)__cvta_generic_to_shared(sptr);
    asm volatile("cp.async.cg.shared.global [%0], [%1], 16;" :: "r"(sa), "l"(gptr)
                 : "memory");
}
__device__ __forceinline__ void cp_commit() {
    asm volatile("cp.async.commit_group;" ::: "memory");
}
template <int N>
__device__ __forceinline__ void cp_wait() {
    asm volatile("cp.async.wait_group %0;" :: "n"(N) : "memory");
}

// FMA-pipe exp2 (no MUFU)
__device__ __forceinline__ float exp2p(float y) {
    y = fmaxf(y, -126.0f);
    float z = y + 12582912.0f;
    int i = __float_as_int(z) - 0x4B400000;
    float f = y - (z - 12582912.0f);
    float p = 1.3534384e-3f;
    p = fmaf(p, f, 9.6181291e-3f);
    p = fmaf(p, f, 5.5504109e-2f);
    p = fmaf(p, f, 2.4022650e-1f);
    p = fmaf(p, f, 6.9314718e-1f);
    p = fmaf(p, f, 1.0f);
    return __int_as_float(__float_as_int(p) + (i << 23));
}

#define LOG2E 1.4426950408889634f

// ---------------------------------------------------------------------------
// RoPE cos/sin table
// ---------------------------------------------------------------------------
__global__ void rope_table_kernel() {
    int idx = blockIdx.x * blockDim.x + threadIdx.x;
    if (idx >= SEQ * 32) return;
    int l = idx >> 5;
    int j = idx & 31;
    float invf = powf(10000.0f, -(float)j * (1.0f / 32.0f));
    float fr = (float)l * invf;
    g_cos[idx] = cosf(fr);
    g_sin[idx] = sinf(fr);
}

// ---------------------------------------------------------------------------
// RNA-round the five GEMM input matrices to tf32 (blockIdx.y selects array)
// ---------------------------------------------------------------------------
__global__ void __launch_bounds__(256) round_tf32_kernel(
    const float* __restrict__ x,  const float* __restrict__ Wq,
    const float* __restrict__ Wk, const float* __restrict__ Wv,
    const float* __restrict__ Wo) {
    int idx = blockIdx.x * blockDim.x + threadIdx.x;   // float4 index, 1M per array
    if (idx >= (SEQ * DM) / 4) return;
    const float* src;
    float* dst;
    switch (blockIdx.y) {
        case 0:  src = x;  dst = g_xr;  break;
        case 1:  src = Wq; dst = g_Wqr; break;
        case 2:  src = Wk; dst = g_Wkr; break;
        case 3:  src = Wv; dst = g_Wvr; break;
        default: src = Wo; dst = g_Wor; break;
    }
    float4 v = ((const float4*)src)[idx];
    v.x = tf32r(v.x); v.y = tf32r(v.y); v.z = tf32r(v.z); v.w = tf32r(v.w);
    ((float4*)dst)[idx] = v;
}

// ---------------------------------------------------------------------------
// Preprocess — one thread per float4 (round-10 version).
// ---------------------------------------------------------------------------
__global__ void __launch_bounds__(256) preprocess_kernel() {
    int t = blockIdx.x * blockDim.x + threadIdx.x;
    int which = blockIdx.y;
    if (which < 2) {
        if (t >= NH * SEQ * 16) return;
        int j4 = t & 15;
        int l = (t >> 4) & (SEQ - 1);
        int h = t >> 15;
        const float* src = (which == 0 ? g_Q : g_K) + (size_t)l * DM + h * HD + 4 * j4;
        float4 q4 = *(const float4*)src;
        float2 cs = *(const float2*)&g_cos[l * 32 + 2 * j4];
        float2 sn = *(const float2*)&g_sin[l * 32 + 2 * j4];
        float oa0 = q4.x * cs.x - q4.y * sn.x;
        float oa1 = q4.z * cs.y - q4.w * sn.y;
        float ob0 = q4.x * sn.x + q4.y * cs.x;
        float ob1 = q4.z * sn.y + q4.w * cs.y;
        float ha0 = bf_hi(oa0), ha1 = bf_hi(oa1);
        float hb0 = bf_hi(ob0), hb1 = bf_hi(ob1);
        unsigned* dh = (which == 0 ? g_QHp : g_KHp) + ((size_t)h * SEQ + l) * 32;
        unsigned* dl = (which == 0 ? g_QLp : g_KLp) + ((size_t)h * SEQ + l) * 32;
        dh[j4]      = pack_bf(ha0, ha1);
        dl[j4]      = pack_bf(oa0 - ha0, oa1 - ha1);
        dh[16 + j4] = pack_bf(hb0, hb1);
        dl[16 + j4] = pack_bf(ob0 - hb0, ob1 - hb1);
    } else {
        if (t >= NH * (SEQ / 2) * 16) return;
        int d4 = t & 15;
        int kp = (t >> 4) & (SEQ / 2 - 1);
        int h = t >> 14;
        const float* a = g_V + (size_t)(2 * kp) * DM + h * HD + 4 * d4;
        const float* b = a + DM;
        float4 va = *(const float4*)a;
        float4 vb = *(const float4*)b;
        float af[4] = {va.x, va.y, va.z, va.w};
        float bf[4] = {vb.x, vb.y, vb.z, vb.w};
        unsigned wh[4], wl[4];
#pragma unroll
        for (int jj = 0; jj < 4; jj++) {
            float hA = bf_hi(af[jj]), hB = bf_hi(bf[jj]);
            wh[jj] = pack_bf(hA, hB);
            wl[jj] = pack_bf(af[jj] - hA, bf[jj] - hB);
        }
        size_t base = ((size_t)h * (SEQ / 2) + kp) * 64 + 4 * d4;
        *(uint4*)(g_VHp + base) = make_uint4(wh[0], wh[1], wh[2], wh[3]);
        *(uint4*)(g_VLp + base) = make_uint4(wl[0], wl[1], wl[2], wl[3]);
    }
}

// ---------------------------------------------------------------------------
// TF32 GEMM, 3-stage cp.async pipeline, operands pre-rounded to tf32.
// C[M,N] = A[M,K] * B[N,K]^T. 128x128x32 CTA tile, 4 warps (128 threads)
// as 2x2, each warp owns a 64x64 tile (4 mi x 8 ni fragments): per k8 step
// 16 A-LDS + 16 B-LDS feed 32 MMAs (1.0 LDS/MMA vs 1.5 before).
// 2 CTAs/SM (3 x 36 KB smem, <=256 regs).
// ---------------------------------------------------------------------------
#define SST 36
#define GTW (128 * SST)        // words per matrix tile: 4608
#define GBUFW (2 * GTW)        // A+B per buffer: 9216
#define GSTAGES 3
#define GSMEM_BYTES (GSTAGES * GBUFW * 4)   // 110592

__device__ __forceinline__ void g_issue(unsigned* buf, const float* A, const float* B,
                                        int bm, int bn, int k0) {
    int t = threadIdx.x;   // 0..127
#pragma unroll
    for (int i = 0; i < 8; i++) {
        int s = t + i * 128;            // 0..1023
        int row = s >> 3, c4 = (s & 7) * 4;
        cp16(&buf[row * SST + c4], A + (size_t)(bm + row) * DM + k0 + c4);
        cp16(&buf[GTW + row * SST + c4], B + (size_t)(bn + row) * DM + k0 + c4);
    }
    cp_commit();
}

__device__ __forceinline__ void gemm_compute_k8(const unsigned* As, const unsigned* Bs,
                                                float acc[4][8][4], int k8,
                                                int wm, int wn, int g, int tg) {
    int c = k8 * 8 + tg;
    unsigned afr[4][4], bfr[8][2];
#pragma unroll
    for (int mi = 0; mi < 4; mi++) {
        int r = wm * 64 + mi * 16 + g;
        afr[mi][0] = As[r * SST + c];
        afr[mi][1] = As[(r + 8) * SST + c];
        afr[mi][2] = As[r * SST + c + 4];
        afr[mi][3] = As[(r + 8) * SST + c + 4];
    }
#pragma unroll
    for (int ni = 0; ni < 8; ni++) {
        int n = wn * 64 + ni * 8 + g;
        bfr[ni][0] = Bs[n * SST + c];
        bfr[ni][1] = Bs[n * SST + c + 4];
    }
#pragma unroll
    for (int mi = 0; mi < 4; mi++)
#pragma unroll
        for (int ni = 0; ni < 8; ni++)
            mma_tf32(acc[mi][ni], afr[mi], bfr[ni]);
}

__device__ __forceinline__ void gemm_body(float* __restrict__ C,
                                          const float* __restrict__ A,
                                          const float* __restrict__ B) {
    extern __shared__ unsigned gsm[];

    int tid = threadIdx.x;
    int lane = tid & 31, warp = tid >> 5;   // 4 warps
    int wm = warp >> 1, wn = warp & 1;      // 2 x 2
    int g = lane >> 2, tg = lane & 3;
    int bm = blockIdx.y * 128, bn = blockIdx.x * 128;

    float acc[4][8][4];
#pragma unroll
    for (int mi = 0; mi < 4; mi++)
#pragma unroll
        for (int ni = 0; ni < 8; ni++)
#pragma unroll
            for (int j = 0; j < 4; j++) acc[mi][ni][j] = 0.0f;

    const int NKT = DM / 32;   // 64
    g_issue(gsm, A, B, bm, bn, 0);
    g_issue(gsm + GBUFW, A, B, bm, bn, 32);

    for (int kt = 0; kt < NKT; kt++) {
        // in-flight before wait: {kt, kt+1} -> wait<1> completes kt
        if (kt + 1 < NKT) cp_wait<1>(); else cp_wait<0>();
        __syncthreads();   // tile kt visible; reads of tile kt-1 done
        if (kt + 2 < NKT)
            g_issue(gsm + ((kt + 2) % GSTAGES) * GBUFW, A, B, bm, bn, (kt + 2) * 32);
        const unsigned* As = gsm + (kt % GSTAGES) * GBUFW;
        const unsigned* Bs = As + GTW;
        gemm_compute_k8(As, Bs, acc, 0, wm, wn, g, tg);
        gemm_compute_k8(As, Bs, acc, 1, wm, wn, g, tg);
        gemm_compute_k8(As, Bs, acc, 2, wm, wn, g, tg);
        gemm_compute_k8(As, Bs, acc, 3, wm, wn, g, tg);
    }

#pragma unroll
    for (int mi = 0; mi < 4; mi++)
#pragma unroll
        for (int ni = 0; ni < 8; ni++) {
            int r0 = bm + wm * 64 + mi * 16 + g;
            int cc = bn + wn * 64 + ni * 8 + 2 * tg;
            *(float2*)&C[(size_t)r0 * DM + cc] =
                make_float2(acc[mi][ni][0], acc[mi][ni][1]);
            *(float2*)&C[(size_t)(r0 + 8) * DM + cc] =
                make_float2(acc[mi][ni][2], acc[mi][ni][3]);
        }
}

__global__ void __launch_bounds__(128, 2) gemm_qkv_kernel() {
    const float* B;
    float* C;
    if (blockIdx.z == 0)      { B = g_Wqr; C = g_Q; }
    else if (blockIdx.z == 1) { B = g_Wkr; C = g_K; }
    else                      { B = g_Wvr; C = g_V; }
    gemm_body(C, g_xr, B);
}

__global__ void __launch_bounds__(128, 2) gemm_out_kernel(float* __restrict__ C) {
    gemm_body(C, g_att, g_Wor);
}

// ---------------------------------------------------------------------------
// Split-BF16 flash attention, cp.async double-buffered (round-10 version).
// Epilogue writes g_att pre-rounded to tf32 for the out-GEMM.
// ---------------------------------------------------------------------------
#define BQ 128
#define BK 64
#define KWST 36
#define VWST 72
#define ABUF 9216
#define AOFF_KH 0
#define AOFF_KL 2304
#define AOFF_VH 4608
#define AOFF_VL 6912
#define AOFF_MS 18432
#define ASMEM_BYTES ((AOFF_MS + SEQ) * 4)   // 81920

__device__ __forceinline__ void attn_issue_tile(unsigned* buf, int h, int k0) {
    int t = threadIdx.x;
    const unsigned* KHs = g_KHp + ((size_t)h * SEQ + k0) * 32;
    const unsigned* KLs = g_KLp + ((size_t)h * SEQ + k0) * 32;
    const unsigned* VHs = g_VHp + ((size_t)h * (SEQ / 2) + (k0 >> 1)) * 64;
    const unsigned* VLs = g_VLp + ((size_t)h * (SEQ / 2) + (k0 >> 1)) * 64;
#pragma unroll
    for (int i = 0; i < 2; i++) {
        int s = t + i * 256;
        int row = s >> 3, c = (s & 7) * 4;
        cp16(&buf[AOFF_KH + row * KWST + c], KHs + row * 32 + c);
        cp16(&buf[AOFF_KL + row * KWST + c], KLs + row * 32 + c);
    }
#pragma unroll
    for (int i = 0; i < 2; i++) {
        int s = t + i * 256;
        int kp = s >> 4, c = (s & 15) * 4;
        cp16(&buf[AOFF_VH + kp * VWST + c], VHs + kp * 64 + c);
        cp16(&buf[AOFF_VL + kp * VWST + c], VLs + kp * 64 + c);
    }
    cp_commit();
}

__global__ void __launch_bounds__(256, 2) attn_bf16_kernel(const int* __restrict__ mask) {
    extern __shared__ unsigned smu[];
    int* MS = (int*)(smu + AOFF_MS);

    int tid = threadIdx.x;
    int lane = tid & 31, w = tid >> 5;
    int g = lane >> 2, tg = lane & 3;
    int h = blockIdx.y;
    int q0 = blockIdx.x * BQ;

    for (int i = tid; i < SEQ; i += 256) MS[i] = mask[i];

    attn_issue_tile(smu, h, 0);

    unsigned qh[4][4], ql[4][4];
    {
        int rA = q0 + w * 16 + g, rB = rA + 8;
        const unsigned* QH = g_QHp + (size_t)h * SEQ * 32;
        const unsigned* QL = g_QLp + (size_t)h * SEQ * 32;
#pragma unroll
        for (int ks = 0; ks < 4; ks++) {
            int c = ks * 8 + tg;
            qh[ks][0] = QH[rA * 32 + c];
            qh[ks][1] = QH[rB * 32 + c];
            qh[ks][2] = QH[rA * 32 + c + 4];
            qh[ks][3] = QH[rB * 32 + c + 4];
            ql[ks][0] = QL[rA * 32 + c];
            ql[ks][1] = QL[rB * 32 + c];
            ql[ks][2] = QL[rA * 32 + c + 4];
            ql[ks][3] = QL[rB * 32 + c + 4];
        }
    }

    float o[8][4];
#pragma unroll
    for (int ni = 0; ni < 8; ni++)
#pragma unroll
        for (int j = 0; j < 4; j++) o[ni][j] = 0.0f;
    float mA = -3.0e38f, mB = -3.0e38f, lA = 0.0f, lB = 0.0f;

    for (int kt = 0; kt < SEQ / BK; kt++) {
        int k0 = kt * BK;
        if (kt + 1 < SEQ / BK) {
            attn_issue_tile(smu + ((kt + 1) & 1) * ABUF, h, k0 + BK);
            cp_wait<1>();
        } else {
            cp_wait<0>();
        }
        __syncthreads();

        const unsigned* KH = smu + (kt & 1) * ABUF + AOFF_KH;
        const unsigned* KL = smu + (kt & 1) * ABUF + AOFF_KL;
        const unsigned* VH = smu + (kt & 1) * ABUF + AOFF_VH;
        const unsigned* VL = smu + (kt & 1) * ABUF + AOFF_VL;

        float sacc[8][4];
#pragma unroll
        for (int ni = 0; ni < 8; ni++)
#pragma unroll
            for (int j = 0; j < 4; j++) sacc[ni][j] = 0.0f;

#pragma unroll
        for (int ks = 0; ks < 4; ks++) {
#pragma unroll
            for (int ni = 0; ni < 8; ni++) {
                int kr = ni * 8 + g;
                unsigned bh[2], bl[2];
                bh[0] = KH[kr * KWST + ks * 8 + tg];
                bh[1] = KH[kr * KWST + ks * 8 + tg + 4];
                bl[0] = KL[kr * KWST + ks * 8 + tg];
                bl[1] = KL[kr * KWST + ks * 8 + tg + 4];
                mma_bf16(sacc[ni], qh[ks], bh);
                mma_bf16(sacc[ni], ql[ks], bh);
                mma_bf16(sacc[ni], qh[ks], bl);
            }
        }

#pragma unroll
        for (int ni = 0; ni < 8; ni++) {
            int m0 = MS[k0 + ni * 8 + 2 * tg];
            int m1 = MS[k0 + ni * 8 + 2 * tg + 1];
            sacc[ni][0] = m0 ? sacc[ni][0] * 0.125f : -1.0e9f;
            sacc[ni][1] = m1 ? sacc[ni][1] * 0.125f : -1.0e9f;
            sacc[ni][2] = m0 ? sacc[ni][2] * 0.125f : -1.0e9f;
            sacc[ni][3] = m1 ? sacc[ni][3] * 0.125f : -1.0e9f;
        }

        float mxA = -3.0e38f, mxB = -3.0e38f;
#pragma unroll
        for (int ni = 0; ni < 8; ni++) {
            mxA = fmaxf(mxA, fmaxf(sacc[ni][0], sacc[ni][1]));
            mxB = fmaxf(mxB, fmaxf(sacc[ni][2], sacc[ni][3]));
        }
        mxA = fmaxf(mxA, __shfl_xor_sync(0xffffffffu, mxA, 1));
        mxA = fmaxf(mxA, __shfl_xor_sync(0xffffffffu, mxA, 2));
        mxB = fmaxf(mxB, __shfl_xor_sync(0xffffffffu, mxB, 1));
        mxB = fmaxf(mxB, __shfl_xor_sync(0xffffffffu, mxB, 2));

        float mnA = fmaxf(mA, mxA), mnB = fmaxf(mB, mxB);
        float corrA = exp2p((mA - mnA) * LOG2E);
        float corrB = exp2p((mB - mnB) * LOG2E);

        float sumA = 0.0f, sumB = 0.0f;
#pragma unroll
        for (int ni = 0; ni < 8; ni++) {
            sacc[ni][0] = exp2p((sacc[ni][0] - mnA) * LOG2E);
            sacc[ni][1] = exp2p((sacc[ni][1] - mnA) * LOG2E);
            sacc[ni][2] = exp2p((sacc[ni][2] - mnB) * LOG2E);
            sacc[ni][3] = exp2p((sacc[ni][3] - mnB) * LOG2E);
            sumA += sacc[ni][0] + sacc[ni][1];
            sumB += sacc[ni][2] + sacc[ni][3];
        }
        sumA += __shfl_xor_sync(0xffffffffu, sumA, 1);
        sumA += __shfl_xor_sync(0xffffffffu, sumA, 2);
        sumB += __shfl_xor_sync(0xffffffffu, sumB, 1);
        sumB += __shfl_xor_sync(0xffffffffu, sumB, 2);

        lA = lA * corrA + sumA;
        lB = lB * corrB + sumB;
        mA = mnA;
        mB = mnB;
#pragma unroll
        for (int ni = 0; ni < 8; ni++) {
            o[ni][0] *= corrA; o[ni][1] *= corrA;
            o[ni][2] *= corrB; o[ni][3] *= corrB;
        }

#pragma unroll
        for (int ks = 0; ks < 4; ks++) {
            unsigned ah[4], al[4];
#pragma unroll
            for (int half = 0; half < 2; half++) {
                const float* s2 = sacc[2 * ks + half];
                float h0 = bf_hi(s2[0]), h1 = bf_hi(s2[1]);
                float h2 = bf_hi(s2[2]), h3 = bf_hi(s2[3]);
                ah[2 * half]     = pack_bf(h0, h1);
                ah[2 * half + 1] = pack_bf(h2, h3);
                al[2 * half]     = pack_bf(s2[0] - h0, s2[1] - h1);
                al[2 * half + 1] = pack_bf(s2[2] - h2, s2[3] - h3);
            }
#pragma unroll
            for (int ni = 0; ni < 8; ni++) {
                int vr = ks * 8 + tg;
                unsigned bh[2], bl[2];
                bh[0] = VH[vr * VWST + ni * 8 + g];
                bh[1] = VH[(vr + 4) * VWST + ni * 8 + g];
                bl[0] = VL[vr * VWST + ni * 8 + g];
                bl[1] = VL[(vr + 4) * VWST + ni * 8 + g];
                mma_bf16(o[ni], ah, bh);
                mma_bf16(o[ni], al, bh);
                mma_bf16(o[ni], ah, bl);
            }
        }
        __syncthreads();
    }

    // normalize + store, pre-rounded to tf32 for the out-GEMM
    float invA = 1.0f / lA, invB = 1.0f / lB;
    float* Og = g_att + (size_t)(q0 + w * 16) * DM + h * HD;
#pragma unroll
    for (int ni = 0; ni < 8; ni++) {
        *(float2*)&Og[(size_t)g * DM + ni * 8 + 2 * tg] =
            make_float2(tf32r(o[ni][0] * invA), tf32r(o[ni][1] * invA));
        *(float2*)&Og[(size_t)(g + 8) * DM + ni * 8 + 2 * tg] =
            make_float2(tf32r(o[ni][2] * invB), tf32r(o[ni][3] * invB));
    }
}

// ---------------------------------------------------------------------------
// launch
// ---------------------------------------------------------------------------
extern "C" void kernel_launch(void* const* d_in, const int* in_sizes, int n_in,
                              void* d_out, int out_size) {
    const float* x    = (const float*)d_in[0];
    const int*   mask = (const int*)d_in[1];
    const float* Wq   = (const float*)d_in[2];
    const float* Wk   = (const float*)d_in[3];
    const float* Wv   = (const float*)d_in[4];
    const float* Wo   = (const float*)d_in[5];
    float* out = (float*)d_out;

    cudaFuncSetAttribute(gemm_qkv_kernel, cudaFuncAttributeMaxDynamicSharedMemorySize,
                         GSMEM_BYTES);
    cudaFuncSetAttribute(gemm_out_kernel, cudaFuncAttributeMaxDynamicSharedMemorySize,
                         GSMEM_BYTES);
    cudaFuncSetAttribute(attn_bf16_kernel, cudaFuncAttributeMaxDynamicSharedMemorySize,
                         ASMEM_BYTES);

    rope_table_kernel<<<(SEQ * 32 + 255) / 256, 256>>>();
    round_tf32_kernel<<<dim3((SEQ * DM / 4 + 255) / 256, 5), 256>>>(x, Wq, Wk, Wv, Wo);
    gemm_qkv_kernel<<<dim3(16, 16, 3), 128, GSMEM_BYTES>>>();
    preprocess_kernel<<<dim3((NH * SEQ * 16 + 255) / 256, 3), 256>>>();
    attn_bf16_kernel<<<dim3(SEQ / BQ, NH), 256, ASMEM_BYTES>>>(mask);
    gemm_out_kernel<<<dim3(16, 16), 128, GSMEM_BYTES>>>(out);
}

// round 12
// speedup vs baseline: 1.2043x; 1.0549x over previous
#include <cuda_runtime.h>
#include <cuda_bf16.h>

#define SEQ 2048
#define DM 2048
#define NH 32
#define HD 64

// Scratch (static device allocations are allowed; cudaMalloc is not)
__device__ float g_Q[SEQ * DM];
__device__ float g_K[SEQ * DM];
__device__ float g_V[SEQ * DM];
__device__ float g_att[SEQ * DM];
__device__ float g_cos[SEQ * 32];
__device__ float g_sin[SEQ * 32];

// tf32-rounded copies of the GEMM inputs (so mma's internal truncation is a
// no-op and cp.async can feed smem directly -> numerics identical to cvt.rna).
__device__ float g_xr[SEQ * DM];
__device__ float g_Wqr[DM * DM];
__device__ float g_Wkr[DM * DM];
__device__ float g_Wvr[DM * DM];
__device__ float g_Wor[DM * DM];

// Preprocessed (roped, hi/lo-split, bf16x2-packed) operands for attention.
__device__ unsigned g_QHp[NH * SEQ * 32];
__device__ unsigned g_QLp[NH * SEQ * 32];
__device__ unsigned g_KHp[NH * SEQ * 32];
__device__ unsigned g_KLp[NH * SEQ * 32];
__device__ unsigned g_VHp[NH * (SEQ / 2) * 64];
__device__ unsigned g_VLp[NH * (SEQ / 2) * 64];

// ---------------------------------------------------------------------------
// helpers
// ---------------------------------------------------------------------------
__device__ __forceinline__ unsigned f2tf32(float f) {
    unsigned r;
    asm("cvt.rna.tf32.f32 %0, %1;" : "=r"(r) : "f"(f));
    return r;
}

__device__ __forceinline__ float tf32r(float f) {
    return __uint_as_float(f2tf32(f));
}

// operands are fp32 bit patterns already rounded to tf32
__device__ __forceinline__ void mma_tf32(float* c, const unsigned* a, const unsigned* b) {
    asm volatile(
        "mma.sync.aligned.m16n8k8.row.col.f32.tf32.tf32.f32 "
        "{%0,%1,%2,%3}, {%4,%5,%6,%7}, {%8,%9}, {%0,%1,%2,%3};"
        : "+f"(c[0]), "+f"(c[1]), "+f"(c[2]), "+f"(c[3])
        : "r"(a[0]), "r"(a[1]), "r"(a[2]), "r"(a[3]), "r"(b[0]), "r"(b[1]));
}

__device__ __forceinline__ void mma_bf16(float* c, const unsigned* a, const unsigned* b) {
    asm volatile(
        "mma.sync.aligned.m16n8k16.row.col.f32.bf16.bf16.f32 "
        "{%0,%1,%2,%3}, {%4,%5,%6,%7}, {%8,%9}, {%0,%1,%2,%3};"
        : "+f"(c[0]), "+f"(c[1]), "+f"(c[2]), "+f"(c[3])
        : "r"(a[0]), "r"(a[1]), "r"(a[2]), "r"(a[3]), "r"(b[0]), "r"(b[1]));
}

// ldmatrix x4: one instruction loads 4 fragment words per lane (4 8x8 b16
// matrices). Pure data mover -> bit-identical to the scalar LDS path.
__device__ __forceinline__ void ldsm4(unsigned* r, unsigned saddr) {
    asm volatile(
        "ldmatrix.sync.aligned.m8n8.x4.shared.b16 {%0,%1,%2,%3}, [%4];"
        : "=r"(r[0]), "=r"(r[1]), "=r"(r[2]), "=r"(r[3]) : "r"(saddr));
}

__device__ __forceinline__ unsigned pack_bf(float e0, float e1) {
    unsigned r;
    asm("cvt.rn.bf16x2.f32 %0, %1, %2;" : "=r"(r) : "f"(e1), "f"(e0));
    return r;
}

__device__ __forceinline__ float bf_hi(float x) {
    return __bfloat162float(__float2bfloat16(x));
}

__device__ __forceinline__ void cp16(void* sptr, const void* gptr) {
    unsigned sa = (unsigned)__cvta_generic_to_shared(sptr);
    asm volatile("cp.async.cg.shared.global [%0], [%1], 16;" :: "r"(sa), "l"(gptr)
                 : "memory");
}
__device__ __forceinline__ void cp_commit() {
    asm volatile("cp.async.commit_group;" ::: "memory");
}
template <int N>
__device__ __forceinline__ void cp_wait() {
    asm volatile("cp.async.wait_group %0;" :: "n"(N) : "memory");
}

// FMA-pipe exp2 (no MUFU)
__device__ __forceinline__ float exp2p(float y) {
    y = fmaxf(y, -126.0f);
    float z = y + 12582912.0f;
    int i = __float_as_int(z) - 0x4B400000;
    float f = y - (z - 12582912.0f);
    float p = 1.3534384e-3f;
    p = fmaf(p, f, 9.6181291e-3f);
    p = fmaf(p, f, 5.5504109e-2f);
    p = fmaf(p, f, 2.4022650e-1f);
    p = fmaf(p, f, 6.9314718e-1f);
    p = fmaf(p, f, 1.0f);
    return __int_as_float(__float_as_int(p) + (i << 23));
}

#define LOG2E 1.4426950408889634f

// ---------------------------------------------------------------------------
// RoPE cos/sin table
// ---------------------------------------------------------------------------
__global__ void rope_table_kernel() {
    int idx = blockIdx.x * blockDim.x + threadIdx.x;
    if (idx >= SEQ * 32) return;
    int l = idx >> 5;
    int j = idx & 31;
    float invf = powf(10000.0f, -(float)j * (1.0f / 32.0f));
    float fr = (float)l * invf;
    g_cos[idx] = cosf(fr);
    g_sin[idx] = sinf(fr);
}

// ---------------------------------------------------------------------------
// RNA-round the five GEMM input matrices to tf32 (blockIdx.y selects array)
// ---------------------------------------------------------------------------
__global__ void __launch_bounds__(256) round_tf32_kernel(
    const float* __restrict__ x,  const float* __restrict__ Wq,
    const float* __restrict__ Wk, const float* __restrict__ Wv,
    const float* __restrict__ Wo) {
    int idx = blockIdx.x * blockDim.x + threadIdx.x;   // float4 index, 1M per array
    if (idx >= (SEQ * DM) / 4) return;
    const float* src;
    float* dst;
    switch (blockIdx.y) {
        case 0:  src = x;  dst = g_xr;  break;
        case 1:  src = Wq; dst = g_Wqr; break;
        case 2:  src = Wk; dst = g_Wkr; break;
        case 3:  src = Wv; dst = g_Wvr; break;
        default: src = Wo; dst = g_Wor; break;
    }
    float4 v = ((const float4*)src)[idx];
    v.x = tf32r(v.x); v.y = tf32r(v.y); v.z = tf32r(v.z); v.w = tf32r(v.w);
    ((float4*)dst)[idx] = v;
}

// ---------------------------------------------------------------------------
// Preprocess — one thread per float4 (round-10 version).
// ---------------------------------------------------------------------------
__global__ void __launch_bounds__(256) preprocess_kernel() {
    int t = blockIdx.x * blockDim.x + threadIdx.x;
    int which = blockIdx.y;
    if (which < 2) {
        if (t >= NH * SEQ * 16) return;
        int j4 = t & 15;
        int l = (t >> 4) & (SEQ - 1);
        int h = t >> 15;
        const float* src = (which == 0 ? g_Q : g_K) + (size_t)l * DM + h * HD + 4 * j4;
        float4 q4 = *(const float4*)src;
        float2 cs = *(const float2*)&g_cos[l * 32 + 2 * j4];
        float2 sn = *(const float2*)&g_sin[l * 32 + 2 * j4];
        float oa0 = q4.x * cs.x - q4.y * sn.x;
        float oa1 = q4.z * cs.y - q4.w * sn.y;
        float ob0 = q4.x * sn.x + q4.y * cs.x;
        float ob1 = q4.z * sn.y + q4.w * cs.y;
        float ha0 = bf_hi(oa0), ha1 = bf_hi(oa1);
        float hb0 = bf_hi(ob0), hb1 = bf_hi(ob1);
        unsigned* dh = (which == 0 ? g_QHp : g_KHp) + ((size_t)h * SEQ + l) * 32;
        unsigned* dl = (which == 0 ? g_QLp : g_KLp) + ((size_t)h * SEQ + l) * 32;
        dh[j4]      = pack_bf(ha0, ha1);
        dl[j4]      = pack_bf(oa0 - ha0, oa1 - ha1);
        dh[16 + j4] = pack_bf(hb0, hb1);
        dl[16 + j4] = pack_bf(ob0 - hb0, ob1 - hb1);
    } else {
        if (t >= NH * (SEQ / 2) * 16) return;
        int d4 = t & 15;
        int kp = (t >> 4) & (SEQ / 2 - 1);
        int h = t >> 14;
        const float* a = g_V + (size_t)(2 * kp) * DM + h * HD + 4 * d4;
        const float* b = a + DM;
        float4 va = *(const float4*)a;
        float4 vb = *(const float4*)b;
        float af[4] = {va.x, va.y, va.z, va.w};
        float bf[4] = {vb.x, vb.y, vb.z, vb.w};
        unsigned wh[4], wl[4];
#pragma unroll
        for (int jj = 0; jj < 4; jj++) {
            float hA = bf_hi(af[jj]), hB = bf_hi(bf[jj]);
            wh[jj] = pack_bf(hA, hB);
            wl[jj] = pack_bf(af[jj] - hA, bf[jj] - hB);
        }
        size_t base = ((size_t)h * (SEQ / 2) + kp) * 64 + 4 * d4;
        *(uint4*)(g_VHp + base) = make_uint4(wh[0], wh[1], wh[2], wh[3]);
        *(uint4*)(g_VLp + base) = make_uint4(wl[0], wl[1], wl[2], wl[3]);
    }
}

// ---------------------------------------------------------------------------
// TF32 GEMM, 3-stage cp.async pipeline + ldmatrix fragment loads.
// C[M,N] = A[M,K] * B[N,K]^T. 128x128x32 CTA tile, 4 warps as 2x2, each warp
// a 64x64 tile. Per k8 step: 4 A-ldsm4 + 4 B-ldsm4 feed 32 MMAs
// (0.25 load-instr/MMA vs 1.0 scalar). Layout/banking unchanged (stride 36
// words = 144 B rows; each ldmatrix phase covers all 32 banks once).
// 2 CTAs/SM.
// ---------------------------------------------------------------------------
#define SST 36
#define GTW (128 * SST)        // words per matrix tile: 4608
#define GBUFW (2 * GTW)        // A+B per buffer: 9216
#define GSTAGES 3
#define GSMEM_BYTES (GSTAGES * GBUFW * 4)   // 110592

__device__ __forceinline__ void g_issue(unsigned* buf, const float* A, const float* B,
                                        int bm, int bn, int k0) {
    int t = threadIdx.x;   // 0..127
#pragma unroll
    for (int i = 0; i < 8; i++) {
        int s = t + i * 128;            // 0..1023
        int row = s >> 3, c4 = (s & 7) * 4;
        cp16(&buf[row * SST + c4], A + (size_t)(bm + row) * DM + k0 + c4);
        cp16(&buf[GTW + row * SST + c4], B + (size_t)(bn + row) * DM + k0 + c4);
    }
    cp_commit();
}

// aoff/boff: per-thread ldmatrix byte offsets (lane-dependent), precomputed.
__device__ __forceinline__ void gemm_compute_k8(unsigned sA, unsigned sB,
                                                float acc[4][8][4], int k8,
                                                unsigned aoff, unsigned boff) {
    unsigned afr[4][4], bfr[4][4];
#pragma unroll
    for (int mi = 0; mi < 4; mi++)
        ldsm4(afr[mi], sA + aoff + (mi * 16 * SST + k8 * 8) * 4);
#pragma unroll
    for (int p = 0; p < 4; p++)
        ldsm4(bfr[p], sB + boff + (p * 16 * SST + k8 * 8) * 4);
#pragma unroll
    for (int mi = 0; mi < 4; mi++)
#pragma unroll
        for (int ni = 0; ni < 8; ni++)
            mma_tf32(acc[mi][ni], afr[mi], &bfr[ni >> 1][(ni & 1) * 2]);
}

__device__ __forceinline__ void gemm_body(float* __restrict__ C,
                                          const float* __restrict__ A,
                                          const float* __restrict__ B) {
    extern __shared__ unsigned gsm[];
    unsigned sb = (unsigned)__cvta_generic_to_shared(gsm);

    int tid = threadIdx.x;
    int lane = tid & 31, warp = tid >> 5;   // 4 warps
    int wm = warp >> 1, wn = warp & 1;      // 2 x 2
    int g = lane >> 2, tg = lane & 3;
    int bm = blockIdx.y * 128, bn = blockIdx.x * 128;
    (void)g; (void)tg;

    // ldmatrix per-lane address components:
    // A x4 matrix order: (r,c),(r+8,c),(r,c+4),(r+8,c+4)
    // B x4 matrix order: (n,c),(n,c+4),(n+8,c),(n+8,c+4)  [= ni pair]
    int m8 = lane >> 3, r8 = lane & 7;
    unsigned aoff = ((wm * 64 + ((m8 & 1) << 3) + r8) * SST + ((m8 >> 1) << 2)) * 4;
    unsigned boff = ((wn * 64 + ((m8 >> 1) << 3) + r8) * SST + ((m8 & 1) << 2)) * 4;

    float acc[4][8][4];
#pragma unroll
    for (int mi = 0; mi < 4; mi++)
#pragma unroll
        for (int ni = 0; ni < 8; ni++)
#pragma unroll
            for (int j = 0; j < 4; j++) acc[mi][ni][j] = 0.0f;

    const int NKT = DM / 32;   // 64
    g_issue(gsm, A, B, bm, bn, 0);
    g_issue(gsm + GBUFW, A, B, bm, bn, 32);

    for (int kt = 0; kt < NKT; kt++) {
        // in-flight before wait: {kt, kt+1} -> wait<1> completes kt
        if (kt + 1 < NKT) cp_wait<1>(); else cp_wait<0>();
        __syncthreads();   // tile kt visible; reads of tile kt-1 done
        if (kt + 2 < NKT)
            g_issue(gsm + ((kt + 2) % GSTAGES) * GBUFW, A, B, bm, bn, (kt + 2) * 32);
        unsigned sA = sb + (kt % GSTAGES) * GBUFW * 4;
        unsigned sB = sA + GTW * 4;
        gemm_compute_k8(sA, sB, acc, 0, aoff, boff);
        gemm_compute_k8(sA, sB, acc, 1, aoff, boff);
        gemm_compute_k8(sA, sB, acc, 2, aoff, boff);
        gemm_compute_k8(sA, sB, acc, 3, aoff, boff);
    }

    {
        int gg = lane >> 2, tg2 = lane & 3;
#pragma unroll
        for (int mi = 0; mi < 4; mi++)
#pragma unroll
            for (int ni = 0; ni < 8; ni++) {
                int r0 = bm + wm * 64 + mi * 16 + gg;
                int cc = bn + wn * 64 + ni * 8 + 2 * tg2;
                *(float2*)&C[(size_t)r0 * DM + cc] =
                    make_float2(acc[mi][ni][0], acc[mi][ni][1]);
                *(float2*)&C[(size_t)(r0 + 8) * DM + cc] =
                    make_float2(acc[mi][ni][2], acc[mi][ni][3]);
            }
    }
}

__global__ void __launch_bounds__(128, 2) gemm_qkv_kernel() {
    const float* B;
    float* C;
    if (blockIdx.z == 0)      { B = g_Wqr; C = g_Q; }
    else if (blockIdx.z == 1) { B = g_Wkr; C = g_K; }
    else                      { B = g_Wvr; C = g_V; }
    gemm_body(C, g_xr, B);
}

__global__ void __launch_bounds__(128, 2) gemm_out_kernel(float* __restrict__ C) {
    gemm_body(C, g_att, g_Wor);
}

// ---------------------------------------------------------------------------
// Split-BF16 flash attention, cp.async double-buffered (round-10 version).
// Epilogue writes g_att pre-rounded to tf32 for the out-GEMM.
// ---------------------------------------------------------------------------
#define BQ 128
#define BK 64
#define KWST 36
#define VWST 72
#define ABUF 9216
#define AOFF_KH 0
#define AOFF_KL 2304
#define AOFF_VH 4608
#define AOFF_VL 6912
#define AOFF_MS 18432
#define ASMEM_BYTES ((AOFF_MS + SEQ) * 4)   // 81920

__device__ __forceinline__ void attn_issue_tile(unsigned* buf, int h, int k0) {
    int t = threadIdx.x;
    const unsigned* KHs = g_KHp + ((size_t)h * SEQ + k0) * 32;
    const unsigned* KLs = g_KLp + ((size_t)h * SEQ + k0) * 32;
    const unsigned* VHs = g_VHp + ((size_t)h * (SEQ / 2) + (k0 >> 1)) * 64;
    const unsigned* VLs = g_VLp + ((size_t)h * (SEQ / 2) + (k0 >> 1)) * 64;
#pragma unroll
    for (int i = 0; i < 2; i++) {
        int s = t + i * 256;
        int row = s >> 3, c = (s & 7) * 4;
        cp16(&buf[AOFF_KH + row * KWST + c], KHs + row * 32 + c);
        cp16(&buf[AOFF_KL + row * KWST + c], KLs + row * 32 + c);
    }
#pragma unroll
    for (int i = 0; i < 2; i++) {
        int s = t + i * 256;
        int kp = s >> 4, c = (s & 15) * 4;
        cp16(&buf[AOFF_VH + kp * VWST + c], VHs + kp * 64 + c);
        cp16(&buf[AOFF_VL + kp * VWST + c], VLs + kp * 64 + c);
    }
    cp_commit();
}

__global__ void __launch_bounds__(256, 2) attn_bf16_kernel(const int* __restrict__ mask) {
    extern __shared__ unsigned smu[];
    int* MS = (int*)(smu + AOFF_MS);

    int tid = threadIdx.x;
    int lane = tid & 31, w = tid >> 5;
    int g = lane >> 2, tg = lane & 3;
    int h = blockIdx.y;
    int q0 = blockIdx.x * BQ;

    for (int i = tid; i < SEQ; i += 256) MS[i] = mask[i];

    attn_issue_tile(smu, h, 0);

    unsigned qh[4][4], ql[4][4];
    {
        int rA = q0 + w * 16 + g, rB = rA + 8;
        const unsigned* QH = g_QHp + (size_t)h * SEQ * 32;
        const unsigned* QL = g_QLp + (size_t)h * SEQ * 32;
#pragma unroll
        for (int ks = 0; ks < 4; ks++) {
            int c = ks * 8 + tg;
            qh[ks][0] = QH[rA * 32 + c];
            qh[ks][1] = QH[rB * 32 + c];
            qh[ks][2] = QH[rA * 32 + c + 4];
            qh[ks][3] = QH[rB * 32 + c + 4];
            ql[ks][0] = QL[rA * 32 + c];
            ql[ks][1] = QL[rB * 32 + c];
            ql[ks][2] = QL[rA * 32 + c + 4];
            ql[ks][3] = QL[rB * 32 + c + 4];
        }
    }

    float o[8][4];
#pragma unroll
    for (int ni = 0; ni < 8; ni++)
#pragma unroll
        for (int j = 0; j < 4; j++) o[ni][j] = 0.0f;
    float mA = -3.0e38f, mB = -3.0e38f, lA = 0.0f, lB = 0.0f;

    for (int kt = 0; kt < SEQ / BK; kt++) {
        int k0 = kt * BK;
        if (kt + 1 < SEQ / BK) {
            attn_issue_tile(smu + ((kt + 1) & 1) * ABUF, h, k0 + BK);
            cp_wait<1>();
        } else {
            cp_wait<0>();
        }
        __syncthreads();

        const unsigned* KH = smu + (kt & 1) * ABUF + AOFF_KH;
        const unsigned* KL = smu + (kt & 1) * ABUF + AOFF_KL;
        const unsigned* VH = smu + (kt & 1) * ABUF + AOFF_VH;
        const unsigned* VL = smu + (kt & 1) * ABUF + AOFF_VL;

        float sacc[8][4];
#pragma unroll
        for (int ni = 0; ni < 8; ni++)
#pragma unroll
            for (int j = 0; j < 4; j++) sacc[ni][j] = 0.0f;

#pragma unroll
        for (int ks = 0; ks < 4; ks++) {
#pragma unroll
            for (int ni = 0; ni < 8; ni++) {
                int kr = ni * 8 + g;
                unsigned bh[2], bl[2];
                bh[0] = KH[kr * KWST + ks * 8 + tg];
                bh[1] = KH[kr * KWST + ks * 8 + tg + 4];
                bl[0] = KL[kr * KWST + ks * 8 + tg];
                bl[1] = KL[kr * KWST + ks * 8 + tg + 4];
                mma_bf16(sacc[ni], qh[ks], bh);
                mma_bf16(sacc[ni], ql[ks], bh);
                mma_bf16(sacc[ni], qh[ks], bl);
            }
        }

#pragma unroll
        for (int ni = 0; ni < 8; ni++) {
            int m0 = MS[k0 + ni * 8 + 2 * tg];
            int m1 = MS[k0 + ni * 8 + 2 * tg + 1];
            sacc[ni][0] = m0 ? sacc[ni][0] * 0.125f : -1.0e9f;
            sacc[ni][1] = m1 ? sacc[ni][1] * 0.125f : -1.0e9f;
            sacc[ni][2] = m0 ? sacc[ni][2] * 0.125f : -1.0e9f;
            sacc[ni][3] = m1 ? sacc[ni][3] * 0.125f : -1.0e9f;
        }

        float mxA = -3.0e38f, mxB = -3.0e38f;
#pragma unroll
        for (int ni = 0; ni < 8; ni++) {
            mxA = fmaxf(mxA, fmaxf(sacc[ni][0], sacc[ni][1]));
            mxB = fmaxf(mxB, fmaxf(sacc[ni][2], sacc[ni][3]));
        }
        mxA = fmaxf(mxA, __shfl_xor_sync(0xffffffffu, mxA, 1));
        mxA = fmaxf(mxA, __shfl_xor_sync(0xffffffffu, mxA, 2));
        mxB = fmaxf(mxB, __shfl_xor_sync(0xffffffffu, mxB, 1));
        mxB = fmaxf(mxB, __shfl_xor_sync(0xffffffffu, mxB, 2));

        float mnA = fmaxf(mA, mxA), mnB = fmaxf(mB, mxB);
        float corrA = exp2p((mA - mnA) * LOG2E);
        float corrB = exp2p((mB - mnB) * LOG2E);

        float sumA = 0.0f, sumB = 0.0f;
#pragma unroll
        for (int ni = 0; ni < 8; ni++) {
            sacc[ni][0] = exp2p((sacc[ni][0] - mnA) * LOG2E);
            sacc[ni][1] = exp2p((sacc[ni][1] - mnA) * LOG2E);
            sacc[ni][2] = exp2p((sacc[ni][2] - mnB) * LOG2E);
            sacc[ni][3] = exp2p((sacc[ni][3] - mnB) * LOG2E);
            sumA += sacc[ni][0] + sacc[ni][1];
            sumB += sacc[ni][2] + sacc[ni][3];
        }
        sumA += __shfl_xor_sync(0xffffffffu, sumA, 1);
        sumA += __shfl_xor_sync(0xffffffffu, sumA, 2);
        sumB += __shfl_xor_sync(0xffffffffu, sumB, 1);
        sumB += __shfl_xor_sync(0xffffffffu, sumB, 2);

        lA = lA * corrA + sumA;
        lB = lB * corrB + sumB;
        mA = mnA;
        mB = mnB;
#pragma unroll
        for (int ni = 0; ni < 8; ni++) {
            o[ni][0] *= corrA; o[ni][1] *= corrA;
            o[ni][2] *= corrB; o[ni][3] *= corrB;
        }

#pragma unroll
        for (int ks = 0; ks < 4; ks++) {
            unsigned ah[4], al[4];
#pragma unroll
            for (int half = 0; half < 2; half++) {
                const float* s2 = sacc[2 * ks + half];
                float h0 = bf_hi(s2[0]), h1 = bf_hi(s2[1]);
                float h2 = bf_hi(s2[2]), h3 = bf_hi(s2[3]);
                ah[2 * half]     = pack_bf(h0, h1);
                ah[2 * half + 1] = pack_bf(h2, h3);
                al[2 * half]     = pack_bf(s2[0] - h0, s2[1] - h1);
                al[2 * half + 1] = pack_bf(s2[2] - h2, s2[3] - h3);
            }
#pragma unroll
            for (int ni = 0; ni < 8; ni++) {
                int vr = ks * 8 + tg;
                unsigned bh[2], bl[2];
                bh[0] = VH[vr * VWST + ni * 8 + g];
                bh[1] = VH[(vr + 4) * VWST + ni * 8 + g];
                bl[0] = VL[vr * VWST + ni * 8 + g];
                bl[1] = VL[(vr + 4) * VWST + ni * 8 + g];
                mma_bf16(o[ni], ah, bh);
                mma_bf16(o[ni], al, bh);
                mma_bf16(o[ni], ah, bl);
            }
        }
        __syncthreads();
    }

    // normalize + store, pre-rounded to tf32 for the out-GEMM
    float invA = 1.0f / lA, invB = 1.0f / lB;
    float* Og = g_att + (size_t)(q0 + w * 16) * DM + h * HD;
#pragma unroll
    for (int ni = 0; ni < 8; ni++) {
        *(float2*)&Og[(size_t)g * DM + ni * 8 + 2 * tg] =
            make_float2(tf32r(o[ni][0] * invA), tf32r(o[ni][1] * invA));
        *(float2*)&Og[(size_t)(g + 8) * DM + ni * 8 + 2 * tg] =
            make_float2(tf32r(o[ni][2] * invB), tf32r(o[ni][3] * invB));
    }
}

// ---------------------------------------------------------------------------
// launch
// ---------------------------------------------------------------------------
extern "C" void kernel_launch(void* const* d_in, const int* in_sizes, int n_in,
                              void* d_out, int out_size) {
    const float* x    = (const float*)d_in[0];
    const int*   mask = (const int*)d_in[1];
    const float* Wq   = (const float*)d_in[2];
    const float* Wk   = (const float*)d_in[3];
    const float* Wv   = (const float*)d_in[4];
    const float* Wo   = (const float*)d_in[5];
    float* out = (float*)d_out;

    cudaFuncSetAttribute(gemm_qkv_kernel, cudaFuncAttributeMaxDynamicSharedMemorySize,
                         GSMEM_BYTES);
    cudaFuncSetAttribute(gemm_out_kernel, cudaFuncAttributeMaxDynamicSharedMemorySize,
                         GSMEM_BYTES);
    cudaFuncSetAttribute(attn_bf16_kernel, cudaFuncAttributeMaxDynamicSharedMemorySize,
                         ASMEM_BYTES);

    rope_table_kernel<<<(SEQ * 32 + 255) / 256, 256>>>();
    round_tf32_kernel<<<dim3((SEQ * DM / 4 + 255) / 256, 5), 256>>>(x, Wq, Wk, Wv, Wo);
    gemm_qkv_kernel<<<dim3(16, 16, 3), 128, GSMEM_BYTES>>>();
    preprocess_kernel<<<dim3((NH * SEQ * 16 + 255) / 256, 3), 256>>>();
    attn_bf16_kernel<<<dim3(SEQ / BQ, NH), 256, ASMEM_BYTES>>>(mask);
    gemm_out_kernel<<<dim3(16, 16), 128, GSMEM_BYTES>>>(out);
}

// round 13
// speedup vs baseline: 1.2398x; 1.0295x over previous
#include <cuda_runtime.h>
#include <cuda_bf16.h>

#define SEQ 2048
#define DM 2048
#define NH 32
#define HD 64

// Scratch (static device allocations are allowed; cudaMalloc is not)
__device__ float g_Q[SEQ * DM];
__device__ float g_K[SEQ * DM];
__device__ float g_V[SEQ * DM];
__device__ float g_att[SEQ * DM];
__device__ float g_cos[SEQ * 32];
__device__ float g_sin[SEQ * 32];

// tf32-rounded copies of the GEMM inputs (cp.async feeds mma directly;
// numerics identical to cvt.rna in-kernel).
__device__ float g_xr[SEQ * DM];
__device__ float g_Wqr[DM * DM];
__device__ float g_Wkr[DM * DM];
__device__ float g_Wvr[DM * DM];
__device__ float g_Wor[DM * DM];

// Preprocessed attention operands.
// Q/K: roped, hi/lo-split, bf16x2-packed: [h][l][word j] = dims (2j,2j+1).
// V: planar bf16 hi/lo: [h][k][word w] = dims (2w,2w+1) of key k.
__device__ unsigned g_QHp[NH * SEQ * 32];
__device__ unsigned g_QLp[NH * SEQ * 32];
__device__ unsigned g_KHp[NH * SEQ * 32];
__device__ unsigned g_KLp[NH * SEQ * 32];
__device__ unsigned g_VHp[NH * SEQ * 32];
__device__ unsigned g_VLp[NH * SEQ * 32];

// ---------------------------------------------------------------------------
// helpers
// ---------------------------------------------------------------------------
__device__ __forceinline__ unsigned f2tf32(float f) {
    unsigned r;
    asm("cvt.rna.tf32.f32 %0, %1;" : "=r"(r) : "f"(f));
    return r;
}

__device__ __forceinline__ float tf32r(float f) {
    return __uint_as_float(f2tf32(f));
}

__device__ __forceinline__ void mma_tf32(float* c, const unsigned* a, const unsigned* b) {
    asm volatile(
        "mma.sync.aligned.m16n8k8.row.col.f32.tf32.tf32.f32 "
        "{%0,%1,%2,%3}, {%4,%5,%6,%7}, {%8,%9}, {%0,%1,%2,%3};"
        : "+f"(c[0]), "+f"(c[1]), "+f"(c[2]), "+f"(c[3])
        : "r"(a[0]), "r"(a[1]), "r"(a[2]), "r"(a[3]), "r"(b[0]), "r"(b[1]));
}

__device__ __forceinline__ void mma_bf16(float* c, const unsigned* a, const unsigned* b) {
    asm volatile(
        "mma.sync.aligned.m16n8k16.row.col.f32.bf16.bf16.f32 "
        "{%0,%1,%2,%3}, {%4,%5,%6,%7}, {%8,%9}, {%0,%1,%2,%3};"
        : "+f"(c[0]), "+f"(c[1]), "+f"(c[2]), "+f"(c[3])
        : "r"(a[0]), "r"(a[1]), "r"(a[2]), "r"(a[3]), "r"(b[0]), "r"(b[1]));
}

__device__ __forceinline__ void ldsm4(unsigned* r, unsigned saddr) {
    asm volatile(
        "ldmatrix.sync.aligned.m8n8.x4.shared.b16 {%0,%1,%2,%3}, [%4];"
        : "=r"(r[0]), "=r"(r[1]), "=r"(r[2]), "=r"(r[3]) : "r"(saddr));
}

__device__ __forceinline__ void ldsm4t(unsigned* r, unsigned saddr) {
    asm volatile(
        "ldmatrix.sync.aligned.m8n8.x4.trans.shared.b16 {%0,%1,%2,%3}, [%4];"
        : "=r"(r[0]), "=r"(r[1]), "=r"(r[2]), "=r"(r[3]) : "r"(saddr));
}

__device__ __forceinline__ unsigned pack_bf(float e0, float e1) {
    unsigned r;
    asm("cvt.rn.bf16x2.f32 %0, %1, %2;" : "=r"(r) : "f"(e1), "f"(e0));
    return r;
}

__device__ __forceinline__ float bf_hi(float x) {
    return __bfloat162float(__float2bfloat16(x));
}

__device__ __forceinline__ void cp16(void* sptr, const void* gptr) {
    unsigned sa = (unsigned)__cvta_generic_to_shared(sptr);
    asm volatile("cp.async.cg.shared.global [%0], [%1], 16;" :: "r"(sa), "l"(gptr)
                 : "memory");
}
__device__ __forceinline__ void cp_commit() {
    asm volatile("cp.async.commit_group;" ::: "memory");
}
template <int N>
__device__ __forceinline__ void cp_wait() {
    asm volatile("cp.async.wait_group %0;" :: "n"(N) : "memory");
}

// FMA-pipe exp2 (no MUFU)
__device__ __forceinline__ float exp2p(float y) {
    y = fmaxf(y, -126.0f);
    float z = y + 12582912.0f;
    int i = __float_as_int(z) - 0x4B400000;
    float f = y - (z - 12582912.0f);
    float p = 1.3534384e-3f;
    p = fmaf(p, f, 9.6181291e-3f);
    p = fmaf(p, f, 5.5504109e-2f);
    p = fmaf(p, f, 2.4022650e-1f);
    p = fmaf(p, f, 6.9314718e-1f);
    p = fmaf(p, f, 1.0f);
    return __int_as_float(__float_as_int(p) + (i << 23));
}

#define LOG2E 1.4426950408889634f

// ---------------------------------------------------------------------------
// RoPE cos/sin table
// ---------------------------------------------------------------------------
__global__ void rope_table_kernel() {
    int idx = blockIdx.x * blockDim.x + threadIdx.x;
    if (idx >= SEQ * 32) return;
    int l = idx >> 5;
    int j = idx & 31;
    float invf = powf(10000.0f, -(float)j * (1.0f / 32.0f));
    float fr = (float)l * invf;
    g_cos[idx] = cosf(fr);
    g_sin[idx] = sinf(fr);
}

// ---------------------------------------------------------------------------
// RNA-round the five GEMM input matrices to tf32 (blockIdx.y selects array)
// ---------------------------------------------------------------------------
__global__ void __launch_bounds__(256) round_tf32_kernel(
    const float* __restrict__ x,  const float* __restrict__ Wq,
    const float* __restrict__ Wk, const float* __restrict__ Wv,
    const float* __restrict__ Wo) {
    int idx = blockIdx.x * blockDim.x + threadIdx.x;
    if (idx >= (SEQ * DM) / 4) return;
    const float* src;
    float* dst;
    switch (blockIdx.y) {
        case 0:  src = x;  dst = g_xr;  break;
        case 1:  src = Wq; dst = g_Wqr; break;
        case 2:  src = Wk; dst = g_Wkr; break;
        case 3:  src = Wv; dst = g_Wvr; break;
        default: src = Wo; dst = g_Wor; break;
    }
    float4 v = ((const float4*)src)[idx];
    v.x = tf32r(v.x); v.y = tf32r(v.y); v.z = tf32r(v.z); v.w = tf32r(v.w);
    ((float4*)dst)[idx] = v;
}

// ---------------------------------------------------------------------------
// Preprocess — one thread per float4.
// y=0/1: rope+split Q/K -> packed [h][l][32 words].
// y=2:   split V -> planar bf16 hi/lo [h][k][32 words] (coalesced uint2).
// ---------------------------------------------------------------------------
__global__ void __launch_bounds__(256) preprocess_kernel() {
    int t = blockIdx.x * blockDim.x + threadIdx.x;
    int which = blockIdx.y;
    if (t >= NH * SEQ * 16) return;
    if (which < 2) {
        int j4 = t & 15;
        int l = (t >> 4) & (SEQ - 1);
        int h = t >> 15;
        const float* src = (which == 0 ? g_Q : g_K) + (size_t)l * DM + h * HD + 4 * j4;
        float4 q4 = *(const float4*)src;
        float2 cs = *(const float2*)&g_cos[l * 32 + 2 * j4];
        float2 sn = *(const float2*)&g_sin[l * 32 + 2 * j4];
        float oa0 = q4.x * cs.x - q4.y * sn.x;
        float oa1 = q4.z * cs.y - q4.w * sn.y;
        float ob0 = q4.x * sn.x + q4.y * cs.x;
        float ob1 = q4.z * sn.y + q4.w * cs.y;
        float ha0 = bf_hi(oa0), ha1 = bf_hi(oa1);
        float hb0 = bf_hi(ob0), hb1 = bf_hi(ob1);
        unsigned* dh = (which == 0 ? g_QHp : g_KHp) + ((size_t)h * SEQ + l) * 32;
        unsigned* dl = (which == 0 ? g_QLp : g_KLp) + ((size_t)h * SEQ + l) * 32;
        dh[j4]      = pack_bf(ha0, ha1);
        dl[j4]      = pack_bf(oa0 - ha0, oa1 - ha1);
        dh[16 + j4] = pack_bf(hb0, hb1);
        dl[16 + j4] = pack_bf(ob0 - hb0, ob1 - hb1);
    } else {
        int d4 = t & 15;
        int k = (t >> 4) & (SEQ - 1);
        int h = t >> 15;
        float4 v4 = *(const float4*)(g_V + (size_t)k * DM + h * HD + 4 * d4);
        float h0 = bf_hi(v4.x), h1 = bf_hi(v4.y);
        float h2 = bf_hi(v4.z), h3 = bf_hi(v4.w);
        size_t base = ((size_t)h * SEQ + k) * 32 + 2 * d4;
        *(uint2*)(g_VHp + base) = make_uint2(pack_bf(h0, h1), pack_bf(h2, h3));
        *(uint2*)(g_VLp + base) = make_uint2(pack_bf(v4.x - h0, v4.y - h1),
                                             pack_bf(v4.z - h2, v4.w - h3));
    }
}

// ---------------------------------------------------------------------------
// TF32 GEMM, 3-stage cp.async pipeline + ldmatrix (round-12 version).
// ---------------------------------------------------------------------------
#define SST 36
#define GTW (128 * SST)
#define GBUFW (2 * GTW)
#define GSTAGES 3
#define GSMEM_BYTES (GSTAGES * GBUFW * 4)   // 110592

__device__ __forceinline__ void g_issue(unsigned* buf, const float* A, const float* B,
                                        int bm, int bn, int k0) {
    int t = threadIdx.x;   // 0..127
#pragma unroll
    for (int i = 0; i < 8; i++) {
        int s = t + i * 128;
        int row = s >> 3, c4 = (s & 7) * 4;
        cp16(&buf[row * SST + c4], A + (size_t)(bm + row) * DM + k0 + c4);
        cp16(&buf[GTW + row * SST + c4], B + (size_t)(bn + row) * DM + k0 + c4);
    }
    cp_commit();
}

__device__ __forceinline__ void gemm_compute_k8(unsigned sA, unsigned sB,
                                                float acc[4][8][4], int k8,
                                                unsigned aoff, unsigned boff) {
    unsigned afr[4][4], bfr[4][4];
#pragma unroll
    for (int mi = 0; mi < 4; mi++)
        ldsm4(afr[mi], sA + aoff + (mi * 16 * SST + k8 * 8) * 4);
#pragma unroll
    for (int p = 0; p < 4; p++)
        ldsm4(bfr[p], sB + boff + (p * 16 * SST + k8 * 8) * 4);
#pragma unroll
    for (int mi = 0; mi < 4; mi++)
#pragma unroll
        for (int ni = 0; ni < 8; ni++)
            mma_tf32(acc[mi][ni], afr[mi], &bfr[ni >> 1][(ni & 1) * 2]);
}

__device__ __forceinline__ void gemm_body(float* __restrict__ C,
                                          const float* __restrict__ A,
                                          const float* __restrict__ B) {
    extern __shared__ unsigned gsm[];
    unsigned sb = (unsigned)__cvta_generic_to_shared(gsm);

    int tid = threadIdx.x;
    int lane = tid & 31, warp = tid >> 5;
    int wm = warp >> 1, wn = warp & 1;
    int bm = blockIdx.y * 128, bn = blockIdx.x * 128;

    int m8 = lane >> 3, r8 = lane & 7;
    unsigned aoff = ((wm * 64 + ((m8 & 1) << 3) + r8) * SST + ((m8 >> 1) << 2)) * 4;
    unsigned boff = ((wn * 64 + ((m8 >> 1) << 3) + r8) * SST + ((m8 & 1) << 2)) * 4;

    float acc[4][8][4];
#pragma unroll
    for (int mi = 0; mi < 4; mi++)
#pragma unroll
        for (int ni = 0; ni < 8; ni++)
#pragma unroll
            for (int j = 0; j < 4; j++) acc[mi][ni][j] = 0.0f;

    const int NKT = DM / 32;
    g_issue(gsm, A, B, bm, bn, 0);
    g_issue(gsm + GBUFW, A, B, bm, bn, 32);

    for (int kt = 0; kt < NKT; kt++) {
        if (kt + 1 < NKT) cp_wait<1>(); else cp_wait<0>();
        __syncthreads();
        if (kt + 2 < NKT)
            g_issue(gsm + ((kt + 2) % GSTAGES) * GBUFW, A, B, bm, bn, (kt + 2) * 32);
        unsigned sA = sb + (kt % GSTAGES) * GBUFW * 4;
        unsigned sB = sA + GTW * 4;
        gemm_compute_k8(sA, sB, acc, 0, aoff, boff);
        gemm_compute_k8(sA, sB, acc, 1, aoff, boff);
        gemm_compute_k8(sA, sB, acc, 2, aoff, boff);
        gemm_compute_k8(sA, sB, acc, 3, aoff, boff);
    }

    {
        int gg = lane >> 2, tg2 = lane & 3;
#pragma unroll
        for (int mi = 0; mi < 4; mi++)
#pragma unroll
            for (int ni = 0; ni < 8; ni++) {
                int r0 = bm + wm * 64 + mi * 16 + gg;
                int cc = bn + wn * 64 + ni * 8 + 2 * tg2;
                *(float2*)&C[(size_t)r0 * DM + cc] =
                    make_float2(acc[mi][ni][0], acc[mi][ni][1]);
                *(float2*)&C[(size_t)(r0 + 8) * DM + cc] =
                    make_float2(acc[mi][ni][2], acc[mi][ni][3]);
            }
    }
}

__global__ void __launch_bounds__(128, 2) gemm_qkv_kernel() {
    const float* B;
    float* C;
    if (blockIdx.z == 0)      { B = g_Wqr; C = g_Q; }
    else if (blockIdx.z == 1) { B = g_Wkr; C = g_K; }
    else                      { B = g_Wvr; C = g_V; }
    gemm_body(C, g_xr, B);
}

__global__ void __launch_bounds__(128, 2) gemm_out_kernel(float* __restrict__ C) {
    gemm_body(C, g_att, g_Wor);
}

// ---------------------------------------------------------------------------
// Split-BF16 flash attention with ldmatrix fragment loads.
// K tiles [key][dimword] stride 36 -> non-trans ldsm4 (GEMM-B pattern).
// V tiles planar bf16 [k][dimword] stride 36 -> trans ldsm4 gives the
// k-pair-packed B fragment directly. Per k-tile per warp: 64 ldsm4 total
// (vs 256 scalar LDS). Numerics bit-identical to round 12.
// ---------------------------------------------------------------------------
#define BQ 128
#define BK 64
#define KWST 36
#define ABUF 9216
#define AOFF_KH 0
#define AOFF_KL 2304
#define AOFF_VH 4608
#define AOFF_VL 6912
#define AOFF_MS 18432
#define ASMEM_BYTES ((AOFF_MS + SEQ) * 4)   // 81920

__device__ __forceinline__ void attn_issue_tile(unsigned* buf, int h, int k0) {
    int t = threadIdx.x;
    const unsigned* KHs = g_KHp + ((size_t)h * SEQ + k0) * 32;
    const unsigned* KLs = g_KLp + ((size_t)h * SEQ + k0) * 32;
    const unsigned* VHs = g_VHp + ((size_t)h * SEQ + k0) * 32;
    const unsigned* VLs = g_VLp + ((size_t)h * SEQ + k0) * 32;
#pragma unroll
    for (int i = 0; i < 2; i++) {
        int s = t + i * 256;            // 0..511
        int row = s >> 3, c = (s & 7) * 4;
        cp16(&buf[AOFF_KH + row * KWST + c], KHs + row * 32 + c);
        cp16(&buf[AOFF_KL + row * KWST + c], KLs + row * 32 + c);
        cp16(&buf[AOFF_VH + row * KWST + c], VHs + row * 32 + c);
        cp16(&buf[AOFF_VL + row * KWST + c], VLs + row * 32 + c);
    }
    cp_commit();
}

__global__ void __launch_bounds__(256, 2) attn_bf16_kernel(const int* __restrict__ mask) {
    extern __shared__ unsigned smu[];
    int* MS = (int*)(smu + AOFF_MS);
    unsigned smem_b = (unsigned)__cvta_generic_to_shared(smu);

    int tid = threadIdx.x;
    int lane = tid & 31, w = tid >> 5;
    int g = lane >> 2, tg = lane & 3;
    int m8 = lane >> 3, r8 = lane & 7;
    int h = blockIdx.y;
    int q0 = blockIdx.x * BQ;

    // ldmatrix per-lane offsets (words*4 = bytes)
    unsigned koff = ((((m8 >> 1) << 3) + r8) * KWST + ((m8 & 1) << 2)) * 4;
    unsigned voff = ((((m8 & 1) << 3) + r8) * KWST + ((m8 >> 1) << 2)) * 4;

    for (int i = tid; i < SEQ; i += 256) MS[i] = mask[i];

    attn_issue_tile(smu, h, 0);

    unsigned qh[4][4], ql[4][4];
    {
        int rA = q0 + w * 16 + g, rB = rA + 8;
        const unsigned* QH = g_QHp + (size_t)h * SEQ * 32;
        const unsigned* QL = g_QLp + (size_t)h * SEQ * 32;
#pragma unroll
        for (int ks = 0; ks < 4; ks++) {
            int c = ks * 8 + tg;
            qh[ks][0] = QH[rA * 32 + c];
            qh[ks][1] = QH[rB * 32 + c];
            qh[ks][2] = QH[rA * 32 + c + 4];
            qh[ks][3] = QH[rB * 32 + c + 4];
            ql[ks][0] = QL[rA * 32 + c];
            ql[ks][1] = QL[rB * 32 + c];
            ql[ks][2] = QL[rA * 32 + c + 4];
            ql[ks][3] = QL[rB * 32 + c + 4];
        }
    }

    float o[8][4];
#pragma unroll
    for (int ni = 0; ni < 8; ni++)
#pragma unroll
        for (int j = 0; j < 4; j++) o[ni][j] = 0.0f;
    float mA = -3.0e38f, mB = -3.0e38f, lA = 0.0f, lB = 0.0f;

    for (int kt = 0; kt < SEQ / BK; kt++) {
        int k0 = kt * BK;
        if (kt + 1 < SEQ / BK) {
            attn_issue_tile(smu + ((kt + 1) & 1) * ABUF, h, k0 + BK);
            cp_wait<1>();
        } else {
            cp_wait<0>();
        }
        __syncthreads();

        unsigned tb = smem_b + ((kt & 1) * ABUF) * 4;
        unsigned sKH = tb + AOFF_KH * 4;
        unsigned sKL = tb + AOFF_KL * 4;
        unsigned sVH = tb + AOFF_VH * 4;
        unsigned sVL = tb + AOFF_VL * 4;

        // --- S = Q . K^T (ldmatrix B-frags: p covers key pair 2p,2p+1) ---
        float sacc[8][4];
#pragma unroll
        for (int ni = 0; ni < 8; ni++)
#pragma unroll
            for (int j = 0; j < 4; j++) sacc[ni][j] = 0.0f;

#pragma unroll
        for (int ks = 0; ks < 4; ks++) {
#pragma unroll
            for (int p = 0; p < 4; p++) {
                unsigned bh[4], bl[4];
                unsigned off = (unsigned)((p * 16 * KWST + ks * 8) * 4);
                ldsm4(bh, sKH + koff + off);
                ldsm4(bl, sKL + koff + off);
                mma_bf16(sacc[2 * p],     qh[ks], bh);
                mma_bf16(sacc[2 * p],     ql[ks], bh);
                mma_bf16(sacc[2 * p],     qh[ks], bl);
                mma_bf16(sacc[2 * p + 1], qh[ks], bh + 2);
                mma_bf16(sacc[2 * p + 1], ql[ks], bh + 2);
                mma_bf16(sacc[2 * p + 1], qh[ks], bl + 2);
            }
        }

        // --- scale + mask ---
#pragma unroll
        for (int ni = 0; ni < 8; ni++) {
            int m0 = MS[k0 + ni * 8 + 2 * tg];
            int m1 = MS[k0 + ni * 8 + 2 * tg + 1];
            sacc[ni][0] = m0 ? sacc[ni][0] * 0.125f : -1.0e9f;
            sacc[ni][1] = m1 ? sacc[ni][1] * 0.125f : -1.0e9f;
            sacc[ni][2] = m0 ? sacc[ni][2] * 0.125f : -1.0e9f;
            sacc[ni][3] = m1 ? sacc[ni][3] * 0.125f : -1.0e9f;
        }

        // --- online softmax (rows g, g+8) ---
        float mxA = -3.0e38f, mxB = -3.0e38f;
#pragma unroll
        for (int ni = 0; ni < 8; ni++) {
            mxA = fmaxf(mxA, fmaxf(sacc[ni][0], sacc[ni][1]));
            mxB = fmaxf(mxB, fmaxf(sacc[ni][2], sacc[ni][3]));
        }
        mxA = fmaxf(mxA, __shfl_xor_sync(0xffffffffu, mxA, 1));
        mxA = fmaxf(mxA, __shfl_xor_sync(0xffffffffu, mxA, 2));
        mxB = fmaxf(mxB, __shfl_xor_sync(0xffffffffu, mxB, 1));
        mxB = fmaxf(mxB, __shfl_xor_sync(0xffffffffu, mxB, 2));

        float mnA = fmaxf(mA, mxA), mnB = fmaxf(mB, mxB);
        float corrA = exp2p((mA - mnA) * LOG2E);
        float corrB = exp2p((mB - mnB) * LOG2E);

        float sumA = 0.0f, sumB = 0.0f;
#pragma unroll
        for (int ni = 0; ni < 8; ni++) {
            sacc[ni][0] = exp2p((sacc[ni][0] - mnA) * LOG2E);
            sacc[ni][1] = exp2p((sacc[ni][1] - mnA) * LOG2E);
            sacc[ni][2] = exp2p((sacc[ni][2] - mnB) * LOG2E);
            sacc[ni][3] = exp2p((sacc[ni][3] - mnB) * LOG2E);
            sumA += sacc[ni][0] + sacc[ni][1];
            sumB += sacc[ni][2] + sacc[ni][3];
        }
        sumA += __shfl_xor_sync(0xffffffffu, sumA, 1);
        sumA += __shfl_xor_sync(0xffffffffu, sumA, 2);
        sumB += __shfl_xor_sync(0xffffffffu, sumB, 1);
        sumB += __shfl_xor_sync(0xffffffffu, sumB, 2);

        lA = lA * corrA + sumA;
        lB = lB * corrB + sumB;
        mA = mnA;
        mB = mnB;
#pragma unroll
        for (int ni = 0; ni < 8; ni++) {
            o[ni][0] *= corrA; o[ni][1] *= corrA;
            o[ni][2] *= corrB; o[ni][3] *= corrB;
        }

        // --- O += P . V (A = S C-frag; B via trans-ldsm4 on planar V) ---
#pragma unroll
        for (int ks = 0; ks < 4; ks++) {
            unsigned ah[4], al[4];
#pragma unroll
            for (int half = 0; half < 2; half++) {
                const float* s2 = sacc[2 * ks + half];
                float h0 = bf_hi(s2[0]), h1 = bf_hi(s2[1]);
                float h2 = bf_hi(s2[2]), h3 = bf_hi(s2[3]);
                ah[2 * half]     = pack_bf(h0, h1);
                ah[2 * half + 1] = pack_bf(h2, h3);
                al[2 * half]     = pack_bf(s2[0] - h0, s2[1] - h1);
                al[2 * half + 1] = pack_bf(s2[2] - h2, s2[3] - h3);
            }
#pragma unroll
            for (int p = 0; p < 4; p++) {
                unsigned vh[4], vl[4];
                unsigned off = (unsigned)((ks * 16 * KWST + p * 8) * 4);
                ldsm4t(vh, sVH + voff + off);
                ldsm4t(vl, sVL + voff + off);
                mma_bf16(o[2 * p],     ah, vh);
                mma_bf16(o[2 * p],     al, vh);
                mma_bf16(o[2 * p],     ah, vl);
                mma_bf16(o[2 * p + 1], ah, vh + 2);
                mma_bf16(o[2 * p + 1], al, vh + 2);
                mma_bf16(o[2 * p + 1], ah, vl + 2);
            }
        }
        __syncthreads();
    }

    // normalize + store, pre-rounded to tf32 for the out-GEMM
    float invA = 1.0f / lA, invB = 1.0f / lB;
    float* Og = g_att + (size_t)(q0 + w * 16) * DM + h * HD;
#pragma unroll
    for (int ni = 0; ni < 8; ni++) {
        *(float2*)&Og[(size_t)g * DM + ni * 8 + 2 * tg] =
            make_float2(tf32r(o[ni][0] * invA), tf32r(o[ni][1] * invA));
        *(float2*)&Og[(size_t)(g + 8) * DM + ni * 8 + 2 * tg] =
            make_float2(tf32r(o[ni][2] * invB), tf32r(o[ni][3] * invB));
    }
}

// ---------------------------------------------------------------------------
// launch
// ---------------------------------------------------------------------------
extern "C" void kernel_launch(void* const* d_in, const int* in_sizes, int n_in,
                              void* d_out, int out_size) {
    const float* x    = (const float*)d_in[0];
    const int*   mask = (const int*)d_in[1];
    const float* Wq   = (const float*)d_in[2];
    const float* Wk   = (const float*)d_in[3];
    const float* Wv   = (const float*)d_in[4];
    const float* Wo   = (const float*)d_in[5];
    float* out = (float*)d_out;

    cudaFuncSetAttribute(gemm_qkv_kernel, cudaFuncAttributeMaxDynamicSharedMemorySize,
                         GSMEM_BYTES);
    cudaFuncSetAttribute(gemm_out_kernel, cudaFuncAttributeMaxDynamicSharedMemorySize,
                         GSMEM_BYTES);
    cudaFuncSetAttribute(attn_bf16_kernel, cudaFuncAttributeMaxDynamicSharedMemorySize,
                         ASMEM_BYTES);

    rope_table_kernel<<<(SEQ * 32 + 255) / 256, 256>>>();
    round_tf32_kernel<<<dim3((SEQ * DM / 4 + 255) / 256, 5), 256>>>(x, Wq, Wk, Wv, Wo);
    gemm_qkv_kernel<<<dim3(16, 16, 3), 128, GSMEM_BYTES>>>();
    preprocess_kernel<<<dim3((NH * SEQ * 16 + 255) / 256, 3), 256>>>();
    attn_bf16_kernel<<<dim3(SEQ / BQ, NH), 256, ASMEM_BYTES>>>(mask);
    gemm_out_kernel<<<dim3(16, 16), 128, GSMEM_BYTES>>>(out);
}

// round 14
// speedup vs baseline: 1.2496x; 1.0078x over previous
#include <cuda_runtime.h>
#include <cuda_bf16.h>

#define SEQ 2048
#define DM 2048
#define NH 32
#define HD 64

// Scratch (static device allocations are allowed; cudaMalloc is not)
__device__ float g_Q[SEQ * DM];
__device__ float g_K[SEQ * DM];
__device__ float g_V[SEQ * DM];
__device__ float g_att[SEQ * DM];
__device__ float g_cos[SEQ * 32];
__device__ float g_sin[SEQ * 32];

// tf32-rounded copies of the GEMM inputs (cp.async feeds mma directly;
// numerics identical to cvt.rna in-kernel).
__device__ float g_xr[SEQ * DM];
__device__ float g_Wqr[DM * DM];
__device__ float g_Wkr[DM * DM];
__device__ float g_Wvr[DM * DM];
__device__ float g_Wor[DM * DM];

// Preprocessed attention operands.
// Q/K: roped, hi/lo-split, bf16x2-packed: [h][l][word j] = dims (2j,2j+1).
// V: planar bf16 hi/lo: [h][k][word w] = dims (2w,2w+1) of key k.
__device__ unsigned g_QHp[NH * SEQ * 32];
__device__ unsigned g_QLp[NH * SEQ * 32];
__device__ unsigned g_KHp[NH * SEQ * 32];
__device__ unsigned g_KLp[NH * SEQ * 32];
__device__ unsigned g_VHp[NH * SEQ * 32];
__device__ unsigned g_VLp[NH * SEQ * 32];

// ---------------------------------------------------------------------------
// helpers
// ---------------------------------------------------------------------------
__device__ __forceinline__ unsigned f2tf32(float f) {
    unsigned r;
    asm("cvt.rna.tf32.f32 %0, %1;" : "=r"(r) : "f"(f));
    return r;
}

__device__ __forceinline__ float tf32r(float f) {
    return __uint_as_float(f2tf32(f));
}

__device__ __forceinline__ void mma_tf32(float* c, const unsigned* a, const unsigned* b) {
    asm volatile(
        "mma.sync.aligned.m16n8k8.row.col.f32.tf32.tf32.f32 "
        "{%0,%1,%2,%3}, {%4,%5,%6,%7}, {%8,%9}, {%0,%1,%2,%3};"
        : "+f"(c[0]), "+f"(c[1]), "+f"(c[2]), "+f"(c[3])
        : "r"(a[0]), "r"(a[1]), "r"(a[2]), "r"(a[3]), "r"(b[0]), "r"(b[1]));
}

__device__ __forceinline__ void mma_bf16(float* c, const unsigned* a, const unsigned* b) {
    asm volatile(
        "mma.sync.aligned.m16n8k16.row.col.f32.bf16.bf16.f32 "
        "{%0,%1,%2,%3}, {%4,%5,%6,%7}, {%8,%9}, {%0,%1,%2,%3};"
        : "+f"(c[0]), "+f"(c[1]), "+f"(c[2]), "+f"(c[3])
        : "r"(a[0]), "r"(a[1]), "r"(a[2]), "r"(a[3]), "r"(b[0]), "r"(b[1]));
}

__device__ __forceinline__ void ldsm4(unsigned* r, unsigned saddr) {
    asm volatile(
        "ldmatrix.sync.aligned.m8n8.x4.shared.b16 {%0,%1,%2,%3}, [%4];"
        : "=r"(r[0]), "=r"(r[1]), "=r"(r[2]), "=r"(r[3]) : "r"(saddr));
}

__device__ __forceinline__ void ldsm4t(unsigned* r, unsigned saddr) {
    asm volatile(
        "ldmatrix.sync.aligned.m8n8.x4.trans.shared.b16 {%0,%1,%2,%3}, [%4];"
        : "=r"(r[0]), "=r"(r[1]), "=r"(r[2]), "=r"(r[3]) : "r"(saddr));
}

__device__ __forceinline__ unsigned pack_bf(float e0, float e1) {
    unsigned r;
    asm("cvt.rn.bf16x2.f32 %0, %1, %2;" : "=r"(r) : "f"(e1), "f"(e0));
    return r;
}

__device__ __forceinline__ float bf_hi(float x) {
    return __bfloat162float(__float2bfloat16(x));
}

__device__ __forceinline__ void cp16(void* sptr, const void* gptr) {
    unsigned sa = (unsigned)__cvta_generic_to_shared(sptr);
    asm volatile("cp.async.cg.shared.global [%0], [%1], 16;" :: "r"(sa), "l"(gptr)
                 : "memory");
}
__device__ __forceinline__ void cp_commit() {
    asm volatile("cp.async.commit_group;" ::: "memory");
}
template <int N>
__device__ __forceinline__ void cp_wait() {
    asm volatile("cp.async.wait_group %0;" :: "n"(N) : "memory");
}

// FMA-pipe exp2 (no MUFU)
__device__ __forceinline__ float exp2p(float y) {
    y = fmaxf(y, -126.0f);
    float z = y + 12582912.0f;
    int i = __float_as_int(z) - 0x4B400000;
    float f = y - (z - 12582912.0f);
    float p = 1.3534384e-3f;
    p = fmaf(p, f, 9.6181291e-3f);
    p = fmaf(p, f, 5.5504109e-2f);
    p = fmaf(p, f, 2.4022650e-1f);
    p = fmaf(p, f, 6.9314718e-1f);
    p = fmaf(p, f, 1.0f);
    return __int_as_float(__float_as_int(p) + (i << 23));
}

#define LOG2E 1.4426950408889634f

// ---------------------------------------------------------------------------
// RoPE cos/sin table
// ---------------------------------------------------------------------------
__global__ void rope_table_kernel() {
    int idx = blockIdx.x * blockDim.x + threadIdx.x;
    if (idx >= SEQ * 32) return;
    int l = idx >> 5;
    int j = idx & 31;
    float invf = powf(10000.0f, -(float)j * (1.0f / 32.0f));
    float fr = (float)l * invf;
    g_cos[idx] = cosf(fr);
    g_sin[idx] = sinf(fr);
}

// ---------------------------------------------------------------------------
// RNA-round the five GEMM input matrices to tf32 (blockIdx.y selects array)
// ---------------------------------------------------------------------------
__global__ void __launch_bounds__(256) round_tf32_kernel(
    const float* __restrict__ x,  const float* __restrict__ Wq,
    const float* __restrict__ Wk, const float* __restrict__ Wv,
    const float* __restrict__ Wo) {
    int idx = blockIdx.x * blockDim.x + threadIdx.x;
    if (idx >= (SEQ * DM) / 4) return;
    const float* src;
    float* dst;
    switch (blockIdx.y) {
        case 0:  src = x;  dst = g_xr;  break;
        case 1:  src = Wq; dst = g_Wqr; break;
        case 2:  src = Wk; dst = g_Wkr; break;
        case 3:  src = Wv; dst = g_Wvr; break;
        default: src = Wo; dst = g_Wor; break;
    }
    float4 v = ((const float4*)src)[idx];
    v.x = tf32r(v.x); v.y = tf32r(v.y); v.z = tf32r(v.z); v.w = tf32r(v.w);
    ((float4*)dst)[idx] = v;
}

// ---------------------------------------------------------------------------
// Preprocess — one thread per float4 (round-13 version).
// ---------------------------------------------------------------------------
__global__ void __launch_bounds__(256) preprocess_kernel() {
    int t = blockIdx.x * blockDim.x + threadIdx.x;
    int which = blockIdx.y;
    if (t >= NH * SEQ * 16) return;
    if (which < 2) {
        int j4 = t & 15;
        int l = (t >> 4) & (SEQ - 1);
        int h = t >> 15;
        const float* src = (which == 0 ? g_Q : g_K) + (size_t)l * DM + h * HD + 4 * j4;
        float4 q4 = *(const float4*)src;
        float2 cs = *(const float2*)&g_cos[l * 32 + 2 * j4];
        float2 sn = *(const float2*)&g_sin[l * 32 + 2 * j4];
        float oa0 = q4.x * cs.x - q4.y * sn.x;
        float oa1 = q4.z * cs.y - q4.w * sn.y;
        float ob0 = q4.x * sn.x + q4.y * cs.x;
        float ob1 = q4.z * sn.y + q4.w * cs.y;
        float ha0 = bf_hi(oa0), ha1 = bf_hi(oa1);
        float hb0 = bf_hi(ob0), hb1 = bf_hi(ob1);
        unsigned* dh = (which == 0 ? g_QHp : g_KHp) + ((size_t)h * SEQ + l) * 32;
        unsigned* dl = (which == 0 ? g_QLp : g_KLp) + ((size_t)h * SEQ + l) * 32;
        dh[j4]      = pack_bf(ha0, ha1);
        dl[j4]      = pack_bf(oa0 - ha0, oa1 - ha1);
        dh[16 + j4] = pack_bf(hb0, hb1);
        dl[16 + j4] = pack_bf(ob0 - hb0, ob1 - hb1);
    } else {
        int d4 = t & 15;
        int k = (t >> 4) & (SEQ - 1);
        int h = t >> 15;
        float4 v4 = *(const float4*)(g_V + (size_t)k * DM + h * HD + 4 * d4);
        float h0 = bf_hi(v4.x), h1 = bf_hi(v4.y);
        float h2 = bf_hi(v4.z), h3 = bf_hi(v4.w);
        size_t base = ((size_t)h * SEQ + k) * 32 + 2 * d4;
        *(uint2*)(g_VHp + base) = make_uint2(pack_bf(h0, h1), pack_bf(h2, h3));
        *(uint2*)(g_VLp + base) = make_uint2(pack_bf(v4.x - h0, v4.y - h1),
                                             pack_bf(v4.z - h2, v4.w - h3));
    }
}

// ---------------------------------------------------------------------------
// TF32 GEMM: 2-stage cp.async pipeline + ldmatrix, 3 CTAs/SM (12 warps/SM).
// C[M,N] = A[M,K] * B[N,K]^T. 128x128x32 CTA tile, 4 warps as 2x2, 64x64
// warp tiles. Copy of tile kt+1 overlaps compute of kt (issue-at-top +
// trailing sync pattern).
// ---------------------------------------------------------------------------
#define SST 36
#define GTW (128 * SST)
#define GBUFW (2 * GTW)
#define GSMEM_BYTES (2 * GBUFW * 4)   // 73728

__device__ __forceinline__ void g_issue(unsigned* buf, const float* A, const float* B,
                                        int bm, int bn, int k0) {
    int t = threadIdx.x;   // 0..127
#pragma unroll
    for (int i = 0; i < 8; i++) {
        int s = t + i * 128;
        int row = s >> 3, c4 = (s & 7) * 4;
        cp16(&buf[row * SST + c4], A + (size_t)(bm + row) * DM + k0 + c4);
        cp16(&buf[GTW + row * SST + c4], B + (size_t)(bn + row) * DM + k0 + c4);
    }
    cp_commit();
}

__device__ __forceinline__ void gemm_compute_k8(unsigned sA, unsigned sB,
                                                float acc[4][8][4], int k8,
                                                unsigned aoff, unsigned boff) {
    unsigned afr[4][4], bfr[4][4];
#pragma unroll
    for (int mi = 0; mi < 4; mi++)
        ldsm4(afr[mi], sA + aoff + (mi * 16 * SST + k8 * 8) * 4);
#pragma unroll
    for (int p = 0; p < 4; p++)
        ldsm4(bfr[p], sB + boff + (p * 16 * SST + k8 * 8) * 4);
#pragma unroll
    for (int mi = 0; mi < 4; mi++)
#pragma unroll
        for (int ni = 0; ni < 8; ni++)
            mma_tf32(acc[mi][ni], afr[mi], &bfr[ni >> 1][(ni & 1) * 2]);
}

__device__ __forceinline__ void gemm_body(float* __restrict__ C,
                                          const float* __restrict__ A,
                                          const float* __restrict__ B) {
    extern __shared__ unsigned gsm[];
    unsigned sb = (unsigned)__cvta_generic_to_shared(gsm);

    int tid = threadIdx.x;
    int lane = tid & 31, warp = tid >> 5;
    int wm = warp >> 1, wn = warp & 1;
    int bm = blockIdx.y * 128, bn = blockIdx.x * 128;

    int m8 = lane >> 3, r8 = lane & 7;
    unsigned aoff = ((wm * 64 + ((m8 & 1) << 3) + r8) * SST + ((m8 >> 1) << 2)) * 4;
    unsigned boff = ((wn * 64 + ((m8 >> 1) << 3) + r8) * SST + ((m8 & 1) << 2)) * 4;

    float acc[4][8][4];
#pragma unroll
    for (int mi = 0; mi < 4; mi++)
#pragma unroll
        for (int ni = 0; ni < 8; ni++)
#pragma unroll
            for (int j = 0; j < 4; j++) acc[mi][ni][j] = 0.0f;

    const int NKT = DM / 32;
    g_issue(gsm, A, B, bm, bn, 0);

    for (int kt = 0; kt < NKT; kt++) {
        if (kt + 1 < NKT) {
            g_issue(gsm + ((kt + 1) & 1) * GBUFW, A, B, bm, bn, (kt + 1) * 32);
            cp_wait<1>();
        } else {
            cp_wait<0>();
        }
        __syncthreads();
        unsigned sA = sb + (kt & 1) * GBUFW * 4;
        unsigned sB = sA + GTW * 4;
        gemm_compute_k8(sA, sB, acc, 0, aoff, boff);
        gemm_compute_k8(sA, sB, acc, 1, aoff, boff);
        gemm_compute_k8(sA, sB, acc, 2, aoff, boff);
        gemm_compute_k8(sA, sB, acc, 3, aoff, boff);
        __syncthreads();   // readers done -> next issue may overwrite buffer
    }

    {
        int gg = lane >> 2, tg2 = lane & 3;
#pragma unroll
        for (int mi = 0; mi < 4; mi++)
#pragma unroll
            for (int ni = 0; ni < 8; ni++) {
                int r0 = bm + wm * 64 + mi * 16 + gg;
                int cc = bn + wn * 64 + ni * 8 + 2 * tg2;
                *(float2*)&C[(size_t)r0 * DM + cc] =
                    make_float2(acc[mi][ni][0], acc[mi][ni][1]);
                *(float2*)&C[(size_t)(r0 + 8) * DM + cc] =
                    make_float2(acc[mi][ni][2], acc[mi][ni][3]);
            }
    }
}

__global__ void __launch_bounds__(128, 3) gemm_qkv_kernel() {
    const float* B;
    float* C;
    if (blockIdx.z == 0)      { B = g_Wqr; C = g_Q; }
    else if (blockIdx.z == 1) { B = g_Wkr; C = g_K; }
    else                      { B = g_Wvr; C = g_V; }
    gemm_body(C, g_xr, B);
}

__global__ void __launch_bounds__(128, 3) gemm_out_kernel(float* __restrict__ C) {
    gemm_body(C, g_att, g_Wor);
}

// ---------------------------------------------------------------------------
// Split-BF16 flash attention: ldmatrix + 3-stage cp.async, ONE sync/tile.
// Mask stored as bytes (2 KB) to fit the 3rd stage in 2-CTA/SM smem.
// ---------------------------------------------------------------------------
#define BQ 128
#define BK 64
#define KWST 36
#define ABUF 9216
#define ASTAGES 3
#define AOFF_KH 0
#define AOFF_KL 2304
#define AOFF_VH 4608
#define AOFF_VL 6912
#define AOFF_MS (ASTAGES * ABUF)            // word offset 27648
#define ASMEM_BYTES ((AOFF_MS + SEQ / 4) * 4)   // 112640

__device__ __forceinline__ void attn_issue_tile(unsigned* buf, int h, int k0) {
    int t = threadIdx.x;
    const unsigned* KHs = g_KHp + ((size_t)h * SEQ + k0) * 32;
    const unsigned* KLs = g_KLp + ((size_t)h * SEQ + k0) * 32;
    const unsigned* VHs = g_VHp + ((size_t)h * SEQ + k0) * 32;
    const unsigned* VLs = g_VLp + ((size_t)h * SEQ + k0) * 32;
#pragma unroll
    for (int i = 0; i < 2; i++) {
        int s = t + i * 256;            // 0..511
        int row = s >> 3, c = (s & 7) * 4;
        cp16(&buf[AOFF_KH + row * KWST + c], KHs + row * 32 + c);
        cp16(&buf[AOFF_KL + row * KWST + c], KLs + row * 32 + c);
        cp16(&buf[AOFF_VH + row * KWST + c], VHs + row * 32 + c);
        cp16(&buf[AOFF_VL + row * KWST + c], VLs + row * 32 + c);
    }
    cp_commit();
}

__global__ void __launch_bounds__(256, 2) attn_bf16_kernel(const int* __restrict__ mask) {
    extern __shared__ unsigned smu[];
    unsigned char* MSB = (unsigned char*)(smu + AOFF_MS);
    unsigned smem_b = (unsigned)__cvta_generic_to_shared(smu);

    int tid = threadIdx.x;
    int lane = tid & 31, w = tid >> 5;
    int g = lane >> 2, tg = lane & 3;
    int m8 = lane >> 3, r8 = lane & 7;
    int h = blockIdx.y;
    int q0 = blockIdx.x * BQ;

    unsigned koff = ((((m8 >> 1) << 3) + r8) * KWST + ((m8 & 1) << 2)) * 4;
    unsigned voff = ((((m8 & 1) << 3) + r8) * KWST + ((m8 >> 1) << 2)) * 4;

    for (int i = tid; i < SEQ; i += 256) MSB[i] = (unsigned char)(mask[i] != 0);

    attn_issue_tile(smu, h, 0);
    attn_issue_tile(smu + ABUF, h, BK);

    unsigned qh[4][4], ql[4][4];
    {
        int rA = q0 + w * 16 + g, rB = rA + 8;
        const unsigned* QH = g_QHp + (size_t)h * SEQ * 32;
        const unsigned* QL = g_QLp + (size_t)h * SEQ * 32;
#pragma unroll
        for (int ks = 0; ks < 4; ks++) {
            int c = ks * 8 + tg;
            qh[ks][0] = QH[rA * 32 + c];
            qh[ks][1] = QH[rB * 32 + c];
            qh[ks][2] = QH[rA * 32 + c + 4];
            qh[ks][3] = QH[rB * 32 + c + 4];
            ql[ks][0] = QL[rA * 32 + c];
            ql[ks][1] = QL[rB * 32 + c];
            ql[ks][2] = QL[rA * 32 + c + 4];
            ql[ks][3] = QL[rB * 32 + c + 4];
        }
    }

    float o[8][4];
#pragma unroll
    for (int ni = 0; ni < 8; ni++)
#pragma unroll
        for (int j = 0; j < 4; j++) o[ni][j] = 0.0f;
    float mA = -3.0e38f, mB = -3.0e38f, lA = 0.0f, lB = 0.0f;

    const int NKT = SEQ / BK;
    for (int kt = 0; kt < NKT; kt++) {
        int k0 = kt * BK;
        // outstanding groups {kt, kt+1} -> wait<1> completes kt
        if (kt + 1 < NKT) cp_wait<1>(); else cp_wait<0>();
        __syncthreads();   // tile kt visible; compute of kt-1 done everywhere
        if (kt + 2 < NKT)
            attn_issue_tile(smu + ((kt + 2) % ASTAGES) * ABUF, h, k0 + 2 * BK);

        unsigned tb = smem_b + ((kt % ASTAGES) * ABUF) * 4;
        unsigned sKH = tb + AOFF_KH * 4;
        unsigned sKL = tb + AOFF_KL * 4;
        unsigned sVH = tb + AOFF_VH * 4;
        unsigned sVL = tb + AOFF_VL * 4;

        // --- S = Q . K^T ---
        float sacc[8][4];
#pragma unroll
        for (int ni = 0; ni < 8; ni++)
#pragma unroll
            for (int j = 0; j < 4; j++) sacc[ni][j] = 0.0f;

#pragma unroll
        for (int ks = 0; ks < 4; ks++) {
#pragma unroll
            for (int p = 0; p < 4; p++) {
                unsigned bh[4], bl[4];
                unsigned off = (unsigned)((p * 16 * KWST + ks * 8) * 4);
                ldsm4(bh, sKH + koff + off);
                ldsm4(bl, sKL + koff + off);
                mma_bf16(sacc[2 * p],     qh[ks], bh);
                mma_bf16(sacc[2 * p],     ql[ks], bh);
                mma_bf16(sacc[2 * p],     qh[ks], bl);
                mma_bf16(sacc[2 * p + 1], qh[ks], bh + 2);
                mma_bf16(sacc[2 * p + 1], ql[ks], bh + 2);
                mma_bf16(sacc[2 * p + 1], qh[ks], bl + 2);
            }
        }

        // --- scale + mask ---
#pragma unroll
        for (int ni = 0; ni < 8; ni++) {
            int m0 = MSB[k0 + ni * 8 + 2 * tg];
            int m1 = MSB[k0 + ni * 8 + 2 * tg + 1];
            sacc[ni][0] = m0 ? sacc[ni][0] * 0.125f : -1.0e9f;
            sacc[ni][1] = m1 ? sacc[ni][1] * 0.125f : -1.0e9f;
            sacc[ni][2] = m0 ? sacc[ni][2] * 0.125f : -1.0e9f;
            sacc[ni][3] = m1 ? sacc[ni][3] * 0.125f : -1.0e9f;
        }

        // --- online softmax (rows g, g+8) ---
        float mxA = -3.0e38f, mxB = -3.0e38f;
#pragma unroll
        for (int ni = 0; ni < 8; ni++) {
            mxA = fmaxf(mxA, fmaxf(sacc[ni][0], sacc[ni][1]));
            mxB = fmaxf(mxB, fmaxf(sacc[ni][2], sacc[ni][3]));
        }
        mxA = fmaxf(mxA, __shfl_xor_sync(0xffffffffu, mxA, 1));
        mxA = fmaxf(mxA, __shfl_xor_sync(0xffffffffu, mxA, 2));
        mxB = fmaxf(mxB, __shfl_xor_sync(0xffffffffu, mxB, 1));
        mxB = fmaxf(mxB, __shfl_xor_sync(0xffffffffu, mxB, 2));

        float mnA = fmaxf(mA, mxA), mnB = fmaxf(mB, mxB);
        float corrA = exp2p((mA - mnA) * LOG2E);
        float corrB = exp2p((mB - mnB) * LOG2E);

        float sumA = 0.0f, sumB = 0.0f;
#pragma unroll
        for (int ni = 0; ni < 8; ni++) {
            sacc[ni][0] = exp2p((sacc[ni][0] - mnA) * LOG2E);
            sacc[ni][1] = exp2p((sacc[ni][1] - mnA) * LOG2E);
            sacc[ni][2] = exp2p((sacc[ni][2] - mnB) * LOG2E);
            sacc[ni][3] = exp2p((sacc[ni][3] - mnB) * LOG2E);
            sumA += sacc[ni][0] + sacc[ni][1];
            sumB += sacc[ni][2] + sacc[ni][3];
        }
        sumA += __shfl_xor_sync(0xffffffffu, sumA, 1);
        sumA += __shfl_xor_sync(0xffffffffu, sumA, 2);
        sumB += __shfl_xor_sync(0xffffffffu, sumB, 1);
        sumB += __shfl_xor_sync(0xffffffffu, sumB, 2);

        lA = lA * corrA + sumA;
        lB = lB * corrB + sumB;
        mA = mnA;
        mB = mnB;
#pragma unroll
        for (int ni = 0; ni < 8; ni++) {
            o[ni][0] *= corrA; o[ni][1] *= corrA;
            o[ni][2] *= corrB; o[ni][3] *= corrB;
        }

        // --- O += P . V ---
#pragma unroll
        for (int ks = 0; ks < 4; ks++) {
            unsigned ah[4], al[4];
#pragma unroll
            for (int half = 0; half < 2; half++) {
                const float* s2 = sacc[2 * ks + half];
                float h0 = bf_hi(s2[0]), h1 = bf_hi(s2[1]);
                float h2 = bf_hi(s2[2]), h3 = bf_hi(s2[3]);
                ah[2 * half]     = pack_bf(h0, h1);
                ah[2 * half + 1] = pack_bf(h2, h3);
                al[2 * half]     = pack_bf(s2[0] - h0, s2[1] - h1);
                al[2 * half + 1] = pack_bf(s2[2] - h2, s2[3] - h3);
            }
#pragma unroll
            for (int p = 0; p < 4; p++) {
                unsigned vh[4], vl[4];
                unsigned off = (unsigned)((ks * 16 * KWST + p * 8) * 4);
                ldsm4t(vh, sVH + voff + off);
                ldsm4t(vl, sVL + voff + off);
                mma_bf16(o[2 * p],     ah, vh);
                mma_bf16(o[2 * p],     al, vh);
                mma_bf16(o[2 * p],     ah, vl);
                mma_bf16(o[2 * p + 1], ah, vh + 2);
                mma_bf16(o[2 * p + 1], al, vh + 2);
                mma_bf16(o[2 * p + 1], ah, vl + 2);
            }
        }
    }

    // normalize + store, pre-rounded to tf32 for the out-GEMM
    float invA = 1.0f / lA, invB = 1.0f / lB;
    float* Og = g_att + (size_t)(q0 + w * 16) * DM + h * HD;
#pragma unroll
    for (int ni = 0; ni < 8; ni++) {
        *(float2*)&Og[(size_t)g * DM + ni * 8 + 2 * tg] =
            make_float2(tf32r(o[ni][0] * invA), tf32r(o[ni][1] * invA));
        *(float2*)&Og[(size_t)(g + 8) * DM + ni * 8 + 2 * tg] =
            make_float2(tf32r(o[ni][2] * invB), tf32r(o[ni][3] * invB));
    }
}

// ---------------------------------------------------------------------------
// launch
// ---------------------------------------------------------------------------
extern "C" void kernel_launch(void* const* d_in, const int* in_sizes, int n_in,
                              void* d_out, int out_size) {
    const float* x    = (const float*)d_in[0];
    const int*   mask = (const int*)d_in[1];
    const float* Wq   = (const float*)d_in[2];
    const float* Wk   = (const float*)d_in[3];
    const float* Wv   = (const float*)d_in[4];
    const float* Wo   = (const float*)d_in[5];
    float* out = (float*)d_out;

    cudaFuncSetAttribute(gemm_qkv_kernel, cudaFuncAttributeMaxDynamicSharedMemorySize,
                         GSMEM_BYTES);
    cudaFuncSetAttribute(gemm_out_kernel, cudaFuncAttributeMaxDynamicSharedMemorySize,
                         GSMEM_BYTES);
    cudaFuncSetAttribute(attn_bf16_kernel, cudaFuncAttributeMaxDynamicSharedMemorySize,
                         ASMEM_BYTES);

    rope_table_kernel<<<(SEQ * 32 + 255) / 256, 256>>>();
    round_tf32_kernel<<<dim3((SEQ * DM / 4 + 255) / 256, 5), 256>>>(x, Wq, Wk, Wv, Wo);
    gemm_qkv_kernel<<<dim3(16, 16, 3), 128, GSMEM_BYTES>>>();
    preprocess_kernel<<<dim3((NH * SEQ * 16 + 255) / 256, 3), 256>>>();
    attn_bf16_kernel<<<dim3(SEQ / BQ, NH), 256, ASMEM_BYTES>>>(mask);
    gemm_out_kernel<<<dim3(16, 16), 128, GSMEM_BYTES>>>(out);
}

// round 15
// speedup vs baseline: 1.3224x; 1.0583x over previous
#include <cuda_runtime.h>
#include <cuda_bf16.h>

#define SEQ 2048
#define DM 2048
#define NH 32
#define HD 64

// Scratch (static device allocations are allowed; cudaMalloc is not)
__device__ float g_Q[SEQ * DM];
__device__ float g_K[SEQ * DM];
__device__ float g_V[SEQ * DM];
__device__ float g_att[SEQ * DM];
__device__ float g_cos[SEQ * 32];
__device__ float g_sin[SEQ * 32];

// tf32-rounded copies of the GEMM inputs (cp.async feeds mma directly;
// numerics identical to cvt.rna in-kernel).
__device__ float g_xr[SEQ * DM];
__device__ float g_Wqr[DM * DM];
__device__ float g_Wkr[DM * DM];
__device__ float g_Wvr[DM * DM];
__device__ float g_Wor[DM * DM];

// Preprocessed attention operands.
// Q: roped, pre-scaled by 0.125*log2(e), hi/lo-split bf16x2: [h][l][32 words].
// K: roped, hi/lo-split bf16x2. V: planar bf16 hi/lo [h][k][32 words].
__device__ unsigned g_QHp[NH * SEQ * 32];
__device__ unsigned g_QLp[NH * SEQ * 32];
__device__ unsigned g_KHp[NH * SEQ * 32];
__device__ unsigned g_KLp[NH * SEQ * 32];
__device__ unsigned g_VHp[NH * SEQ * 32];
__device__ unsigned g_VLp[NH * SEQ * 32];

#define LOG2E 1.4426950408889634f
// scores arrive already scaled by 0.125*log2e; masked entries use the
// equivalently scaled constant so softmax is unchanged.
#define MASKVAL (-1.0e9f * 1.4426950408889634f)

// ---------------------------------------------------------------------------
// helpers
// ---------------------------------------------------------------------------
__device__ __forceinline__ unsigned f2tf32(float f) {
    unsigned r;
    asm("cvt.rna.tf32.f32 %0, %1;" : "=r"(r) : "f"(f));
    return r;
}

__device__ __forceinline__ float tf32r(float f) {
    return __uint_as_float(f2tf32(f));
}

__device__ __forceinline__ void mma_tf32(float* c, const unsigned* a, const unsigned* b) {
    asm volatile(
        "mma.sync.aligned.m16n8k8.row.col.f32.tf32.tf32.f32 "
        "{%0,%1,%2,%3}, {%4,%5,%6,%7}, {%8,%9}, {%0,%1,%2,%3};"
        : "+f"(c[0]), "+f"(c[1]), "+f"(c[2]), "+f"(c[3])
        : "r"(a[0]), "r"(a[1]), "r"(a[2]), "r"(a[3]), "r"(b[0]), "r"(b[1]));
}

__device__ __forceinline__ void mma_bf16(float* c, const unsigned* a, const unsigned* b) {
    asm volatile(
        "mma.sync.aligned.m16n8k16.row.col.f32.bf16.bf16.f32 "
        "{%0,%1,%2,%3}, {%4,%5,%6,%7}, {%8,%9}, {%0,%1,%2,%3};"
        : "+f"(c[0]), "+f"(c[1]), "+f"(c[2]), "+f"(c[3])
        : "r"(a[0]), "r"(a[1]), "r"(a[2]), "r"(a[3]), "r"(b[0]), "r"(b[1]));
}

__device__ __forceinline__ void ldsm4(unsigned* r, unsigned saddr) {
    asm volatile(
        "ldmatrix.sync.aligned.m8n8.x4.shared.b16 {%0,%1,%2,%3}, [%4];"
        : "=r"(r[0]), "=r"(r[1]), "=r"(r[2]), "=r"(r[3]) : "r"(saddr));
}

__device__ __forceinline__ void ldsm4t(unsigned* r, unsigned saddr) {
    asm volatile(
        "ldmatrix.sync.aligned.m8n8.x4.trans.shared.b16 {%0,%1,%2,%3}, [%4];"
        : "=r"(r[0]), "=r"(r[1]), "=r"(r[2]), "=r"(r[3]) : "r"(saddr));
}

__device__ __forceinline__ unsigned pack_bf(float e0, float e1) {
    unsigned r;
    asm("cvt.rn.bf16x2.f32 %0, %1, %2;" : "=r"(r) : "f"(e1), "f"(e0));
    return r;
}

__device__ __forceinline__ float bf_hi(float x) {
    return __bfloat162float(__float2bfloat16(x));
}

// MUFU exp2: offloads the softmax exponentials to the (idle) MUFU pipe.
// ex2.approx: ~2^-22 rel error; very negative args -> 0 (no clamp needed).
__device__ __forceinline__ float ex2(float y) {
    float r;
    asm("ex2.approx.ftz.f32 %0, %1;" : "=f"(r) : "f"(y));
    return r;
}

__device__ __forceinline__ void cp16(void* sptr, const void* gptr) {
    unsigned sa = (unsigned)__cvta_generic_to_shared(sptr);
    asm volatile("cp.async.cg.shared.global [%0], [%1], 16;" :: "r"(sa), "l"(gptr)
                 : "memory");
}
__device__ __forceinline__ void cp_commit() {
    asm volatile("cp.async.commit_group;" ::: "memory");
}
template <int N>
__device__ __forceinline__ void cp_wait() {
    asm volatile("cp.async.wait_group %0;" :: "n"(N) : "memory");
}

// ---------------------------------------------------------------------------
// RoPE cos/sin table
// ---------------------------------------------------------------------------
__global__ void rope_table_kernel() {
    int idx = blockIdx.x * blockDim.x + threadIdx.x;
    if (idx >= SEQ * 32) return;
    int l = idx >> 5;
    int j = idx & 31;
    float invf = powf(10000.0f, -(float)j * (1.0f / 32.0f));
    float fr = (float)l * invf;
    g_cos[idx] = cosf(fr);
    g_sin[idx] = sinf(fr);
}

// ---------------------------------------------------------------------------
// RNA-round the five GEMM input matrices to tf32 (blockIdx.y selects array)
// ---------------------------------------------------------------------------
__global__ void __launch_bounds__(256) round_tf32_kernel(
    const float* __restrict__ x,  const float* __restrict__ Wq,
    const float* __restrict__ Wk, const float* __restrict__ Wv,
    const float* __restrict__ Wo) {
    int idx = blockIdx.x * blockDim.x + threadIdx.x;
    if (idx >= (SEQ * DM) / 4) return;
    const float* src;
    float* dst;
    switch (blockIdx.y) {
        case 0:  src = x;  dst = g_xr;  break;
        case 1:  src = Wq; dst = g_Wqr; break;
        case 2:  src = Wk; dst = g_Wkr; break;
        case 3:  src = Wv; dst = g_Wvr; break;
        default: src = Wo; dst = g_Wor; break;
    }
    float4 v = ((const float4*)src)[idx];
    v.x = tf32r(v.x); v.y = tf32r(v.y); v.z = tf32r(v.z); v.w = tf32r(v.w);
    ((float4*)dst)[idx] = v;
}

// ---------------------------------------------------------------------------
// Preprocess — one thread per float4.
// y=0: rope Q, pre-scale by 0.125*log2e, split -> packed [h][l][32 words].
// y=1: rope K, split. y=2: split V planar.
// ---------------------------------------------------------------------------
__global__ void __launch_bounds__(256) preprocess_kernel() {
    int t = blockIdx.x * blockDim.x + threadIdx.x;
    int which = blockIdx.y;
    if (t >= NH * SEQ * 16) return;
    if (which < 2) {
        int j4 = t & 15;
        int l = (t >> 4) & (SEQ - 1);
        int h = t >> 15;
        const float* src = (which == 0 ? g_Q : g_K) + (size_t)l * DM + h * HD + 4 * j4;
        float4 q4 = *(const float4*)src;
        if (which == 0) {
            const float qs = 0.125f * LOG2E;
            q4.x *= qs; q4.y *= qs; q4.z *= qs; q4.w *= qs;
        }
        float2 cs = *(const float2*)&g_cos[l * 32 + 2 * j4];
        float2 sn = *(const float2*)&g_sin[l * 32 + 2 * j4];
        float oa0 = q4.x * cs.x - q4.y * sn.x;
        float oa1 = q4.z * cs.y - q4.w * sn.y;
        float ob0 = q4.x * sn.x + q4.y * cs.x;
        float ob1 = q4.z * sn.y + q4.w * cs.y;
        float ha0 = bf_hi(oa0), ha1 = bf_hi(oa1);
        float hb0 = bf_hi(ob0), hb1 = bf_hi(ob1);
        unsigned* dh = (which == 0 ? g_QHp : g_KHp) + ((size_t)h * SEQ + l) * 32;
        unsigned* dl = (which == 0 ? g_QLp : g_KLp) + ((size_t)h * SEQ + l) * 32;
        dh[j4]      = pack_bf(ha0, ha1);
        dl[j4]      = pack_bf(oa0 - ha0, oa1 - ha1);
        dh[16 + j4] = pack_bf(hb0, hb1);
        dl[16 + j4] = pack_bf(ob0 - hb0, ob1 - hb1);
    } else {
        int d4 = t & 15;
        int k = (t >> 4) & (SEQ - 1);
        int h = t >> 15;
        float4 v4 = *(const float4*)(g_V + (size_t)k * DM + h * HD + 4 * d4);
        float h0 = bf_hi(v4.x), h1 = bf_hi(v4.y);
        float h2 = bf_hi(v4.z), h3 = bf_hi(v4.w);
        size_t base = ((size_t)h * SEQ + k) * 32 + 2 * d4;
        *(uint2*)(g_VHp + base) = make_uint2(pack_bf(h0, h1), pack_bf(h2, h3));
        *(uint2*)(g_VLp + base) = make_uint2(pack_bf(v4.x - h0, v4.y - h1),
                                             pack_bf(v4.z - h2, v4.w - h3));
    }
}

// ---------------------------------------------------------------------------
// TF32 GEMM: 2-stage cp.async pipeline + ldmatrix, 3 CTAs/SM (round-14).
// ---------------------------------------------------------------------------
#define SST 36
#define GTW (128 * SST)
#define GBUFW (2 * GTW)
#define GSMEM_BYTES (2 * GBUFW * 4)   // 73728

__device__ __forceinline__ void g_issue(unsigned* buf, const float* A, const float* B,
                                        int bm, int bn, int k0) {
    int t = threadIdx.x;   // 0..127
#pragma unroll
    for (int i = 0; i < 8; i++) {
        int s = t + i * 128;
        int row = s >> 3, c4 = (s & 7) * 4;
        cp16(&buf[row * SST + c4], A + (size_t)(bm + row) * DM + k0 + c4);
        cp16(&buf[GTW + row * SST + c4], B + (size_t)(bn + row) * DM + k0 + c4);
    }
    cp_commit();
}

__device__ __forceinline__ void gemm_compute_k8(unsigned sA, unsigned sB,
                                                float acc[4][8][4], int k8,
                                                unsigned aoff, unsigned boff) {
    unsigned afr[4][4], bfr[4][4];
#pragma unroll
    for (int mi = 0; mi < 4; mi++)
        ldsm4(afr[mi], sA + aoff + (mi * 16 * SST + k8 * 8) * 4);
#pragma unroll
    for (int p = 0; p < 4; p++)
        ldsm4(bfr[p], sB + boff + (p * 16 * SST + k8 * 8) * 4);
#pragma unroll
    for (int mi = 0; mi < 4; mi++)
#pragma unroll
        for (int ni = 0; ni < 8; ni++)
            mma_tf32(acc[mi][ni], afr[mi], &bfr[ni >> 1][(ni & 1) * 2]);
}

__device__ __forceinline__ void gemm_body(float* __restrict__ C,
                                          const float* __restrict__ A,
                                          const float* __restrict__ B) {
    extern __shared__ unsigned gsm[];
    unsigned sb = (unsigned)__cvta_generic_to_shared(gsm);

    int tid = threadIdx.x;
    int lane = tid & 31, warp = tid >> 5;
    int wm = warp >> 1, wn = warp & 1;
    int bm = blockIdx.y * 128, bn = blockIdx.x * 128;

    int m8 = lane >> 3, r8 = lane & 7;
    unsigned aoff = ((wm * 64 + ((m8 & 1) << 3) + r8) * SST + ((m8 >> 1) << 2)) * 4;
    unsigned boff = ((wn * 64 + ((m8 >> 1) << 3) + r8) * SST + ((m8 & 1) << 2)) * 4;

    float acc[4][8][4];
#pragma unroll
    for (int mi = 0; mi < 4; mi++)
#pragma unroll
        for (int ni = 0; ni < 8; ni++)
#pragma unroll
            for (int j = 0; j < 4; j++) acc[mi][ni][j] = 0.0f;

    const int NKT = DM / 32;
    g_issue(gsm, A, B, bm, bn, 0);

    for (int kt = 0; kt < NKT; kt++) {
        if (kt + 1 < NKT) {
            g_issue(gsm + ((kt + 1) & 1) * GBUFW, A, B, bm, bn, (kt + 1) * 32);
            cp_wait<1>();
        } else {
            cp_wait<0>();
        }
        __syncthreads();
        unsigned sA = sb + (kt & 1) * GBUFW * 4;
        unsigned sB = sA + GTW * 4;
        gemm_compute_k8(sA, sB, acc, 0, aoff, boff);
        gemm_compute_k8(sA, sB, acc, 1, aoff, boff);
        gemm_compute_k8(sA, sB, acc, 2, aoff, boff);
        gemm_compute_k8(sA, sB, acc, 3, aoff, boff);
        __syncthreads();
    }

    {
        int gg = lane >> 2, tg2 = lane & 3;
#pragma unroll
        for (int mi = 0; mi < 4; mi++)
#pragma unroll
            for (int ni = 0; ni < 8; ni++) {
                int r0 = bm + wm * 64 + mi * 16 + gg;
                int cc = bn + wn * 64 + ni * 8 + 2 * tg2;
                *(float2*)&C[(size_t)r0 * DM + cc] =
                    make_float2(acc[mi][ni][0], acc[mi][ni][1]);
                *(float2*)&C[(size_t)(r0 + 8) * DM + cc] =
                    make_float2(acc[mi][ni][2], acc[mi][ni][3]);
            }
    }
}

__global__ void __launch_bounds__(128, 3) gemm_qkv_kernel() {
    const float* B;
    float* C;
    if (blockIdx.z == 0)      { B = g_Wqr; C = g_Q; }
    else if (blockIdx.z == 1) { B = g_Wkr; C = g_K; }
    else                      { B = g_Wvr; C = g_V; }
    gemm_body(C, g_xr, B);
}

__global__ void __launch_bounds__(128, 3) gemm_out_kernel(float* __restrict__ C) {
    gemm_body(C, g_att, g_Wor);
}

// ---------------------------------------------------------------------------
// Split-BF16 flash attention: ldmatrix + 3-stage cp.async + MUFU softmax.
// Scores arrive pre-scaled by 0.125*log2e (folded into Q), so the softmax is
// max/sub/ex2 only — no multiplies; exponentials run on the MUFU pipe.
// ---------------------------------------------------------------------------
#define BQ 128
#define BK 64
#define KWST 36
#define ABUF 9216
#define ASTAGES 3
#define AOFF_MS (ASTAGES * ABUF)            // word offset 27648
#define ASMEM_BYTES ((AOFF_MS + SEQ / 4) * 4)   // 112640
#define AO_KH 0
#define AO_KL 2304
#define AO_VH 4608
#define AO_VL 6912

__device__ __forceinline__ void attn_issue_tile(unsigned* buf, int h, int k0) {
    int t = threadIdx.x;
    const unsigned* KHs = g_KHp + ((size_t)h * SEQ + k0) * 32;
    const unsigned* KLs = g_KLp + ((size_t)h * SEQ + k0) * 32;
    const unsigned* VHs = g_VHp + ((size_t)h * SEQ + k0) * 32;
    const unsigned* VLs = g_VLp + ((size_t)h * SEQ + k0) * 32;
#pragma unroll
    for (int i = 0; i < 2; i++) {
        int s = t + i * 256;            // 0..511
        int row = s >> 3, c = (s & 7) * 4;
        cp16(&buf[AO_KH + row * KWST + c], KHs + row * 32 + c);
        cp16(&buf[AO_KL + row * KWST + c], KLs + row * 32 + c);
        cp16(&buf[AO_VH + row * KWST + c], VHs + row * 32 + c);
        cp16(&buf[AO_VL + row * KWST + c], VLs + row * 32 + c);
    }
    cp_commit();
}

__global__ void __launch_bounds__(256, 2) attn_bf16_kernel(const int* __restrict__ mask) {
    extern __shared__ unsigned smu[];
    unsigned char* MSB = (unsigned char*)(smu + AOFF_MS);
    unsigned smem_b = (unsigned)__cvta_generic_to_shared(smu);

    int tid = threadIdx.x;
    int lane = tid & 31, w = tid >> 5;
    int g = lane >> 2, tg = lane & 3;
    int m8 = lane >> 3, r8 = lane & 7;
    int h = blockIdx.y;
    int q0 = blockIdx.x * BQ;

    unsigned koff = ((((m8 >> 1) << 3) + r8) * KWST + ((m8 & 1) << 2)) * 4;
    unsigned voff = ((((m8 & 1) << 3) + r8) * KWST + ((m8 >> 1) << 2)) * 4;

    for (int i = tid; i < SEQ; i += 256) MSB[i] = (unsigned char)(mask[i] != 0);

    attn_issue_tile(smu, h, 0);
    attn_issue_tile(smu + ABUF, h, BK);

    unsigned qh[4][4], ql[4][4];
    {
        int rA = q0 + w * 16 + g, rB = rA + 8;
        const unsigned* QH = g_QHp + (size_t)h * SEQ * 32;
        const unsigned* QL = g_QLp + (size_t)h * SEQ * 32;
#pragma unroll
        for (int ks = 0; ks < 4; ks++) {
            int c = ks * 8 + tg;
            qh[ks][0] = QH[rA * 32 + c];
            qh[ks][1] = QH[rB * 32 + c];
            qh[ks][2] = QH[rA * 32 + c + 4];
            qh[ks][3] = QH[rB * 32 + c + 4];
            ql[ks][0] = QL[rA * 32 + c];
            ql[ks][1] = QL[rB * 32 + c];
            ql[ks][2] = QL[rA * 32 + c + 4];
            ql[ks][3] = QL[rB * 32 + c + 4];
        }
    }

    float o[8][4];
#pragma unroll
    for (int ni = 0; ni < 8; ni++)
#pragma unroll
        for (int j = 0; j < 4; j++) o[ni][j] = 0.0f;
    float mA = -3.0e38f, mB = -3.0e38f, lA = 0.0f, lB = 0.0f;

    const int NKT = SEQ / BK;
    for (int kt = 0; kt < NKT; kt++) {
        int k0 = kt * BK;
        if (kt + 1 < NKT) cp_wait<1>(); else cp_wait<0>();
        __syncthreads();
        if (kt + 2 < NKT)
            attn_issue_tile(smu + ((kt + 2) % ASTAGES) * ABUF, h, k0 + 2 * BK);

        unsigned tb = smem_b + ((kt % ASTAGES) * ABUF) * 4;
        unsigned sKH = tb + AO_KH * 4;
        unsigned sKL = tb + AO_KL * 4;
        unsigned sVH = tb + AO_VH * 4;
        unsigned sVL = tb + AO_VL * 4;

        // --- S = Q . K^T (already in 0.125*log2e units) ---
        float sacc[8][4];
#pragma unroll
        for (int ni = 0; ni < 8; ni++)
#pragma unroll
            for (int j = 0; j < 4; j++) sacc[ni][j] = 0.0f;

#pragma unroll
        for (int ks = 0; ks < 4; ks++) {
#pragma unroll
            for (int p = 0; p < 4; p++) {
                unsigned bh[4], bl[4];
                unsigned off = (unsigned)((p * 16 * KWST + ks * 8) * 4);
                ldsm4(bh, sKH + koff + off);
                ldsm4(bl, sKL + koff + off);
                mma_bf16(sacc[2 * p],     qh[ks], bh);
                mma_bf16(sacc[2 * p],     ql[ks], bh);
                mma_bf16(sacc[2 * p],     qh[ks], bl);
                mma_bf16(sacc[2 * p + 1], qh[ks], bh + 2);
                mma_bf16(sacc[2 * p + 1], ql[ks], bh + 2);
                mma_bf16(sacc[2 * p + 1], qh[ks], bl + 2);
            }
        }

        // --- mask (scores already scaled) ---
#pragma unroll
        for (int ni = 0; ni < 8; ni++) {
            int m0 = MSB[k0 + ni * 8 + 2 * tg];
            int m1 = MSB[k0 + ni * 8 + 2 * tg + 1];
            sacc[ni][0] = m0 ? sacc[ni][0] : MASKVAL;
            sacc[ni][1] = m1 ? sacc[ni][1] : MASKVAL;
            sacc[ni][2] = m0 ? sacc[ni][2] : MASKVAL;
            sacc[ni][3] = m1 ? sacc[ni][3] : MASKVAL;
        }

        // --- online softmax (rows g, g+8), exponentials on MUFU ---
        float mxA = -3.0e38f, mxB = -3.0e38f;
#pragma unroll
        for (int ni = 0; ni < 8; ni++) {
            mxA = fmaxf(mxA, fmaxf(sacc[ni][0], sacc[ni][1]));
            mxB = fmaxf(mxB, fmaxf(sacc[ni][2], sacc[ni][3]));
        }
        mxA = fmaxf(mxA, __shfl_xor_sync(0xffffffffu, mxA, 1));
        mxA = fmaxf(mxA, __shfl_xor_sync(0xffffffffu, mxA, 2));
        mxB = fmaxf(mxB, __shfl_xor_sync(0xffffffffu, mxB, 1));
        mxB = fmaxf(mxB, __shfl_xor_sync(0xffffffffu, mxB, 2));

        float mnA = fmaxf(mA, mxA), mnB = fmaxf(mB, mxB);
        float corrA = ex2(mA - mnA);
        float corrB = ex2(mB - mnB);

        float sumA = 0.0f, sumB = 0.0f;
#pragma unroll
        for (int ni = 0; ni < 8; ni++) {
            sacc[ni][0] = ex2(sacc[ni][0] - mnA);
            sacc[ni][1] = ex2(sacc[ni][1] - mnA);
            sacc[ni][2] = ex2(sacc[ni][2] - mnB);
            sacc[ni][3] = ex2(sacc[ni][3] - mnB);
            sumA += sacc[ni][0] + sacc[ni][1];
            sumB += sacc[ni][2] + sacc[ni][3];
        }
        sumA += __shfl_xor_sync(0xffffffffu, sumA, 1);
        sumA += __shfl_xor_sync(0xffffffffu, sumA, 2);
        sumB += __shfl_xor_sync(0xffffffffu, sumB, 1);
        sumB += __shfl_xor_sync(0xffffffffu, sumB, 2);

        lA = lA * corrA + sumA;
        lB = lB * corrB + sumB;
        mA = mnA;
        mB = mnB;
#pragma unroll
        for (int ni = 0; ni < 8; ni++) {
            o[ni][0] *= corrA; o[ni][1] *= corrA;
            o[ni][2] *= corrB; o[ni][3] *= corrB;
        }

        // --- O += P . V ---
#pragma unroll
        for (int ks = 0; ks < 4; ks++) {
            unsigned ah[4], al[4];
#pragma unroll
            for (int half = 0; half < 2; half++) {
                const float* s2 = sacc[2 * ks + half];
                float h0 = bf_hi(s2[0]), h1 = bf_hi(s2[1]);
                float h2 = bf_hi(s2[2]), h3 = bf_hi(s2[3]);
                ah[2 * half]     = pack_bf(h0, h1);
                ah[2 * half + 1] = pack_bf(h2, h3);
                al[2 * half]     = pack_bf(s2[0] - h0, s2[1] - h1);
                al[2 * half + 1] = pack_bf(s2[2] - h2, s2[3] - h3);
            }
#pragma unroll
            for (int p = 0; p < 4; p++) {
                unsigned vh[4], vl[4];
                unsigned off = (unsigned)((ks * 16 * KWST + p * 8) * 4);
                ldsm4t(vh, sVH + voff + off);
                ldsm4t(vl, sVL + voff + off);
                mma_bf16(o[2 * p],     ah, vh);
                mma_bf16(o[2 * p],     al, vh);
                mma_bf16(o[2 * p],     ah, vl);
                mma_bf16(o[2 * p + 1], ah, vh + 2);
                mma_bf16(o[2 * p + 1], al, vh + 2);
                mma_bf16(o[2 * p + 1], ah, vl + 2);
            }
        }
    }

    // normalize + store, pre-rounded to tf32 for the out-GEMM
    float invA = 1.0f / lA, invB = 1.0f / lB;
    float* Og = g_att + (size_t)(q0 + w * 16) * DM + h * HD;
#pragma unroll
    for (int ni = 0; ni < 8; ni++) {
        *(float2*)&Og[(size_t)g * DM + ni * 8 + 2 * tg] =
            make_float2(tf32r(o[ni][0] * invA), tf32r(o[ni][1] * invA));
        *(float2*)&Og[(size_t)(g + 8) * DM + ni * 8 + 2 * tg] =
            make_float2(tf32r(o[ni][2] * invB), tf32r(o[ni][3] * invB));
    }
}

// ---------------------------------------------------------------------------
// launch
// ---------------------------------------------------------------------------
extern "C" void kernel_launch(void* const* d_in, const int* in_sizes, int n_in,
                              void* d_out, int out_size) {
    const float* x    = (const float*)d_in[0];
    const int*   mask = (const int*)d_in[1];
    const float* Wq   = (const float*)d_in[2];
    const float* Wk   = (const float*)d_in[3];
    const float* Wv   = (const float*)d_in[4];
    const float* Wo   = (const float*)d_in[5];
    float* out = (float*)d_out;

    cudaFuncSetAttribute(gemm_qkv_kernel, cudaFuncAttributeMaxDynamicSharedMemorySize,
                         GSMEM_BYTES);
    cudaFuncSetAttribute(gemm_out_kernel, cudaFuncAttributeMaxDynamicSharedMemorySize,
                         GSMEM_BYTES);
    cudaFuncSetAttribute(attn_bf16_kernel, cudaFuncAttributeMaxDynamicSharedMemorySize,
                         ASMEM_BYTES);

    rope_table_kernel<<<(SEQ * 32 + 255) / 256, 256>>>();
    round_tf32_kernel<<<dim3((SEQ * DM / 4 + 255) / 256, 5), 256>>>(x, Wq, Wk, Wv, Wo);
    gemm_qkv_kernel<<<dim3(16, 16, 3), 128, GSMEM_BYTES>>>();
    preprocess_kernel<<<dim3((NH * SEQ * 16 + 255) / 256, 3), 256>>>();
    attn_bf16_kernel<<<dim3(SEQ / BQ, NH), 256, ASMEM_BYTES>>>(mask);
    gemm_out_kernel<<<dim3(16, 16), 128, GSMEM_BYTES>>>(out);
}

// round 16
// speedup vs baseline: 1.3635x; 1.0310x over previous
#include <cuda_runtime.h>
#include <cuda_bf16.h>

#define SEQ 2048
#define DM 2048
#define NH 32
#define HD 64

// Scratch (static device allocations are allowed; cudaMalloc is not)
__device__ float g_Q[SEQ * DM];
__device__ float g_K[SEQ * DM];
__device__ float g_V[SEQ * DM];
__device__ float g_att[SEQ * DM];
__device__ float g_cos[SEQ * 32];
__device__ float g_sin[SEQ * 32];

// tf32-rounded copies of the GEMM inputs (cp.async feeds mma directly).
__device__ float g_xr[SEQ * DM];
__device__ float g_Wqr[DM * DM];
__device__ float g_Wkr[DM * DM];
__device__ float g_Wvr[DM * DM];
__device__ float g_Wor[DM * DM];

// Preprocessed attention operands.
// Q: roped, pre-scaled by 0.125*log2e, tf32-rounded fp32 [h][l][64].
// K: roped, tf32-rounded fp32 [h][l][64].
// V: planar bf16 hi/lo [h][k][32 words].
__device__ float    g_Qr[NH * SEQ * 64];
__device__ float    g_Kr[NH * SEQ * 64];
__device__ unsigned g_VHp[NH * SEQ * 32];
__device__ unsigned g_VLp[NH * SEQ * 32];

#define LOG2E 1.4426950408889634f
#define MASKVAL (-1.0e9f * 1.4426950408889634f)

// ---------------------------------------------------------------------------
// helpers
// ---------------------------------------------------------------------------
__device__ __forceinline__ unsigned f2tf32(float f) {
    unsigned r;
    asm("cvt.rna.tf32.f32 %0, %1;" : "=r"(r) : "f"(f));
    return r;
}

__device__ __forceinline__ float tf32r(float f) {
    return __uint_as_float(f2tf32(f));
}

__device__ __forceinline__ void mma_tf32(float* c, const unsigned* a, const unsigned* b) {
    asm volatile(
        "mma.sync.aligned.m16n8k8.row.col.f32.tf32.tf32.f32 "
        "{%0,%1,%2,%3}, {%4,%5,%6,%7}, {%8,%9}, {%0,%1,%2,%3};"
        : "+f"(c[0]), "+f"(c[1]), "+f"(c[2]), "+f"(c[3])
        : "r"(a[0]), "r"(a[1]), "r"(a[2]), "r"(a[3]), "r"(b[0]), "r"(b[1]));
}

__device__ __forceinline__ void mma_bf16(float* c, const unsigned* a, const unsigned* b) {
    asm volatile(
        "mma.sync.aligned.m16n8k16.row.col.f32.bf16.bf16.f32 "
        "{%0,%1,%2,%3}, {%4,%5,%6,%7}, {%8,%9}, {%0,%1,%2,%3};"
        : "+f"(c[0]), "+f"(c[1]), "+f"(c[2]), "+f"(c[3])
        : "r"(a[0]), "r"(a[1]), "r"(a[2]), "r"(a[3]), "r"(b[0]), "r"(b[1]));
}

__device__ __forceinline__ void ldsm4(unsigned* r, unsigned saddr) {
    asm volatile(
        "ldmatrix.sync.aligned.m8n8.x4.shared.b16 {%0,%1,%2,%3}, [%4];"
        : "=r"(r[0]), "=r"(r[1]), "=r"(r[2]), "=r"(r[3]) : "r"(saddr));
}

__device__ __forceinline__ void ldsm4t(unsigned* r, unsigned saddr) {
    asm volatile(
        "ldmatrix.sync.aligned.m8n8.x4.trans.shared.b16 {%0,%1,%2,%3}, [%4];"
        : "=r"(r[0]), "=r"(r[1]), "=r"(r[2]), "=r"(r[3]) : "r"(saddr));
}

__device__ __forceinline__ unsigned pack_bf(float e0, float e1) {
    unsigned r;
    asm("cvt.rn.bf16x2.f32 %0, %1, %2;" : "=r"(r) : "f"(e1), "f"(e0));
    return r;
}

__device__ __forceinline__ float bf_hi(float x) {
    return __bfloat162float(__float2bfloat16(x));
}

// pack the high halves (bf16 truncation) of two fp32 into one word
__device__ __forceinline__ unsigned prmt_hi(float a, float b) {
    unsigned r;
    asm("prmt.b32 %0, %1, %2, 0x7632;"
        : "=r"(r) : "r"(__float_as_uint(a)), "r"(__float_as_uint(b)));
    return r;
}

// top-16-bit truncation of an fp32 (exact bf16 value)
__device__ __forceinline__ float trunc_hi(float x) {
    return __uint_as_float(__float_as_uint(x) & 0xFFFF0000u);
}

// MUFU exp2 (softmax exponentials on the idle MUFU pipe)
__device__ __forceinline__ float ex2(float y) {
    float r;
    asm("ex2.approx.ftz.f32 %0, %1;" : "=f"(r) : "f"(y));
    return r;
}

__device__ __forceinline__ void cp16(void* sptr, const void* gptr) {
    unsigned sa = (unsigned)__cvta_generic_to_shared(sptr);
    asm volatile("cp.async.cg.shared.global [%0], [%1], 16;" :: "r"(sa), "l"(gptr)
                 : "memory");
}
__device__ __forceinline__ void cp_commit() {
    asm volatile("cp.async.commit_group;" ::: "memory");
}
template <int N>
__device__ __forceinline__ void cp_wait() {
    asm volatile("cp.async.wait_group %0;" :: "n"(N) : "memory");
}

// ---------------------------------------------------------------------------
// RoPE cos/sin table
// ---------------------------------------------------------------------------
__global__ void rope_table_kernel() {
    int idx = blockIdx.x * blockDim.x + threadIdx.x;
    if (idx >= SEQ * 32) return;
    int l = idx >> 5;
    int j = idx & 31;
    float invf = powf(10000.0f, -(float)j * (1.0f / 32.0f));
    float fr = (float)l * invf;
    g_cos[idx] = cosf(fr);
    g_sin[idx] = sinf(fr);
}

// ---------------------------------------------------------------------------
// RNA-round the five GEMM input matrices to tf32
// ---------------------------------------------------------------------------
__global__ void __launch_bounds__(256) round_tf32_kernel(
    const float* __restrict__ x,  const float* __restrict__ Wq,
    const float* __restrict__ Wk, const float* __restrict__ Wv,
    const float* __restrict__ Wo) {
    int idx = blockIdx.x * blockDim.x + threadIdx.x;
    if (idx >= (SEQ * DM) / 4) return;
    const float* src;
    float* dst;
    switch (blockIdx.y) {
        case 0:  src = x;  dst = g_xr;  break;
        case 1:  src = Wq; dst = g_Wqr; break;
        case 2:  src = Wk; dst = g_Wkr; break;
        case 3:  src = Wv; dst = g_Wvr; break;
        default: src = Wo; dst = g_Wor; break;
    }
    float4 v = ((const float4*)src)[idx];
    v.x = tf32r(v.x); v.y = tf32r(v.y); v.z = tf32r(v.z); v.w = tf32r(v.w);
    ((float4*)dst)[idx] = v;
}

// ---------------------------------------------------------------------------
// Preprocess — one thread per float4.
// y=0: Q -> rope, *0.125*log2e, tf32-round -> fp32 [h][l][64]
// y=1: K -> rope, tf32-round -> fp32 [h][l][64]
// y=2: V -> split bf16 planar [h][k][32 words]
// ---------------------------------------------------------------------------
__global__ void __launch_bounds__(256) preprocess_kernel() {
    int t = blockIdx.x * blockDim.x + threadIdx.x;
    int which = blockIdx.y;
    if (t >= NH * SEQ * 16) return;
    if (which < 2) {
        int j4 = t & 15;
        int l = (t >> 4) & (SEQ - 1);
        int h = t >> 15;
        const float* src = (which == 0 ? g_Q : g_K) + (size_t)l * DM + h * HD + 4 * j4;
        float4 q4 = *(const float4*)src;
        if (which == 0) {
            const float qs = 0.125f * LOG2E;
            q4.x *= qs; q4.y *= qs; q4.z *= qs; q4.w *= qs;
        }
        float2 cs = *(const float2*)&g_cos[l * 32 + 2 * j4];
        float2 sn = *(const float2*)&g_sin[l * 32 + 2 * j4];
        float oa0 = q4.x * cs.x - q4.y * sn.x;
        float oa1 = q4.z * cs.y - q4.w * sn.y;
        float ob0 = q4.x * sn.x + q4.y * cs.x;
        float ob1 = q4.z * sn.y + q4.w * cs.y;
        float* dst = (which == 0 ? g_Qr : g_Kr) + ((size_t)h * SEQ + l) * 64;
        *(float2*)&dst[2 * j4]      = make_float2(tf32r(oa0), tf32r(oa1));
        *(float2*)&dst[32 + 2 * j4] = make_float2(tf32r(ob0), tf32r(ob1));
    } else {
        int d4 = t & 15;
        int k = (t >> 4) & (SEQ - 1);
        int h = t >> 15;
        float4 v4 = *(const float4*)(g_V + (size_t)k * DM + h * HD + 4 * d4);
        float h0 = bf_hi(v4.x), h1 = bf_hi(v4.y);
        float h2 = bf_hi(v4.z), h3 = bf_hi(v4.w);
        size_t base = ((size_t)h * SEQ + k) * 32 + 2 * d4;
        *(uint2*)(g_VHp + base) = make_uint2(pack_bf(h0, h1), pack_bf(h2, h3));
        *(uint2*)(g_VLp + base) = make_uint2(pack_bf(v4.x - h0, v4.y - h1),
                                             pack_bf(v4.z - h2, v4.w - h3));
    }
}

// ---------------------------------------------------------------------------
// TF32 GEMM: 2-stage cp.async pipeline + ldmatrix, 3 CTAs/SM (round-14/15).
// ---------------------------------------------------------------------------
#define SST 36
#define GTW (128 * SST)
#define GBUFW (2 * GTW)
#define GSMEM_BYTES (2 * GBUFW * 4)   // 73728

__device__ __forceinline__ void g_issue(unsigned* buf, const float* A, const float* B,
                                        int bm, int bn, int k0) {
    int t = threadIdx.x;   // 0..127
#pragma unroll
    for (int i = 0; i < 8; i++) {
        int s = t + i * 128;
        int row = s >> 3, c4 = (s & 7) * 4;
        cp16(&buf[row * SST + c4], A + (size_t)(bm + row) * DM + k0 + c4);
        cp16(&buf[GTW + row * SST + c4], B + (size_t)(bn + row) * DM + k0 + c4);
    }
    cp_commit();
}

__device__ __forceinline__ void gemm_compute_k8(unsigned sA, unsigned sB,
                                                float acc[4][8][4], int k8,
                                                unsigned aoff, unsigned boff) {
    unsigned afr[4][4], bfr[4][4];
#pragma unroll
    for (int mi = 0; mi < 4; mi++)
        ldsm4(afr[mi], sA + aoff + (mi * 16 * SST + k8 * 8) * 4);
#pragma unroll
    for (int p = 0; p < 4; p++)
        ldsm4(bfr[p], sB + boff + (p * 16 * SST + k8 * 8) * 4);
#pragma unroll
    for (int mi = 0; mi < 4; mi++)
#pragma unroll
        for (int ni = 0; ni < 8; ni++)
            mma_tf32(acc[mi][ni], afr[mi], &bfr[ni >> 1][(ni & 1) * 2]);
}

__device__ __forceinline__ void gemm_body(float* __restrict__ C,
                                          const float* __restrict__ A,
                                          const float* __restrict__ B) {
    extern __shared__ unsigned gsm[];
    unsigned sb = (unsigned)__cvta_generic_to_shared(gsm);

    int tid = threadIdx.x;
    int lane = tid & 31, warp = tid >> 5;
    int wm = warp >> 1, wn = warp & 1;
    int bm = blockIdx.y * 128, bn = blockIdx.x * 128;

    int m8 = lane >> 3, r8 = lane & 7;
    unsigned aoff = ((wm * 64 + ((m8 & 1) << 3) + r8) * SST + ((m8 >> 1) << 2)) * 4;
    unsigned boff = ((wn * 64 + ((m8 >> 1) << 3) + r8) * SST + ((m8 & 1) << 2)) * 4;

    float acc[4][8][4];
#pragma unroll
    for (int mi = 0; mi < 4; mi++)
#pragma unroll
        for (int ni = 0; ni < 8; ni++)
#pragma unroll
            for (int j = 0; j < 4; j++) acc[mi][ni][j] = 0.0f;

    const int NKT = DM / 32;
    g_issue(gsm, A, B, bm, bn, 0);

    for (int kt = 0; kt < NKT; kt++) {
        if (kt + 1 < NKT) {
            g_issue(gsm + ((kt + 1) & 1) * GBUFW, A, B, bm, bn, (kt + 1) * 32);
            cp_wait<1>();
        } else {
            cp_wait<0>();
        }
        __syncthreads();
        unsigned sA = sb + (kt & 1) * GBUFW * 4;
        unsigned sB = sA + GTW * 4;
        gemm_compute_k8(sA, sB, acc, 0, aoff, boff);
        gemm_compute_k8(sA, sB, acc, 1, aoff, boff);
        gemm_compute_k8(sA, sB, acc, 2, aoff, boff);
        gemm_compute_k8(sA, sB, acc, 3, aoff, boff);
        __syncthreads();
    }

    {
        int gg = lane >> 2, tg2 = lane & 3;
#pragma unroll
        for (int mi = 0; mi < 4; mi++)
#pragma unroll
            for (int ni = 0; ni < 8; ni++) {
                int r0 = bm + wm * 64 + mi * 16 + gg;
                int cc = bn + wn * 64 + ni * 8 + 2 * tg2;
                *(float2*)&C[(size_t)r0 * DM + cc] =
                    make_float2(acc[mi][ni][0], acc[mi][ni][1]);
                *(float2*)&C[(size_t)(r0 + 8) * DM + cc] =
                    make_float2(acc[mi][ni][2], acc[mi][ni][3]);
            }
    }
}

__global__ void __launch_bounds__(128, 3) gemm_qkv_kernel() {
    const float* B;
    float* C;
    if (blockIdx.z == 0)      { B = g_Wqr; C = g_Q; }
    else if (blockIdx.z == 1) { B = g_Wkr; C = g_K; }
    else                      { B = g_Wvr; C = g_V; }
    gemm_body(C, g_xr, B);
}

__global__ void __launch_bounds__(128, 3) gemm_out_kernel(float* __restrict__ C) {
    gemm_body(C, g_att, g_Wor);
}

// ---------------------------------------------------------------------------
// Flash attention: S in single tf32 (GEMM-proven path), PV in split-bf16.
// K tiles fp32 [key][dim] stride 76 (16B-aligned rows, conflict-free ldsm).
// V tiles planar bf16 hi/lo stride 36, trans-ldsm. 3-stage cp.async,
// one sync/tile, MUFU softmax, PRMT truncation-split for the PV A-frag.
// ---------------------------------------------------------------------------
#define BQ 128
#define BK 64
#define KST 76
#define VST 36
#define AO_K  0
#define AO_VH 4864
#define AO_VL 7168
#define ABUF  9472
#define ASTAGES 3
#define AOFF_MS (ASTAGES * ABUF)                 // 28416 words
#define ASMEM_BYTES ((AOFF_MS + SEQ / 4) * 4)    // 115712

__device__ __forceinline__ void attn_issue_tile(unsigned* buf, int h, int k0) {
    int t = threadIdx.x;
    const float*    Ks  = g_Kr  + ((size_t)h * SEQ + k0) * 64;
    const unsigned* VHs = g_VHp + ((size_t)h * SEQ + k0) * 32;
    const unsigned* VLs = g_VLp + ((size_t)h * SEQ + k0) * 32;
#pragma unroll
    for (int i = 0; i < 4; i++) {
        int s = t + i * 256;            // 0..1023
        int row = s >> 4, c4 = (s & 15) * 4;
        cp16(&buf[AO_K + row * KST + c4], Ks + row * 64 + c4);
    }
#pragma unroll
    for (int i = 0; i < 2; i++) {
        int s = t + i * 256;            // 0..511
        int row = s >> 3, c = (s & 7) * 4;
        cp16(&buf[AO_VH + row * VST + c], VHs + row * 32 + c);
        cp16(&buf[AO_VL + row * VST + c], VLs + row * 32 + c);
    }
    cp_commit();
}

__global__ void __launch_bounds__(256, 2) attn_kernel(const int* __restrict__ mask) {
    extern __shared__ unsigned smu[];
    unsigned char* MSB = (unsigned char*)(smu + AOFF_MS);
    unsigned smem_b = (unsigned)__cvta_generic_to_shared(smu);

    int tid = threadIdx.x;
    int lane = tid & 31, w = tid >> 5;
    int g = lane >> 2, tg = lane & 3;
    int m8 = lane >> 3, r8 = lane & 7;
    int h = blockIdx.y;
    int q0 = blockIdx.x * BQ;

    // ldmatrix per-lane byte offsets
    unsigned koff = ((((m8 >> 1) << 3) + r8) * KST + ((m8 & 1) << 2)) * 4;
    unsigned voff = ((((m8 & 1) << 3) + r8) * VST + ((m8 >> 1) << 2)) * 4;

    for (int i = tid; i < SEQ; i += 256) MSB[i] = (unsigned char)(mask[i] != 0);

    attn_issue_tile(smu, h, 0);
    attn_issue_tile(smu + ABUF, h, BK);

    // Q a-fragments (tf32 bit patterns) straight from global
    unsigned qa[8][4];
    {
        const unsigned* Qu = (const unsigned*)(g_Qr + (size_t)h * SEQ * 64);
        int rA = q0 + w * 16 + g, rB = rA + 8;
#pragma unroll
        for (int ks = 0; ks < 8; ks++) {
            int c = ks * 8 + tg;
            qa[ks][0] = Qu[rA * 64 + c];
            qa[ks][1] = Qu[rB * 64 + c];
            qa[ks][2] = Qu[rA * 64 + c + 4];
            qa[ks][3] = Qu[rB * 64 + c + 4];
        }
    }

    float o[8][4];
#pragma unroll
    for (int ni = 0; ni < 8; ni++)
#pragma unroll
        for (int j = 0; j < 4; j++) o[ni][j] = 0.0f;
    float mA = -3.0e38f, mB = -3.0e38f, lA = 0.0f, lB = 0.0f;

    const int NKT = SEQ / BK;
    for (int kt = 0; kt < NKT; kt++) {
        int k0 = kt * BK;
        if (kt + 1 < NKT) cp_wait<1>(); else cp_wait<0>();
        __syncthreads();
        if (kt + 2 < NKT)
            attn_issue_tile(smu + ((kt + 2) % ASTAGES) * ABUF, h, k0 + 2 * BK);

        unsigned tb = smem_b + ((kt % ASTAGES) * ABUF) * 4;
        unsigned sK  = tb + AO_K * 4;
        unsigned sVH = tb + AO_VH * 4;
        unsigned sVL = tb + AO_VL * 4;

        // --- S = Q . K^T (single tf32; scores in 0.125*log2e units) ---
        float sacc[8][4];
#pragma unroll
        for (int ni = 0; ni < 8; ni++)
#pragma unroll
            for (int j = 0; j < 4; j++) sacc[ni][j] = 0.0f;

#pragma unroll
        for (int ks = 0; ks < 8; ks++) {
#pragma unroll
            for (int p = 0; p < 4; p++) {
                unsigned bf[4];
                ldsm4(bf, sK + koff + (unsigned)((p * 16 * KST + ks * 8) * 4));
                mma_tf32(sacc[2 * p],     qa[ks], bf);
                mma_tf32(sacc[2 * p + 1], qa[ks], bf + 2);
            }
        }

        // --- mask ---
#pragma unroll
        for (int ni = 0; ni < 8; ni++) {
            int m0 = MSB[k0 + ni * 8 + 2 * tg];
            int m1 = MSB[k0 + ni * 8 + 2 * tg + 1];
            sacc[ni][0] = m0 ? sacc[ni][0] : MASKVAL;
            sacc[ni][1] = m1 ? sacc[ni][1] : MASKVAL;
            sacc[ni][2] = m0 ? sacc[ni][2] : MASKVAL;
            sacc[ni][3] = m1 ? sacc[ni][3] : MASKVAL;
        }

        // --- online softmax (rows g, g+8), exponentials on MUFU ---
        float mxA = -3.0e38f, mxB = -3.0e38f;
#pragma unroll
        for (int ni = 0; ni < 8; ni++) {
            mxA = fmaxf(mxA, fmaxf(sacc[ni][0], sacc[ni][1]));
            mxB = fmaxf(mxB, fmaxf(sacc[ni][2], sacc[ni][3]));
        }
        mxA = fmaxf(mxA, __shfl_xor_sync(0xffffffffu, mxA, 1));
        mxA = fmaxf(mxA, __shfl_xor_sync(0xffffffffu, mxA, 2));
        mxB = fmaxf(mxB, __shfl_xor_sync(0xffffffffu, mxB, 1));
        mxB = fmaxf(mxB, __shfl_xor_sync(0xffffffffu, mxB, 2));

        float mnA = fmaxf(mA, mxA), mnB = fmaxf(mB, mxB);
        float corrA = ex2(mA - mnA);
        float corrB = ex2(mB - mnB);

        float sumA = 0.0f, sumB = 0.0f;
#pragma unroll
        for (int ni = 0; ni < 8; ni++) {
            sacc[ni][0] = ex2(sacc[ni][0] - mnA);
            sacc[ni][1] = ex2(sacc[ni][1] - mnA);
            sacc[ni][2] = ex2(sacc[ni][2] - mnB);
            sacc[ni][3] = ex2(sacc[ni][3] - mnB);
            sumA += sacc[ni][0] + sacc[ni][1];
            sumB += sacc[ni][2] + sacc[ni][3];
        }
        sumA += __shfl_xor_sync(0xffffffffu, sumA, 1);
        sumA += __shfl_xor_sync(0xffffffffu, sumA, 2);
        sumB += __shfl_xor_sync(0xffffffffu, sumB, 1);
        sumB += __shfl_xor_sync(0xffffffffu, sumB, 2);

        lA = lA * corrA + sumA;
        lB = lB * corrB + sumB;
        mA = mnA;
        mB = mnB;
#pragma unroll
        for (int ni = 0; ni < 8; ni++) {
            o[ni][0] *= corrA; o[ni][1] *= corrA;
            o[ni][2] *= corrB; o[ni][3] *= corrB;
        }

        // --- O += P . V (PRMT truncation-split A-frag; V split via trans-ldsm) ---
#pragma unroll
        for (int ks = 0; ks < 4; ks++) {
            unsigned ah[4], al[4];
#pragma unroll
            for (int half = 0; half < 2; half++) {
                const float* s2 = sacc[2 * ks + half];
                float l0 = s2[0] - trunc_hi(s2[0]);
                float l1 = s2[1] - trunc_hi(s2[1]);
                float l2 = s2[2] - trunc_hi(s2[2]);
                float l3 = s2[3] - trunc_hi(s2[3]);
                ah[2 * half]     = prmt_hi(s2[0], s2[1]);
                ah[2 * half + 1] = prmt_hi(s2[2], s2[3]);
                al[2 * half]     = prmt_hi(l0, l1);
                al[2 * half + 1] = prmt_hi(l2, l3);
            }
#pragma unroll
            for (int p = 0; p < 4; p++) {
                unsigned vh[4], vl[4];
                unsigned off = (unsigned)((ks * 16 * VST + p * 8) * 4);
                ldsm4t(vh, sVH + voff + off);
                ldsm4t(vl, sVL + voff + off);
                mma_bf16(o[2 * p],     ah, vh);
                mma_bf16(o[2 * p],     al, vh);
                mma_bf16(o[2 * p],     ah, vl);
                mma_bf16(o[2 * p + 1], ah, vh + 2);
                mma_bf16(o[2 * p + 1], al, vh + 2);
                mma_bf16(o[2 * p + 1], ah, vl + 2);
            }
        }
    }

    // normalize + store, pre-rounded to tf32 for the out-GEMM
    float invA = 1.0f / lA, invB = 1.0f / lB;
    float* Og = g_att + (size_t)(q0 + w * 16) * DM + h * HD;
#pragma unroll
    for (int ni = 0; ni < 8; ni++) {
        *(float2*)&Og[(size_t)g * DM + ni * 8 + 2 * tg] =
            make_float2(tf32r(o[ni][0] * invA), tf32r(o[ni][1] * invA));
        *(float2*)&Og[(size_t)(g + 8) * DM + ni * 8 + 2 * tg] =
            make_float2(tf32r(o[ni][2] * invB), tf32r(o[ni][3] * invB));
    }
}

// ---------------------------------------------------------------------------
// launch
// ---------------------------------------------------------------------------
extern "C" void kernel_launch(void* const* d_in, const int* in_sizes, int n_in,
                              void* d_out, int out_size) {
    const float* x    = (const float*)d_in[0];
    const int*   mask = (const int*)d_in[1];
    const float* Wq   = (const float*)d_in[2];
    const float* Wk   = (const float*)d_in[3];
    const float* Wv   = (const float*)d_in[4];
    const float* Wo   = (const float*)d_in[5];
    float* out = (float*)d_out;

    cudaFuncSetAttribute(gemm_qkv_kernel, cudaFuncAttributeMaxDynamicSharedMemorySize,
                         GSMEM_BYTES);
    cudaFuncSetAttribute(gemm_out_kernel, cudaFuncAttributeMaxDynamicSharedMemorySize,
                         GSMEM_BYTES);
    cudaFuncSetAttribute(attn_kernel, cudaFuncAttributeMaxDynamicSharedMemorySize,
                         ASMEM_BYTES);

    rope_table_kernel<<<(SEQ * 32 + 255) / 256, 256>>>();
    round_tf32_kernel<<<dim3((SEQ * DM / 4 + 255) / 256, 5), 256>>>(x, Wq, Wk, Wv, Wo);
    gemm_qkv_kernel<<<dim3(16, 16, 3), 128, GSMEM_BYTES>>>();
    preprocess_kernel<<<dim3((NH * SEQ * 16 + 255) / 256, 3), 256>>>();
    attn_kernel<<<dim3(SEQ / BQ, NH), 256, ASMEM_BYTES>>>(mask);
    gemm_out_kernel<<<dim3(16, 16), 128, GSMEM_BYTES>>>(out);
}

// round 17
// speedup vs baseline: 1.3960x; 1.0239x over previous
#include <cuda_runtime.h>
#include <cuda_bf16.h>

#define SEQ 2048
#define DM 2048
#define NH 32
#define HD 64

// Scratch (static device allocations are allowed; cudaMalloc is not)
__device__ float g_att[SEQ * DM];
__device__ float2 g_cs[SEQ * 32];   // (cos, sin) per (position, pair)

// tf32-rounded copies of the GEMM inputs (cp.async feeds mma directly).
__device__ float g_xr[SEQ * DM];
__device__ float g_Wqr[DM * DM];
__device__ float g_Wkr[DM * DM];
__device__ float g_Wvr[DM * DM];
__device__ float g_Wor[DM * DM];

// Preprocessed attention operands (written by the QKV GEMM epilogue).
// Q/K: roped (PERMUTED dim layout: rotated pair stored back at (2p,2p+1)),
//      Q pre-scaled by 0.125*log2e, tf32-rounded fp32 [h][l][64].
// V: planar bf16 hi/lo [h][k][32 words] (natural dim order).
__device__ float    g_Qr[NH * SEQ * 64];
__device__ float    g_Kr[NH * SEQ * 64];
__device__ unsigned g_VHp[NH * SEQ * 32];
__device__ unsigned g_VLp[NH * SEQ * 32];

#define LOG2E 1.4426950408889634f
#define MASKVAL (-1.0e9f * 1.4426950408889634f)

// ---------------------------------------------------------------------------
// helpers
// ---------------------------------------------------------------------------
__device__ __forceinline__ unsigned f2tf32(float f) {
    unsigned r;
    asm("cvt.rna.tf32.f32 %0, %1;" : "=r"(r) : "f"(f));
    return r;
}

__device__ __forceinline__ float tf32r(float f) {
    return __uint_as_float(f2tf32(f));
}

__device__ __forceinline__ void mma_tf32(float* c, const unsigned* a, const unsigned* b) {
    asm volatile(
        "mma.sync.aligned.m16n8k8.row.col.f32.tf32.tf32.f32 "
        "{%0,%1,%2,%3}, {%4,%5,%6,%7}, {%8,%9}, {%0,%1,%2,%3};"
        : "+f"(c[0]), "+f"(c[1]), "+f"(c[2]), "+f"(c[3])
        : "r"(a[0]), "r"(a[1]), "r"(a[2]), "r"(a[3]), "r"(b[0]), "r"(b[1]));
}

__device__ __forceinline__ void mma_bf16(float* c, const unsigned* a, const unsigned* b) {
    asm volatile(
        "mma.sync.aligned.m16n8k16.row.col.f32.bf16.bf16.f32 "
        "{%0,%1,%2,%3}, {%4,%5,%6,%7}, {%8,%9}, {%0,%1,%2,%3};"
        : "+f"(c[0]), "+f"(c[1]), "+f"(c[2]), "+f"(c[3])
        : "r"(a[0]), "r"(a[1]), "r"(a[2]), "r"(a[3]), "r"(b[0]), "r"(b[1]));
}

__device__ __forceinline__ void ldsm4(unsigned* r, unsigned saddr) {
    asm volatile(
        "ldmatrix.sync.aligned.m8n8.x4.shared.b16 {%0,%1,%2,%3}, [%4];"
        : "=r"(r[0]), "=r"(r[1]), "=r"(r[2]), "=r"(r[3]) : "r"(saddr));
}

__device__ __forceinline__ void ldsm4t(unsigned* r, unsigned saddr) {
    asm volatile(
        "ldmatrix.sync.aligned.m8n8.x4.trans.shared.b16 {%0,%1,%2,%3}, [%4];"
        : "=r"(r[0]), "=r"(r[1]), "=r"(r[2]), "=r"(r[3]) : "r"(saddr));
}

__device__ __forceinline__ unsigned pack_bf(float e0, float e1) {
    unsigned r;
    asm("cvt.rn.bf16x2.f32 %0, %1, %2;" : "=r"(r) : "f"(e1), "f"(e0));
    return r;
}

__device__ __forceinline__ float bf_hi(float x) {
    return __bfloat162float(__float2bfloat16(x));
}

// pack the high halves (bf16 truncation) of two fp32 into one word
__device__ __forceinline__ unsigned prmt_hi(float a, float b) {
    unsigned r;
    asm("prmt.b32 %0, %1, %2, 0x7632;"
        : "=r"(r) : "r"(__float_as_uint(a)), "r"(__float_as_uint(b)));
    return r;
}

// top-16-bit truncation of an fp32 (exact bf16 value)
__device__ __forceinline__ float trunc_hi(float x) {
    return __uint_as_float(__float_as_uint(x) & 0xFFFF0000u);
}

// MUFU exp2
__device__ __forceinline__ float ex2(float y) {
    float r;
    asm("ex2.approx.ftz.f32 %0, %1;" : "=f"(r) : "f"(y));
    return r;
}

__device__ __forceinline__ void cp16(void* sptr, const void* gptr) {
    unsigned sa = (unsigned)__cvta_generic_to_shared(sptr);
    asm volatile("cp.async.cg.shared.global [%0], [%1], 16;" :: "r"(sa), "l"(gptr)
                 : "memory");
}
__device__ __forceinline__ void cp_commit() {
    asm volatile("cp.async.commit_group;" ::: "memory");
}
template <int N>
__device__ __forceinline__ void cp_wait() {
    asm volatile("cp.async.wait_group %0;" :: "n"(N) : "memory");
}

// ---------------------------------------------------------------------------
// RoPE cos/sin table (packed float2)
// ---------------------------------------------------------------------------
__global__ void rope_table_kernel() {
    int idx = blockIdx.x * blockDim.x + threadIdx.x;
    if (idx >= SEQ * 32) return;
    int l = idx >> 5;
    int j = idx & 31;
    float invf = powf(10000.0f, -(float)j * (1.0f / 32.0f));
    float fr = (float)l * invf;
    g_cs[idx] = make_float2(cosf(fr), sinf(fr));
}

// ---------------------------------------------------------------------------
// RNA-round the five GEMM input matrices to tf32
// ---------------------------------------------------------------------------
__global__ void __launch_bounds__(256) round_tf32_kernel(
    const float* __restrict__ x,  const float* __restrict__ Wq,
    const float* __restrict__ Wk, const float* __restrict__ Wv,
    const float* __restrict__ Wo) {
    int idx = blockIdx.x * blockDim.x + threadIdx.x;
    if (idx >= (SEQ * DM) / 4) return;
    const float* src;
    float* dst;
    switch (blockIdx.y) {
        case 0:  src = x;  dst = g_xr;  break;
        case 1:  src = Wq; dst = g_Wqr; break;
        case 2:  src = Wk; dst = g_Wkr; break;
        case 3:  src = Wv; dst = g_Wvr; break;
        default: src = Wo; dst = g_Wor; break;
    }
    float4 v = ((const float4*)src)[idx];
    v.x = tf32r(v.x); v.y = tf32r(v.y); v.z = tf32r(v.z); v.w = tf32r(v.w);
    ((float4*)dst)[idx] = v;
}

// ---------------------------------------------------------------------------
// TF32 GEMM: 2-stage cp.async pipeline + ldmatrix, 3 CTAs/SM.
// MODE 0: plain C write (out-GEMM).
// MODE 1: Q epilogue — scale by 0.125*log2e, rope (permuted layout), tf32,
//         write g_Qr.   MODE 2: K likewise (no scale) -> g_Kr.
// MODE 3: V epilogue — bf16 hi/lo split -> g_VHp/g_VLp.
// Epilogue thread holds column pair (2p, 2p+1) of each row: rope rotates the
// pair in place (dim-permuted layout; Q and K share it, so S is unchanged).
// ---------------------------------------------------------------------------
#define SST 36
#define GTW (128 * SST)
#define GBUFW (2 * GTW)
#define GSMEM_BYTES (2 * GBUFW * 4)   // 73728

__device__ __forceinline__ void g_issue(unsigned* buf, const float* A, const float* B,
                                        int bm, int bn, int k0) {
    int t = threadIdx.x;   // 0..127
#pragma unroll
    for (int i = 0; i < 8; i++) {
        int s = t + i * 128;
        int row = s >> 3, c4 = (s & 7) * 4;
        cp16(&buf[row * SST + c4], A + (size_t)(bm + row) * DM + k0 + c4);
        cp16(&buf[GTW + row * SST + c4], B + (size_t)(bn + row) * DM + k0 + c4);
    }
    cp_commit();
}

__device__ __forceinline__ void gemm_compute_k8(unsigned sA, unsigned sB,
                                                float acc[4][8][4], int k8,
                                                unsigned aoff, unsigned boff) {
    unsigned afr[4][4], bfr[4][4];
#pragma unroll
    for (int mi = 0; mi < 4; mi++)
        ldsm4(afr[mi], sA + aoff + (mi * 16 * SST + k8 * 8) * 4);
#pragma unroll
    for (int p = 0; p < 4; p++)
        ldsm4(bfr[p], sB + boff + (p * 16 * SST + k8 * 8) * 4);
#pragma unroll
    for (int mi = 0; mi < 4; mi++)
#pragma unroll
        for (int ni = 0; ni < 8; ni++)
            mma_tf32(acc[mi][ni], afr[mi], &bfr[ni >> 1][(ni & 1) * 2]);
}

template <int MODE>
__device__ __forceinline__ void gemm_body(float* __restrict__ C,
                                          const float* __restrict__ A,
                                          const float* __restrict__ B) {
    extern __shared__ unsigned gsm[];
    unsigned sb = (unsigned)__cvta_generic_to_shared(gsm);

    int tid = threadIdx.x;
    int lane = tid & 31, warp = tid >> 5;
    int wm = warp >> 1, wn = warp & 1;
    int bm = blockIdx.y * 128, bn = blockIdx.x * 128;

    int m8 = lane >> 3, r8 = lane & 7;
    unsigned aoff = ((wm * 64 + ((m8 & 1) << 3) + r8) * SST + ((m8 >> 1) << 2)) * 4;
    unsigned boff = ((wn * 64 + ((m8 >> 1) << 3) + r8) * SST + ((m8 & 1) << 2)) * 4;

    float acc[4][8][4];
#pragma unroll
    for (int mi = 0; mi < 4; mi++)
#pragma unroll
        for (int ni = 0; ni < 8; ni++)
#pragma unroll
            for (int j = 0; j < 4; j++) acc[mi][ni][j] = 0.0f;

    const int NKT = DM / 32;
    g_issue(gsm, A, B, bm, bn, 0);

    for (int kt = 0; kt < NKT; kt++) {
        if (kt + 1 < NKT) {
            g_issue(gsm + ((kt + 1) & 1) * GBUFW, A, B, bm, bn, (kt + 1) * 32);
            cp_wait<1>();
        } else {
            cp_wait<0>();
        }
        __syncthreads();
        unsigned sA = sb + (kt & 1) * GBUFW * 4;
        unsigned sB = sA + GTW * 4;
        gemm_compute_k8(sA, sB, acc, 0, aoff, boff);
        gemm_compute_k8(sA, sB, acc, 1, aoff, boff);
        gemm_compute_k8(sA, sB, acc, 2, aoff, boff);
        gemm_compute_k8(sA, sB, acc, 3, aoff, boff);
        __syncthreads();
    }

    int gg = lane >> 2, tg2 = lane & 3;
    if (MODE == 0) {
#pragma unroll
        for (int mi = 0; mi < 4; mi++)
#pragma unroll
            for (int ni = 0; ni < 8; ni++) {
                int r0 = bm + wm * 64 + mi * 16 + gg;
                int cc = bn + wn * 64 + ni * 8 + 2 * tg2;
                *(float2*)&C[(size_t)r0 * DM + cc] =
                    make_float2(acc[mi][ni][0], acc[mi][ni][1]);
                *(float2*)&C[(size_t)(r0 + 8) * DM + cc] =
                    make_float2(acc[mi][ni][2], acc[mi][ni][3]);
            }
    } else if (MODE <= 2) {
        // rope epilogue (permuted layout): pair (2p,2p+1) rotated in place
        int head = (bn >> 6) + wn;
        float* dst = (MODE == 1 ? g_Qr : g_Kr) + (size_t)head * SEQ * 64;
        const float qs = 0.125f * LOG2E;
#pragma unroll
        for (int mi = 0; mi < 4; mi++)
#pragma unroll
            for (int ni = 0; ni < 8; ni++) {
                int r0 = bm + wm * 64 + mi * 16 + gg;
                int c = ni * 8 + 2 * tg2;          // even, within head
                int p = c >> 1;
                float2 cs0 = g_cs[r0 * 32 + p];
                float2 cs1 = g_cs[(r0 + 8) * 32 + p];
                float x0 = acc[mi][ni][0], x1 = acc[mi][ni][1];
                float y0 = acc[mi][ni][2], y1 = acc[mi][ni][3];
                if (MODE == 1) { x0 *= qs; x1 *= qs; y0 *= qs; y1 *= qs; }
                float oa0 = x0 * cs0.x - x1 * cs0.y;
                float ob0 = x0 * cs0.y + x1 * cs0.x;
                float oa1 = y0 * cs1.x - y1 * cs1.y;
                float ob1 = y0 * cs1.y + y1 * cs1.x;
                *(float2*)&dst[(size_t)r0 * 64 + c] =
                    make_float2(tf32r(oa0), tf32r(ob0));
                *(float2*)&dst[(size_t)(r0 + 8) * 64 + c] =
                    make_float2(tf32r(oa1), tf32r(ob1));
            }
    } else {
        // V epilogue: bf16 hi/lo split, word w packs dims (2w, 2w+1)
        int head = (bn >> 6) + wn;
        unsigned* dh = g_VHp + (size_t)head * SEQ * 32;
        unsigned* dl = g_VLp + (size_t)head * SEQ * 32;
#pragma unroll
        for (int mi = 0; mi < 4; mi++)
#pragma unroll
            for (int ni = 0; ni < 8; ni++) {
                int r0 = bm + wm * 64 + mi * 16 + gg;
                int wd = ni * 4 + tg2;
                float a0 = acc[mi][ni][0], a1 = acc[mi][ni][1];
                float b0 = acc[mi][ni][2], b1 = acc[mi][ni][3];
                float h0 = bf_hi(a0), h1 = bf_hi(a1);
                float h2 = bf_hi(b0), h3 = bf_hi(b1);
                dh[(size_t)r0 * 32 + wd]       = pack_bf(h0, h1);
                dl[(size_t)r0 * 32 + wd]       = pack_bf(a0 - h0, a1 - h1);
                dh[(size_t)(r0 + 8) * 32 + wd] = pack_bf(h2, h3);
                dl[(size_t)(r0 + 8) * 32 + wd] = pack_bf(b0 - h2, b1 - h3);
            }
    }
}

__global__ void __launch_bounds__(128, 3) gemm_qkv_kernel() {
    if (blockIdx.z == 0)      gemm_body<1>(nullptr, g_xr, g_Wqr);
    else if (blockIdx.z == 1) gemm_body<2>(nullptr, g_xr, g_Wkr);
    else                      gemm_body<3>(nullptr, g_xr, g_Wvr);
}

__global__ void __launch_bounds__(128, 3) gemm_out_kernel(float* __restrict__ C) {
    gemm_body<0>(C, g_att, g_Wor);
}

// ---------------------------------------------------------------------------
// Flash attention (round-16 version): S single tf32, PV split-bf16,
// 3-stage cp.async, one sync/tile, MUFU softmax, PRMT split.
// ---------------------------------------------------------------------------
#define BQ 128
#define BK 64
#define KST 76
#define VST 36
#define AO_K  0
#define AO_VH 4864
#define AO_VL 7168
#define ABUF  9472
#define ASTAGES 3
#define AOFF_MS (ASTAGES * ABUF)                 // 28416 words
#define ASMEM_BYTES ((AOFF_MS + SEQ / 4) * 4)    // 115712

__device__ __forceinline__ void attn_issue_tile(unsigned* buf, int h, int k0) {
    int t = threadIdx.x;
    const float*    Ks  = g_Kr  + ((size_t)h * SEQ + k0) * 64;
    const unsigned* VHs = g_VHp + ((size_t)h * SEQ + k0) * 32;
    const unsigned* VLs = g_VLp + ((size_t)h * SEQ + k0) * 32;
#pragma unroll
    for (int i = 0; i < 4; i++) {
        int s = t + i * 256;            // 0..1023
        int row = s >> 4, c4 = (s & 15) * 4;
        cp16(&buf[AO_K + row * KST + c4], Ks + row * 64 + c4);
    }
#pragma unroll
    for (int i = 0; i < 2; i++) {
        int s = t + i * 256;            // 0..511
        int row = s >> 3, c = (s & 7) * 4;
        cp16(&buf[AO_VH + row * VST + c], VHs + row * 32 + c);
        cp16(&buf[AO_VL + row * VST + c], VLs + row * 32 + c);
    }
    cp_commit();
}

__global__ void __launch_bounds__(256, 2) attn_kernel(const int* __restrict__ mask) {
    extern __shared__ unsigned smu[];
    unsigned char* MSB = (unsigned char*)(smu + AOFF_MS);
    unsigned smem_b = (unsigned)__cvta_generic_to_shared(smu);

    int tid = threadIdx.x;
    int lane = tid & 31, w = tid >> 5;
    int g = lane >> 2, tg = lane & 3;
    int m8 = lane >> 3, r8 = lane & 7;
    int h = blockIdx.y;
    int q0 = blockIdx.x * BQ;

    unsigned koff = ((((m8 >> 1) << 3) + r8) * KST + ((m8 & 1) << 2)) * 4;
    unsigned voff = ((((m8 & 1) << 3) + r8) * VST + ((m8 >> 1) << 2)) * 4;

    for (int i = tid; i < SEQ; i += 256) MSB[i] = (unsigned char)(mask[i] != 0);

    attn_issue_tile(smu, h, 0);
    attn_issue_tile(smu + ABUF, h, BK);

    // Q a-fragments (tf32 bit patterns) straight from global
    unsigned qa[8][4];
    {
        const unsigned* Qu = (const unsigned*)(g_Qr + (size_t)h * SEQ * 64);
        int rA = q0 + w * 16 + g, rB = rA + 8;
#pragma unroll
        for (int ks = 0; ks < 8; ks++) {
            int c = ks * 8 + tg;
            qa[ks][0] = Qu[rA * 64 + c];
            qa[ks][1] = Qu[rB * 64 + c];
            qa[ks][2] = Qu[rA * 64 + c + 4];
            qa[ks][3] = Qu[rB * 64 + c + 4];
        }
    }

    float o[8][4];
#pragma unroll
    for (int ni = 0; ni < 8; ni++)
#pragma unroll
        for (int j = 0; j < 4; j++) o[ni][j] = 0.0f;
    float mA = -3.0e38f, mB = -3.0e38f, lA = 0.0f, lB = 0.0f;

    const int NKT = SEQ / BK;
    for (int kt = 0; kt < NKT; kt++) {
        int k0 = kt * BK;
        if (kt + 1 < NKT) cp_wait<1>(); else cp_wait<0>();
        __syncthreads();
        if (kt + 2 < NKT)
            attn_issue_tile(smu + ((kt + 2) % ASTAGES) * ABUF, h, k0 + 2 * BK);

        unsigned tb = smem_b + ((kt % ASTAGES) * ABUF) * 4;
        unsigned sK  = tb + AO_K * 4;
        unsigned sVH = tb + AO_VH * 4;
        unsigned sVL = tb + AO_VL * 4;

        // --- S = Q . K^T (single tf32; scores in 0.125*log2e units) ---
        float sacc[8][4];
#pragma unroll
        for (int ni = 0; ni < 8; ni++)
#pragma unroll
            for (int j = 0; j < 4; j++) sacc[ni][j] = 0.0f;

#pragma unroll
        for (int ks = 0; ks < 8; ks++) {
#pragma unroll
            for (int p = 0; p < 4; p++) {
                unsigned bf[4];
                ldsm4(bf, sK + koff + (unsigned)((p * 16 * KST + ks * 8) * 4));
                mma_tf32(sacc[2 * p],     qa[ks], bf);
                mma_tf32(sacc[2 * p + 1], qa[ks], bf + 2);
            }
        }

        // --- mask ---
#pragma unroll
        for (int ni = 0; ni < 8; ni++) {
            int m0 = MSB[k0 + ni * 8 + 2 * tg];
            int m1 = MSB[k0 + ni * 8 + 2 * tg + 1];
            sacc[ni][0] = m0 ? sacc[ni][0] : MASKVAL;
            sacc[ni][1] = m1 ? sacc[ni][1] : MASKVAL;
            sacc[ni][2] = m0 ? sacc[ni][2] : MASKVAL;
            sacc[ni][3] = m1 ? sacc[ni][3] : MASKVAL;
        }

        // --- online softmax (rows g, g+8), exponentials on MUFU ---
        float mxA = -3.0e38f, mxB = -3.0e38f;
#pragma unroll
        for (int ni = 0; ni < 8; ni++) {
            mxA = fmaxf(mxA, fmaxf(sacc[ni][0], sacc[ni][1]));
            mxB = fmaxf(mxB, fmaxf(sacc[ni][2], sacc[ni][3]));
        }
        mxA = fmaxf(mxA, __shfl_xor_sync(0xffffffffu, mxA, 1));
        mxA = fmaxf(mxA, __shfl_xor_sync(0xffffffffu, mxA, 2));
        mxB = fmaxf(mxB, __shfl_xor_sync(0xffffffffu, mxB, 1));
        mxB = fmaxf(mxB, __shfl_xor_sync(0xffffffffu, mxB, 2));

        float mnA = fmaxf(mA, mxA), mnB = fmaxf(mB, mxB);
        float corrA = ex2(mA - mnA);
        float corrB = ex2(mB - mnB);

        float sumA = 0.0f, sumB = 0.0f;
#pragma unroll
        for (int ni = 0; ni < 8; ni++) {
            sacc[ni][0] = ex2(sacc[ni][0] - mnA);
            sacc[ni][1] = ex2(sacc[ni][1] - mnA);
            sacc[ni][2] = ex2(sacc[ni][2] - mnB);
            sacc[ni][3] = ex2(sacc[ni][3] - mnB);
            sumA += sacc[ni][0] + sacc[ni][1];
            sumB += sacc[ni][2] + sacc[ni][3];
        }
        sumA += __shfl_xor_sync(0xffffffffu, sumA, 1);
        sumA += __shfl_xor_sync(0xffffffffu, sumA, 2);
        sumB += __shfl_xor_sync(0xffffffffu, sumB, 1);
        sumB += __shfl_xor_sync(0xffffffffu, sumB, 2);

        lA = lA * corrA + sumA;
        lB = lB * corrB + sumB;
        mA = mnA;
        mB = mnB;
#pragma unroll
        for (int ni = 0; ni < 8; ni++) {
            o[ni][0] *= corrA; o[ni][1] *= corrA;
            o[ni][2] *= corrB; o[ni][3] *= corrB;
        }

        // --- O += P . V (PRMT truncation-split A-frag; V split trans-ldsm) ---
#pragma unroll
        for (int ks = 0; ks < 4; ks++) {
            unsigned ah[4], al[4];
#pragma unroll
            for (int half = 0; half < 2; half++) {
                const float* s2 = sacc[2 * ks + half];
                float l0 = s2[0] - trunc_hi(s2[0]);
                float l1 = s2[1] - trunc_hi(s2[1]);
                float l2 = s2[2] - trunc_hi(s2[2]);
                float l3 = s2[3] - trunc_hi(s2[3]);
                ah[2 * half]     = prmt_hi(s2[0], s2[1]);
                ah[2 * half + 1] = prmt_hi(s2[2], s2[3]);
                al[2 * half]     = prmt_hi(l0, l1);
                al[2 * half + 1] = prmt_hi(l2, l3);
            }
#pragma unroll
            for (int p = 0; p < 4; p++) {
                unsigned vh[4], vl[4];
                unsigned off = (unsigned)((ks * 16 * VST + p * 8) * 4);
                ldsm4t(vh, sVH + voff + off);
                ldsm4t(vl, sVL + voff + off);
                mma_bf16(o[2 * p],     ah, vh);
                mma_bf16(o[2 * p],     al, vh);
                mma_bf16(o[2 * p],     ah, vl);
                mma_bf16(o[2 * p + 1], ah, vh + 2);
                mma_bf16(o[2 * p + 1], al, vh + 2);
                mma_bf16(o[2 * p + 1], ah, vl + 2);
            }
        }
    }

    // normalize + store, pre-rounded to tf32 for the out-GEMM
    float invA = 1.0f / lA, invB = 1.0f / lB;
    float* Og = g_att + (size_t)(q0 + w * 16) * DM + h * HD;
#pragma unroll
    for (int ni = 0; ni < 8; ni++) {
        *(float2*)&Og[(size_t)g * DM + ni * 8 + 2 * tg] =
            make_float2(tf32r(o[ni][0] * invA), tf32r(o[ni][1] * invA));
        *(float2*)&Og[(size_t)(g + 8) * DM + ni * 8 + 2 * tg] =
            make_float2(tf32r(o[ni][2] * invB), tf32r(o[ni][3] * invB));
    }
}

// ---------------------------------------------------------------------------
// launch
// ---------------------------------------------------------------------------
extern "C" void kernel_launch(void* const* d_in, const int* in_sizes, int n_in,
                              void* d_out, int out_size) {
    const float* x    = (const float*)d_in[0];
    const int*   mask = (const int*)d_in[1];
    const float* Wq   = (const float*)d_in[2];
    const float* Wk   = (const float*)d_in[3];
    const float* Wv   = (const float*)d_in[4];
    const float* Wo   = (const float*)d_in[5];
    float* out = (float*)d_out;

    cudaFuncSetAttribute(gemm_qkv_kernel, cudaFuncAttributeMaxDynamicSharedMemorySize,
                         GSMEM_BYTES);
    cudaFuncSetAttribute(gemm_out_kernel, cudaFuncAttributeMaxDynamicSharedMemorySize,
                         GSMEM_BYTES);
    cudaFuncSetAttribute(attn_kernel, cudaFuncAttributeMaxDynamicSharedMemorySize,
                         ASMEM_BYTES);

    rope_table_kernel<<<(SEQ * 32 + 255) / 256, 256>>>();
    round_tf32_kernel<<<dim3((SEQ * DM / 4 + 255) / 256, 5), 256>>>(x, Wq, Wk, Wv, Wo);
    gemm_qkv_kernel<<<dim3(16, 16, 3), 128, GSMEM_BYTES>>>();
    attn_kernel<<<dim3(SEQ / BQ, NH), 256, ASMEM_BYTES>>>(mask);
    gemm_out_kernel<<<dim3(16, 16), 128, GSMEM_BYTES>>>(out);
}